// round 7
// baseline (speedup 1.0000x reference)
#include <cuda_runtime.h>
#include <cuda_bf16.h>
#include <cuda_fp16.h>
#include <cstdint>

#define N_NODES 100000
#define N_PAD   100096                 // 782*128, pads A so GEMM tiles never read OOB
#define N_EDGES 1600000
#define SCAN_CHUNK 4096
#define SCAN_NB ((N_NODES + SCAN_CHUNK - 1) / SCAN_CHUNK)  // 25

// GEMM smem geometry: per stage [Ah|Al|Wh|Wl]; A is 128 rows, W is NT rows; 64-wide K chunk
#define CSTR_B 144                     // bytes per smem row (72 bf16), 16B-aligned, conflict-free
#define A_TILE_B (128 * CSTR_B)        // 18432 B

// ---------------- scratch (static device globals; no allocs) ----------------
__device__ int g_is64;
__device__ __align__(16) int g_deg[N_NODES + 4];
__device__ __align__(16) int g_rowptr[N_NODES + 4];
__device__ __align__(16) int g_cursor[N_NODES];
__device__ int g_col[N_EDGES];
__device__ int g_bsum[SCAN_NB];
__device__ int g_boff[SCAN_NB];
__device__ __half g_y16[(size_t)N_NODES * 128];         // neighbor-transform y, fp16 gather payload
__device__ float  g_hr[(size_t)N_NODES * 128];          // root-transform, fp32
__device__ __nv_bfloat16 g_ahi[(size_t)N_PAD * 128];    // activation hi (pad rows stay 0)
__device__ __nv_bfloat16 g_alo[(size_t)N_PAD * 128];    // activation lo
__device__ __nv_bfloat16 g_whi[640 * 128];              // stacked weights: L1(256) L2(256) L3(128)
__device__ __nv_bfloat16 g_wlo[640 * 128];

// ---------------- PTX helpers ----------------
#define CP_ASYNC16(dst, src) \
    asm volatile("cp.async.cg.shared.global [%0], [%1], 16;\n" :: "r"(dst), "l"(src))
#define CP_COMMIT() asm volatile("cp.async.commit_group;\n")
#define CP_WAIT(n)  asm volatile("cp.async.wait_group %0;\n" :: "n"(n))
#define LDSM_X4(r0, r1, r2, r3, addr) \
    asm volatile("ldmatrix.sync.aligned.m8n8.x4.shared.b16 {%0,%1,%2,%3}, [%4];" \
                 : "=r"(r0), "=r"(r1), "=r"(r2), "=r"(r3) : "r"(addr))

__device__ __forceinline__ void mma_bf16(float acc[4], const uint32_t a[4], uint32_t b0, uint32_t b1) {
    asm volatile(
        "mma.sync.aligned.m16n8k16.row.col.f32.bf16.bf16.f32 "
        "{%0,%1,%2,%3}, {%4,%5,%6,%7}, {%8,%9}, {%0,%1,%2,%3};\n"
        : "+f"(acc[0]), "+f"(acc[1]), "+f"(acc[2]), "+f"(acc[3])
        : "r"(a[0]), "r"(a[1]), "r"(a[2]), "r"(a[3]), "r"(b0), "r"(b1));
}

// ---------------- edge dtype detection (int64 vs int32) ----------------
__global__ void k_detect(const int* __restrict__ ei32) {
    if (threadIdx.x == 0 && blockIdx.x == 0) {
        int is64 = 1;
        for (int i = 0; i < 128; i++) {
            if (ei32[2 * i + 1] != 0) { is64 = 0; break; }
        }
        g_is64 = is64;
    }
}

__device__ __forceinline__ int edge_val(const void* ei, size_t idx, int is64) {
    if (is64) return (int)((const long long*)ei)[idx];
    return ((const int*)ei)[idx];
}

// ---------------- CSR build ----------------
__global__ void k_count(const void* __restrict__ ei) {
    int e = blockIdx.x * blockDim.x + threadIdx.x;
    if (e < N_EDGES) {
        int dst = edge_val(ei, (size_t)N_EDGES + e, g_is64);
        atomicAdd(&g_deg[dst], 1);
    }
}

__global__ __launch_bounds__(1024) void k_scanA() {
    __shared__ int wsum[32];
    int b = blockIdx.x, tid = threadIdx.x, lane = tid & 31, wid = tid >> 5;
    int base = b * SCAN_CHUNK + tid * 4;
    int4 v = make_int4(0, 0, 0, 0);
    if (base + 3 < N_NODES) {
        v = *(const int4*)(g_deg + base);
    } else {
        int* p = (int*)&v;
        for (int i = 0; i < 4; i++) if (base + i < N_NODES) p[i] = g_deg[base + i];
    }
    int s0 = v.x, s1 = s0 + v.y, s2 = s1 + v.z, s3 = s2 + v.w;
    int x = s3;
    #pragma unroll
    for (int s = 1; s < 32; s <<= 1) {
        int t = __shfl_up_sync(0xffffffffu, x, s);
        if (lane >= s) x += t;
    }
    if (lane == 31) wsum[wid] = x;
    __syncthreads();
    if (wid == 0) {
        int w = wsum[lane];
        #pragma unroll
        for (int s = 1; s < 32; s <<= 1) {
            int t = __shfl_up_sync(0xffffffffu, w, s);
            if (lane >= s) w += t;
        }
        wsum[lane] = w;
    }
    __syncthreads();
    int off = (wid > 0 ? wsum[wid - 1] : 0) + (x - s3);
    int4 o = make_int4(off, off + s0, off + s1, off + s2);
    if (base + 3 < N_NODES) {
        *(int4*)(g_rowptr + base) = o;
    } else {
        int* p = (int*)&o;
        for (int i = 0; i < 4; i++) if (base + i < N_NODES) g_rowptr[base + i] = p[i];
    }
    if (tid == 0) g_bsum[b] = wsum[31];
}

__global__ void k_scanB() {
    int lane = threadIdx.x;
    int v = (lane < SCAN_NB) ? g_bsum[lane] : 0;
    int x = v;
    #pragma unroll
    for (int s = 1; s < 32; s <<= 1) {
        int t = __shfl_up_sync(0xffffffffu, x, s);
        if (lane >= s) x += t;
    }
    if (lane < SCAN_NB) g_boff[lane] = x - v;
    if (lane == 31) g_rowptr[N_NODES] = x;
}

__global__ void k_scanC() {
    int i = blockIdx.x * blockDim.x + threadIdx.x;
    if (i < N_NODES) {
        int r = g_rowptr[i] + g_boff[i / SCAN_CHUNK];
        g_rowptr[i] = r;
        g_cursor[i] = r;
    }
}

__global__ void k_fill(const void* __restrict__ ei) {
    int e = blockIdx.x * blockDim.x + threadIdx.x;
    if (e < N_EDGES) {
        int is64 = g_is64;
        int dst = edge_val(ei, (size_t)N_EDGES + e, is64);
        int src = edge_val(ei, (size_t)e, is64);
        int pos = atomicAdd(&g_cursor[dst], 1);
        g_col[pos] = src;
    }
}

// ---------------- conversions ----------------
__global__ void k_convw(const float* __restrict__ w1l, const float* __restrict__ w1r,
                        const float* __restrict__ w2l, const float* __restrict__ w2r,
                        const float* __restrict__ w3l, const float* __restrict__ w3r) {
    int i = blockIdx.x * blockDim.x + threadIdx.x;
    if (i >= 640 * 128) return;
    int row = i >> 7, c = i & 127;
    const float* src; int r;
    if (row < 128)      { src = w1l; r = row; }
    else if (row < 256) { src = w1r; r = row - 128; }
    else if (row < 384) { src = w2l; r = row - 256; }
    else if (row < 512) { src = w2r; r = row - 384; }
    else if (row < 576) { src = w3l; r = row - 512; }
    else                { src = w3r; r = row - 576; }
    float v = src[r * 128 + c];
    __nv_bfloat16 hi = __float2bfloat16(v);
    g_whi[i] = hi;
    g_wlo[i] = __float2bfloat16(v - __bfloat162float(hi));
}

__global__ void k_convx(const float4* __restrict__ x) {
    int i = blockIdx.x * blockDim.x + threadIdx.x;
    if (i >= N_NODES * 32) return;
    float4 v = x[i];
    size_t o = (size_t)i * 4;
    __nv_bfloat16 h0 = __float2bfloat16(v.x), h1 = __float2bfloat16(v.y);
    __nv_bfloat16 h2 = __float2bfloat16(v.z), h3 = __float2bfloat16(v.w);
    *(__nv_bfloat162*)(g_ahi + o)     = __nv_bfloat162(h0, h1);
    *(__nv_bfloat162*)(g_ahi + o + 2) = __nv_bfloat162(h2, h3);
    __nv_bfloat16 l0 = __float2bfloat16(v.x - __bfloat162float(h0));
    __nv_bfloat16 l1 = __float2bfloat16(v.y - __bfloat162float(h1));
    __nv_bfloat16 l2 = __float2bfloat16(v.z - __bfloat162float(h2));
    __nv_bfloat16 l3 = __float2bfloat16(v.w - __bfloat162float(h3));
    *(__nv_bfloat162*)(g_alo + o)     = __nv_bfloat162(l0, l1);
    *(__nv_bfloat162*)(g_alo + o + 2) = __nv_bfloat162(l2, l3);
}

// ---------------- GEMM: M=128 x N=NT tile, 2-stage cp.async, ldmatrix, bf16-split mma ----------------
// Weight rows [wbase, wbase+NT/2) = W_l (-> y fp16), [wbase+NT/2, wbase+NT) = W_r (-> hr fp32)
template<int NT, int NTHR>
__global__ __launch_bounds__(NTHR, 1) void k_gemm(int wbase) {
    constexpr int W_TILE_B = NT * CSTR_B;
    constexpr int STAGE_B  = 2 * A_TILE_B + 2 * W_TILE_B;
    constexpr int WCOLS    = NT / 64;
    constexpr int YC       = NT / 2;

    extern __shared__ __align__(16) char smemc[];
    uint32_t smem_u = (uint32_t)__cvta_generic_to_shared(smemc);
    int m0 = blockIdx.x * 128;
    int tid = threadIdx.x;

    #pragma unroll
    for (int st = 0; st < 2; st++) {
        uint32_t sb = smem_u + st * STAGE_B;
        int kb = st * 64;
        for (int i = tid; i < 2048; i += NTHR) {
            int t = i >> 10, c = i & 1023;
            int r = c >> 3, q = c & 7;
            uint32_t doff = (uint32_t)(t * A_TILE_B + r * CSTR_B + q * 16);
            const __nv_bfloat16* src = (t == 0 ? g_ahi : g_alo) + (size_t)(m0 + r) * 128 + kb + q * 8;
            CP_ASYNC16(sb + doff, src);
        }
        for (int i = tid; i < 2 * NT * 8; i += NTHR) {
            int t = i / (NT * 8), c = i % (NT * 8);
            int r = c >> 3, q = c & 7;
            uint32_t doff = (uint32_t)(2 * A_TILE_B + t * W_TILE_B + r * CSTR_B + q * 16);
            const __nv_bfloat16* src = (t == 0 ? g_whi : g_wlo) + (size_t)(wbase + r) * 128 + kb + q * 8;
            CP_ASYNC16(sb + doff, src);
        }
        CP_COMMIT();
    }

    int warp = tid >> 5, lane = tid & 31;
    int wm = (warp / WCOLS) * 32, wn = (warp % WCOLS) * 64;
    uint32_t aoff = ((lane & 7) + ((lane >> 3) & 1) * 8) * CSTR_B + (lane >> 4) * 16;
    uint32_t woff = (lane & 7) * CSTR_B + ((lane >> 3) & 1) * 16 + ((lane >> 3) >> 1) * (8 * CSTR_B);

    float acc[2][8][4] = {};

    #pragma unroll
    for (int st = 0; st < 2; st++) {
        if (st == 0) { CP_WAIT(1); } else { CP_WAIT(0); }
        __syncthreads();
        uint32_t sb = smem_u + st * STAGE_B;
        #pragma unroll
        for (int kl = 0; kl < 64; kl += 16) {
            uint32_t ah[2][4], al[2][4], bh[8][2], bl[8][2];
            #pragma unroll
            for (int i = 0; i < 2; i++) {
                uint32_t abase = sb + (wm + i * 16) * CSTR_B + kl * 2 + aoff;
                LDSM_X4(ah[i][0], ah[i][1], ah[i][2], ah[i][3], abase);
                LDSM_X4(al[i][0], al[i][1], al[i][2], al[i][3], abase + A_TILE_B);
            }
            #pragma unroll
            for (int jp = 0; jp < 4; jp++) {
                uint32_t wb = sb + 2 * A_TILE_B + (wn + jp * 16) * CSTR_B + kl * 2 + woff;
                LDSM_X4(bh[2*jp][0], bh[2*jp][1], bh[2*jp+1][0], bh[2*jp+1][1], wb);
                LDSM_X4(bl[2*jp][0], bl[2*jp][1], bl[2*jp+1][0], bl[2*jp+1][1], wb + W_TILE_B);
            }
            #pragma unroll
            for (int j = 0; j < 8; j++) {
                #pragma unroll
                for (int i = 0; i < 2; i++) {
                    mma_bf16(acc[i][j], ah[i], bh[j][0], bh[j][1]);  // hi*hi
                    mma_bf16(acc[i][j], ah[i], bl[j][0], bl[j][1]);  // hi*lo
                    mma_bf16(acc[i][j], al[i], bh[j][0], bh[j][1]);  // lo*hi
                }
            }
        }
    }

    int g = lane >> 2, tg = lane & 3;
    #pragma unroll
    for (int i = 0; i < 2; i++) {
        #pragma unroll
        for (int j = 0; j < 8; j++) {
            int rm = m0 + wm + i * 16 + g;
            int cn = wn + j * 8 + tg * 2;
            if (cn < YC) {
                __half2 v01 = __floats2half2_rn(acc[i][j][0], acc[i][j][1]);
                __half2 v23 = __floats2half2_rn(acc[i][j][2], acc[i][j][3]);
                if (rm < N_NODES)     *(__half2*)&g_y16[(size_t)rm * YC + cn]       = v01;
                if (rm + 8 < N_NODES) *(__half2*)&g_y16[(size_t)(rm + 8) * YC + cn] = v23;
            } else {
                int hc = cn - YC;
                if (rm < N_NODES)
                    *(float2*)&g_hr[(size_t)rm * YC + hc] = make_float2(acc[i][j][0], acc[i][j][1]);
                if (rm + 8 < N_NODES)
                    *(float2*)&g_hr[(size_t)(rm + 8) * YC + hc] = make_float2(acc[i][j][2], acc[i][j][3]);
            }
        }
    }
}

// ---------------- aggregation (vectorized LDG.128 gathers) ----------------
__device__ __forceinline__ void acc_h8(float a[8], uint4 p) {
    __half2* h = (__half2*)&p;
    #pragma unroll
    for (int q = 0; q < 4; q++) {
        float2 f = __half22float2(h[q]);
        a[2 * q]     += f.x;
        a[2 * q + 1] += f.y;
    }
}

// 128-ch: warp per node; half-warp per edge stream (16 lanes x 16B = 256B row)
__global__ void k_agg128(const float* __restrict__ bias, int relu) {
    int warp = (blockIdx.x * blockDim.x + threadIdx.x) >> 5;
    int lane = threadIdx.x & 31;
    if (warp >= N_NODES) return;
    int hw = lane >> 4, ln = lane & 15;
    int rs = g_rowptr[warp], re = g_rowptr[warp + 1];
    float a[8] = {};
    const uint4* Y4 = (const uint4*)g_y16;  // row stride 16 uint4
    int e = rs + hw;
    for (; e + 2 < re; e += 4) {            // 2 edges in flight per half-warp
        int s0 = g_col[e], s1 = g_col[e + 2];
        uint4 p0 = Y4[(size_t)s0 * 16 + ln];
        uint4 p1 = Y4[(size_t)s1 * 16 + ln];
        acc_h8(a, p0); acc_h8(a, p1);
    }
    for (; e < re; e += 2) {
        uint4 p = Y4[(size_t)g_col[e] * 16 + ln];
        acc_h8(a, p);
    }
    __syncwarp();
    #pragma unroll
    for (int q = 0; q < 8; q++) a[q] += __shfl_down_sync(0xffffffffu, a[q], 16);
    if (hw == 0) {
        float inv = 1.f / fmaxf((float)(re - rs), 1.f);
        const float4* H4 = (const float4*)g_hr;   // row stride 32 float4
        float4 h0 = H4[(size_t)warp * 32 + ln * 2];
        float4 h1 = H4[(size_t)warp * 32 + ln * 2 + 1];
        const float4* B4 = (const float4*)bias;
        float4 b0 = B4[ln * 2], b1 = B4[ln * 2 + 1];
        float o[8];
        o[0] = a[0] * inv + h0.x + b0.x; o[1] = a[1] * inv + h0.y + b0.y;
        o[2] = a[2] * inv + h0.z + b0.z; o[3] = a[3] * inv + h0.w + b0.w;
        o[4] = a[4] * inv + h1.x + b1.x; o[5] = a[5] * inv + h1.y + b1.y;
        o[6] = a[6] * inv + h1.z + b1.z; o[7] = a[7] * inv + h1.w + b1.w;
        if (relu) {
            #pragma unroll
            for (int q = 0; q < 8; q++) o[q] = fmaxf(o[q], 0.f);
        }
        __nv_bfloat162 hh[4], hl[4];
        #pragma unroll
        for (int q = 0; q < 4; q++) {
            __nv_bfloat16 c0 = __float2bfloat16(o[2 * q]);
            __nv_bfloat16 c1 = __float2bfloat16(o[2 * q + 1]);
            hh[q] = __nv_bfloat162(c0, c1);
            hl[q] = __nv_bfloat162(__float2bfloat16(o[2 * q] - __bfloat162float(c0)),
                                   __float2bfloat16(o[2 * q + 1] - __bfloat162float(c1)));
        }
        size_t idx = (size_t)warp * 128 + ln * 8;
        *(uint4*)(g_ahi + idx) = *(uint4*)hh;
        *(uint4*)(g_alo + idx) = *(uint4*)hl;
    }
}

// 64-ch: half-warp per node; 8-lane group per edge stream (8 lanes x 16B = 128B row)
__global__ void k_agg64(const float* __restrict__ bias, float* __restrict__ out) {
    int gw = (blockIdx.x * blockDim.x + threadIdx.x) >> 5;
    int lane = threadIdx.x & 31;
    int hw = lane >> 4;            // node select within warp
    int sub = (lane >> 3) & 1;     // edge stream within half-warp
    int ln = lane & 7;             // 16B chunk within row
    int node = gw * 2 + hw;
    if (node >= N_NODES) return;
    int rs = g_rowptr[node], re = g_rowptr[node + 1];
    float a[8] = {};
    const uint4* Y4 = (const uint4*)g_y16;  // row stride 8 uint4 (64 halves)
    int e = rs + sub;
    for (; e + 2 < re; e += 4) {
        int s0 = g_col[e], s1 = g_col[e + 2];
        uint4 p0 = Y4[(size_t)s0 * 8 + ln];
        uint4 p1 = Y4[(size_t)s1 * 8 + ln];
        acc_h8(a, p0); acc_h8(a, p1);
    }
    for (; e < re; e += 2) {
        uint4 p = Y4[(size_t)g_col[e] * 8 + ln];
        acc_h8(a, p);
    }
    __syncwarp();
    #pragma unroll
    for (int q = 0; q < 8; q++) a[q] += __shfl_down_sync(0xffffffffu, a[q], 8);
    if (sub == 0) {
        float inv = 1.f / fmaxf((float)(re - rs), 1.f);
        const float4* H4 = (const float4*)g_hr;   // row stride 16 float4
        float4 h0 = H4[(size_t)node * 16 + ln * 2];
        float4 h1 = H4[(size_t)node * 16 + ln * 2 + 1];
        const float4* B4 = (const float4*)bias;
        float4 b0 = B4[ln * 2], b1 = B4[ln * 2 + 1];
        float4 o0, o1;
        o0.x = a[0] * inv + h0.x + b0.x; o0.y = a[1] * inv + h0.y + b0.y;
        o0.z = a[2] * inv + h0.z + b0.z; o0.w = a[3] * inv + h0.w + b0.w;
        o1.x = a[4] * inv + h1.x + b1.x; o1.y = a[5] * inv + h1.y + b1.y;
        o1.z = a[6] * inv + h1.z + b1.z; o1.w = a[7] * inv + h1.w + b1.w;
        float4* O4 = (float4*)out;                 // row stride 16 float4
        O4[(size_t)node * 16 + ln * 2]     = o0;
        O4[(size_t)node * 16 + ln * 2 + 1] = o1;
    }
}

// ---------------- launch ----------------
extern "C" void kernel_launch(void* const* d_in, const int* in_sizes, int n_in,
                              void* d_out, int out_size) {
    const float* x   = (const float*)d_in[0];
    const void*  ei  = d_in[1];
    const float* w1l = (const float*)d_in[2];
    const float* w1r = (const float*)d_in[3];
    const float* b1  = (const float*)d_in[4];
    const float* w2l = (const float*)d_in[5];
    const float* w2r = (const float*)d_in[6];
    const float* b2  = (const float*)d_in[7];
    const float* w3l = (const float*)d_in[8];
    const float* w3r = (const float*)d_in[9];
    const float* b3  = (const float*)d_in[10];
    float* out = (float*)d_out;

    constexpr int SMEM_BIG   = 2 * (2 * A_TILE_B + 2 * 256 * CSTR_B);  // 221184
    constexpr int SMEM_SMALL = 2 * (2 * A_TILE_B + 2 * 128 * CSTR_B);  // 147456
    cudaFuncSetAttribute(k_gemm<256, 512>, cudaFuncAttributeMaxDynamicSharedMemorySize, SMEM_BIG);
    cudaFuncSetAttribute(k_gemm<128, 256>, cudaFuncAttributeMaxDynamicSharedMemorySize, SMEM_SMALL);

    void* deg_ptr = nullptr;
    cudaGetSymbolAddress(&deg_ptr, g_deg);

    dim3 grid(782, 1);

    k_detect<<<1, 32>>>((const int*)ei);
    cudaMemsetAsync(deg_ptr, 0, N_NODES * sizeof(int));
    k_convw<<<320, 256>>>(w1l, w1r, w2l, w2r, w3l, w3r);
    k_convx<<<(N_NODES * 32 + 255) / 256, 256>>>((const float4*)x);
    k_gemm<256, 512><<<grid, 512, SMEM_BIG>>>(0);         // layer-1 GEMM (profiled slot)
    k_count<<<(N_EDGES + 255) / 256, 256>>>(ei);
    k_scanA<<<SCAN_NB, 1024>>>();
    k_scanB<<<1, 32>>>();
    k_scanC<<<(N_NODES + 255) / 256, 256>>>();
    k_fill<<<(N_EDGES + 255) / 256, 256>>>(ei);

    // layer 1 aggregate
    k_agg128<<<(N_NODES + 7) / 8, 256>>>(b1, 1);
    // layer 2
    k_gemm<256, 512><<<grid, 512, SMEM_BIG>>>(256);
    k_agg128<<<(N_NODES + 7) / 8, 256>>>(b2, 1);
    // layer 3
    k_gemm<128, 256><<<grid, 256, SMEM_SMALL>>>(512);
    k_agg64<<<(N_NODES + 15) / 16, 256>>>(b3, out);
}

// round 8
// speedup vs baseline: 1.0110x; 1.0110x over previous
#include <cuda_runtime.h>
#include <cuda_bf16.h>
#include <cuda_fp16.h>
#include <cstdint>

#define N_NODES 100000
#define N_PAD   100096
#define N_EDGES 1600000
#define SCAN_CHUNK 4096
#define SCAN_NB ((N_NODES + SCAN_CHUNK - 1) / SCAN_CHUNK)  // 25

#define CSTR_B 144                     // bytes per smem row (72 bf16), 16B-aligned, conflict-free
#define A_TILE_B (128 * CSTR_B)        // 18432 B

// ---------------- scratch (static device globals; no allocs) ----------------
__device__ int g_is64;
__device__ __align__(16) int g_deg[N_NODES + 4];
__device__ __align__(16) int g_rowptr[N_NODES + 4];
__device__ __align__(16) int g_cursor[N_NODES];
__device__ int g_col[N_EDGES];
__device__ int g_bsum[SCAN_NB];
__device__ __half g_y16[(size_t)N_NODES * 128];         // neighbor-transform y, fp16 gather payload
__device__ float  g_hr[(size_t)N_NODES * 128];          // root-transform, fp32
__device__ __nv_bfloat16 g_ahi[(size_t)N_PAD * 128];    // activation hi (pad rows stay 0)
__device__ __nv_bfloat16 g_alo[(size_t)N_PAD * 128];    // activation lo
__device__ __nv_bfloat16 g_whi[640 * 128];              // stacked weights: L1(256) L2(256) L3(128)
__device__ __nv_bfloat16 g_wlo[640 * 128];

// ---------------- PTX helpers ----------------
#define CP_ASYNC16(dst, src) \
    asm volatile("cp.async.cg.shared.global [%0], [%1], 16;\n" :: "r"(dst), "l"(src))
#define CP_COMMIT() asm volatile("cp.async.commit_group;\n")
#define CP_WAIT(n)  asm volatile("cp.async.wait_group %0;\n" :: "n"(n))
#define LDSM_X4(r0, r1, r2, r3, addr) \
    asm volatile("ldmatrix.sync.aligned.m8n8.x4.shared.b16 {%0,%1,%2,%3}, [%4];" \
                 : "=r"(r0), "=r"(r1), "=r"(r2), "=r"(r3) : "r"(addr))

__device__ __forceinline__ void mma_bf16(float acc[4], const uint32_t a[4], uint32_t b0, uint32_t b1) {
    asm volatile(
        "mma.sync.aligned.m16n8k16.row.col.f32.bf16.bf16.f32 "
        "{%0,%1,%2,%3}, {%4,%5,%6,%7}, {%8,%9}, {%0,%1,%2,%3};\n"
        : "+f"(acc[0]), "+f"(acc[1]), "+f"(acc[2]), "+f"(acc[3])
        : "r"(a[0]), "r"(a[1]), "r"(a[2]), "r"(a[3]), "r"(b0), "r"(b1));
}

// ---------------- edge dtype detection (int64 vs int32) ----------------
__global__ void k_detect(const int* __restrict__ ei32) {
    if (threadIdx.x == 0 && blockIdx.x == 0) {
        int is64 = 1;
        for (int i = 0; i < 128; i++) {
            if (ei32[2 * i + 1] != 0) { is64 = 0; break; }
        }
        g_is64 = is64;
    }
}

__device__ __forceinline__ int edge_val(const void* ei, size_t idx, int is64) {
    if (is64) return (int)((const long long*)ei)[idx];
    return ((const int*)ei)[idx];
}

// ---------------- CSR build ----------------
__global__ void k_count(const void* __restrict__ ei) {
    int e = blockIdx.x * blockDim.x + threadIdx.x;
    if (e < N_EDGES) {
        int dst = edge_val(ei, (size_t)N_EDGES + e, g_is64);
        atomicAdd(&g_deg[dst], 1);
    }
}

__global__ __launch_bounds__(1024) void k_scanA() {
    __shared__ int wsum[32];
    int b = blockIdx.x, tid = threadIdx.x, lane = tid & 31, wid = tid >> 5;
    int base = b * SCAN_CHUNK + tid * 4;
    int4 v = make_int4(0, 0, 0, 0);
    if (base + 3 < N_NODES) {
        v = *(const int4*)(g_deg + base);
    } else {
        int* p = (int*)&v;
        for (int i = 0; i < 4; i++) if (base + i < N_NODES) p[i] = g_deg[base + i];
    }
    int s0 = v.x, s1 = s0 + v.y, s2 = s1 + v.z, s3 = s2 + v.w;
    int x = s3;
    #pragma unroll
    for (int s = 1; s < 32; s <<= 1) {
        int t = __shfl_up_sync(0xffffffffu, x, s);
        if (lane >= s) x += t;
    }
    if (lane == 31) wsum[wid] = x;
    __syncthreads();
    if (wid == 0) {
        int w = wsum[lane];
        #pragma unroll
        for (int s = 1; s < 32; s <<= 1) {
            int t = __shfl_up_sync(0xffffffffu, w, s);
            if (lane >= s) w += t;
        }
        wsum[lane] = w;
    }
    __syncthreads();
    int off = (wid > 0 ? wsum[wid - 1] : 0) + (x - s3);
    int4 o = make_int4(off, off + s0, off + s1, off + s2);
    if (base + 3 < N_NODES) {
        *(int4*)(g_rowptr + base) = o;
    } else {
        int* p = (int*)&o;
        for (int i = 0; i < 4; i++) if (base + i < N_NODES) g_rowptr[base + i] = p[i];
    }
    if (tid == 0) g_bsum[b] = wsum[31];
}

// scanC now also does the 25-element top-level scan per block (scanB removed)
__global__ void k_scanC() {
    __shared__ int boff[SCAN_NB + 1];
    int tid = threadIdx.x;
    if (tid < 32) {
        int v = (tid < SCAN_NB) ? g_bsum[tid] : 0;
        int x = v;
        #pragma unroll
        for (int s = 1; s < 32; s <<= 1) {
            int t = __shfl_up_sync(0xffffffffu, x, s);
            if (tid >= s) x += t;
        }
        if (tid < SCAN_NB) boff[tid] = x - v;
        if (tid == 31) boff[SCAN_NB] = x;  // grand total
    }
    __syncthreads();
    int i = blockIdx.x * blockDim.x + tid;
    if (i < N_NODES) {
        int r = g_rowptr[i] + boff[i / SCAN_CHUNK];
        g_rowptr[i] = r;
        g_cursor[i] = r;
    }
    if (i == 0) g_rowptr[N_NODES] = boff[SCAN_NB];
}

__global__ void k_fill(const void* __restrict__ ei) {
    int e = blockIdx.x * blockDim.x + threadIdx.x;
    if (e < N_EDGES) {
        int is64 = g_is64;
        int dst = edge_val(ei, (size_t)N_EDGES + e, is64);
        int src = edge_val(ei, (size_t)e, is64);
        int pos = atomicAdd(&g_cursor[dst], 1);
        g_col[pos] = src;
    }
}

// ---------------- weight conversion ----------------
__global__ void k_convw(const float* __restrict__ w1l, const float* __restrict__ w1r,
                        const float* __restrict__ w2l, const float* __restrict__ w2r,
                        const float* __restrict__ w3l, const float* __restrict__ w3r) {
    int i = blockIdx.x * blockDim.x + threadIdx.x;
    if (i >= 640 * 128) return;
    int row = i >> 7, c = i & 127;
    const float* src; int r;
    if (row < 128)      { src = w1l; r = row; }
    else if (row < 256) { src = w1r; r = row - 128; }
    else if (row < 384) { src = w2l; r = row - 256; }
    else if (row < 512) { src = w2r; r = row - 384; }
    else if (row < 576) { src = w3l; r = row - 512; }
    else                { src = w3r; r = row - 576; }
    float v = src[r * 128 + c];
    __nv_bfloat16 hi = __float2bfloat16(v);
    g_whi[i] = hi;
    g_wlo[i] = __float2bfloat16(v - __bfloat162float(hi));
}

// ---------------- GEMM: M=128 x N=NT tile, 2-stage cp.async, ldmatrix, bf16-split mma ----------------
// LOADX: layer-1 variant loads A from fp32 x and converts hi/lo in-kernel (no materialized conv).
// Weight rows [wbase, wbase+NT/2) = W_l (-> y fp16), [wbase+NT/2, wbase+NT) = W_r (-> hr fp32)
template<int NT, int NTHR, bool LOADX>
__global__ __launch_bounds__(NTHR, 1) void k_gemm(int wbase, const float* __restrict__ x) {
    constexpr int W_TILE_B = NT * CSTR_B;
    constexpr int STAGE_B  = 2 * A_TILE_B + 2 * W_TILE_B;
    constexpr int WCOLS    = NT / 64;
    constexpr int YC       = NT / 2;

    extern __shared__ __align__(16) char smemc[];
    uint32_t smem_u = (uint32_t)__cvta_generic_to_shared(smemc);
    char* smem_g = smemc;
    int m0 = blockIdx.x * 128;
    int tid = threadIdx.x;

    // W tiles via cp.async (one commit group per stage)
    #pragma unroll
    for (int st = 0; st < 2; st++) {
        uint32_t sb = smem_u + st * STAGE_B;
        int kb = st * 64;
        if (!LOADX) {
            for (int i = tid; i < 2048; i += NTHR) {
                int t = i >> 10, c = i & 1023;
                int r = c >> 3, q = c & 7;
                uint32_t doff = (uint32_t)(t * A_TILE_B + r * CSTR_B + q * 16);
                const __nv_bfloat16* src = (t == 0 ? g_ahi : g_alo) + (size_t)(m0 + r) * 128 + kb + q * 8;
                CP_ASYNC16(sb + doff, src);
            }
        }
        for (int i = tid; i < 2 * NT * 8; i += NTHR) {
            int t = i / (NT * 8), c = i % (NT * 8);
            int r = c >> 3, q = c & 7;
            uint32_t doff = (uint32_t)(2 * A_TILE_B + t * W_TILE_B + r * CSTR_B + q * 16);
            const __nv_bfloat16* src = (t == 0 ? g_whi : g_wlo) + (size_t)(wbase + r) * 128 + kb + q * 8;
            CP_ASYNC16(sb + doff, src);
        }
        CP_COMMIT();
    }

    if (LOADX) {
        // convert x (fp32) -> bf16 hi/lo directly into both stages' A tiles
        #pragma unroll
        for (int st = 0; st < 2; st++) {
            char* sb = smem_g + st * STAGE_B;
            int kb = st * 64;
            for (int i = tid; i < 1024; i += NTHR) {
                int r = i >> 3, q = i & 7;
                int m = m0 + r;
                float4 v0 = make_float4(0.f, 0.f, 0.f, 0.f), v1 = v0;
                if (m < N_NODES) {
                    const float4* xs = (const float4*)(x + (size_t)m * 128 + kb + q * 8);
                    v0 = xs[0]; v1 = xs[1];
                }
                float f[8] = {v0.x, v0.y, v0.z, v0.w, v1.x, v1.y, v1.z, v1.w};
                __nv_bfloat162 hh[4], hl[4];
                #pragma unroll
                for (int p = 0; p < 4; p++) {
                    __nv_bfloat16 c0 = __float2bfloat16(f[2 * p]);
                    __nv_bfloat16 c1 = __float2bfloat16(f[2 * p + 1]);
                    hh[p] = __nv_bfloat162(c0, c1);
                    hl[p] = __nv_bfloat162(__float2bfloat16(f[2 * p]     - __bfloat162float(c0)),
                                           __float2bfloat16(f[2 * p + 1] - __bfloat162float(c1)));
                }
                uint32_t doff = (uint32_t)(r * CSTR_B + q * 16);
                *(uint4*)(sb + doff)            = *(uint4*)hh;
                *(uint4*)(sb + A_TILE_B + doff) = *(uint4*)hl;
            }
        }
    }

    int warp = tid >> 5, lane = tid & 31;
    int wm = (warp / WCOLS) * 32, wn = (warp % WCOLS) * 64;
    uint32_t aoff = ((lane & 7) + ((lane >> 3) & 1) * 8) * CSTR_B + (lane >> 4) * 16;
    uint32_t woff = (lane & 7) * CSTR_B + ((lane >> 3) & 1) * 16 + ((lane >> 3) >> 1) * (8 * CSTR_B);

    float acc[2][8][4] = {};

    #pragma unroll
    for (int st = 0; st < 2; st++) {
        if (st == 0) { CP_WAIT(1); } else { CP_WAIT(0); }
        __syncthreads();
        uint32_t sb = smem_u + st * STAGE_B;
        #pragma unroll
        for (int kl = 0; kl < 64; kl += 16) {
            uint32_t ah[2][4], al[2][4], bh[8][2], bl[8][2];
            #pragma unroll
            for (int i = 0; i < 2; i++) {
                uint32_t abase = sb + (wm + i * 16) * CSTR_B + kl * 2 + aoff;
                LDSM_X4(ah[i][0], ah[i][1], ah[i][2], ah[i][3], abase);
                LDSM_X4(al[i][0], al[i][1], al[i][2], al[i][3], abase + A_TILE_B);
            }
            #pragma unroll
            for (int jp = 0; jp < 4; jp++) {
                uint32_t wb = sb + 2 * A_TILE_B + (wn + jp * 16) * CSTR_B + kl * 2 + woff;
                LDSM_X4(bh[2*jp][0], bh[2*jp][1], bh[2*jp+1][0], bh[2*jp+1][1], wb);
                LDSM_X4(bl[2*jp][0], bl[2*jp][1], bl[2*jp+1][0], bl[2*jp+1][1], wb + W_TILE_B);
            }
            #pragma unroll
            for (int j = 0; j < 8; j++) {
                #pragma unroll
                for (int i = 0; i < 2; i++) {
                    mma_bf16(acc[i][j], ah[i], bh[j][0], bh[j][1]);  // hi*hi
                    mma_bf16(acc[i][j], ah[i], bl[j][0], bl[j][1]);  // hi*lo
                    mma_bf16(acc[i][j], al[i], bh[j][0], bh[j][1]);  // lo*hi
                }
            }
        }
    }

    int g = lane >> 2, tg = lane & 3;
    #pragma unroll
    for (int i = 0; i < 2; i++) {
        #pragma unroll
        for (int j = 0; j < 8; j++) {
            int rm = m0 + wm + i * 16 + g;
            int cn = wn + j * 8 + tg * 2;
            if (cn < YC) {
                __half2 v01 = __floats2half2_rn(acc[i][j][0], acc[i][j][1]);
                __half2 v23 = __floats2half2_rn(acc[i][j][2], acc[i][j][3]);
                if (rm < N_NODES)     *(__half2*)&g_y16[(size_t)rm * YC + cn]       = v01;
                if (rm + 8 < N_NODES) *(__half2*)&g_y16[(size_t)(rm + 8) * YC + cn] = v23;
            } else {
                int hc = cn - YC;
                if (rm < N_NODES)
                    *(float2*)&g_hr[(size_t)rm * YC + hc] = make_float2(acc[i][j][0], acc[i][j][1]);
                if (rm + 8 < N_NODES)
                    *(float2*)&g_hr[(size_t)(rm + 8) * YC + hc] = make_float2(acc[i][j][2], acc[i][j][3]);
            }
        }
    }
}

// ---------------- aggregation (R5 form): out = mean(gather y16) + hr + b (+relu) ----------------
__device__ __forceinline__ void acc_half4(float4& acc, uint2 p) {
    float2 fa = __half22float2(*(__half2*)&p.x);
    float2 fb = __half22float2(*(__half2*)&p.y);
    acc.x += fa.x; acc.y += fa.y; acc.z += fb.x; acc.w += fb.y;
}

__global__ void k_agg128(const float* __restrict__ bias, int relu) {
    int warp = (blockIdx.x * blockDim.x + threadIdx.x) >> 5;
    int lane = threadIdx.x & 31;
    if (warp >= N_NODES) return;
    int rs = g_rowptr[warp], re = g_rowptr[warp + 1];
    float4 acc = make_float4(0.f, 0.f, 0.f, 0.f);
    const uint2* Y2 = (const uint2*)g_y16;
    int e = rs;
    for (; e + 4 <= re; e += 4) {
        int s0 = g_col[e], s1 = g_col[e + 1], s2 = g_col[e + 2], s3 = g_col[e + 3];
        uint2 p0 = Y2[(size_t)s0 * 32 + lane];
        uint2 p1 = Y2[(size_t)s1 * 32 + lane];
        uint2 p2 = Y2[(size_t)s2 * 32 + lane];
        uint2 p3 = Y2[(size_t)s3 * 32 + lane];
        acc_half4(acc, p0); acc_half4(acc, p1); acc_half4(acc, p2); acc_half4(acc, p3);
    }
    for (; e < re; e++) {
        uint2 p = Y2[(size_t)g_col[e] * 32 + lane];
        acc_half4(acc, p);
    }
    float inv = 1.f / fmaxf((float)(re - rs), 1.f);
    float4 hr = ((const float4*)g_hr)[(size_t)warp * 32 + lane];
    float4 b  = ((const float4*)bias)[lane];
    float o0 = acc.x * inv + hr.x + b.x;
    float o1 = acc.y * inv + hr.y + b.y;
    float o2 = acc.z * inv + hr.z + b.z;
    float o3 = acc.w * inv + hr.w + b.w;
    if (relu) {
        o0 = fmaxf(o0, 0.f); o1 = fmaxf(o1, 0.f);
        o2 = fmaxf(o2, 0.f); o3 = fmaxf(o3, 0.f);
    }
    size_t idx = (size_t)warp * 128 + lane * 4;
    __nv_bfloat16 h0 = __float2bfloat16(o0), h1 = __float2bfloat16(o1);
    __nv_bfloat16 h2 = __float2bfloat16(o2), h3 = __float2bfloat16(o3);
    *(__nv_bfloat162*)(g_ahi + idx)     = __nv_bfloat162(h0, h1);
    *(__nv_bfloat162*)(g_ahi + idx + 2) = __nv_bfloat162(h2, h3);
    __nv_bfloat16 l0 = __float2bfloat16(o0 - __bfloat162float(h0));
    __nv_bfloat16 l1 = __float2bfloat16(o1 - __bfloat162float(h1));
    __nv_bfloat16 l2 = __float2bfloat16(o2 - __bfloat162float(h2));
    __nv_bfloat16 l3 = __float2bfloat16(o3 - __bfloat162float(h3));
    *(__nv_bfloat162*)(g_alo + idx)     = __nv_bfloat162(l0, l1);
    *(__nv_bfloat162*)(g_alo + idx + 2) = __nv_bfloat162(l2, l3);
}

__global__ void k_agg64(const float* __restrict__ bias, float* __restrict__ out) {
    int gw = (blockIdx.x * blockDim.x + threadIdx.x) >> 5;
    int lane = threadIdx.x & 31;
    int half = lane >> 4, ln = lane & 15;
    int node = gw * 2 + half;
    if (node >= N_NODES) return;
    int rs = g_rowptr[node], re = g_rowptr[node + 1];
    float4 acc = make_float4(0.f, 0.f, 0.f, 0.f);
    const uint2* Y2 = (const uint2*)g_y16;
    int e = rs;
    for (; e + 4 <= re; e += 4) {
        int s0 = g_col[e], s1 = g_col[e + 1], s2 = g_col[e + 2], s3 = g_col[e + 3];
        uint2 p0 = Y2[(size_t)s0 * 16 + ln];
        uint2 p1 = Y2[(size_t)s1 * 16 + ln];
        uint2 p2 = Y2[(size_t)s2 * 16 + ln];
        uint2 p3 = Y2[(size_t)s3 * 16 + ln];
        acc_half4(acc, p0); acc_half4(acc, p1); acc_half4(acc, p2); acc_half4(acc, p3);
    }
    for (; e < re; e++) {
        uint2 p = Y2[(size_t)g_col[e] * 16 + ln];
        acc_half4(acc, p);
    }
    float inv = 1.f / fmaxf((float)(re - rs), 1.f);
    float4 hr = ((const float4*)g_hr)[(size_t)node * 16 + ln];
    float4 b  = ((const float4*)bias)[ln];
    float4 o;
    o.x = acc.x * inv + hr.x + b.x;
    o.y = acc.y * inv + hr.y + b.y;
    o.z = acc.z * inv + hr.z + b.z;
    o.w = acc.w * inv + hr.w + b.w;
    ((float4*)out)[(size_t)node * 16 + ln] = o;
}

// ---------------- launch ----------------
extern "C" void kernel_launch(void* const* d_in, const int* in_sizes, int n_in,
                              void* d_out, int out_size) {
    const float* x   = (const float*)d_in[0];
    const void*  ei  = d_in[1];
    const float* w1l = (const float*)d_in[2];
    const float* w1r = (const float*)d_in[3];
    const float* b1  = (const float*)d_in[4];
    const float* w2l = (const float*)d_in[5];
    const float* w2r = (const float*)d_in[6];
    const float* b2  = (const float*)d_in[7];
    const float* w3l = (const float*)d_in[8];
    const float* w3r = (const float*)d_in[9];
    const float* b3  = (const float*)d_in[10];
    float* out = (float*)d_out;

    constexpr int SMEM_BIG   = 2 * (2 * A_TILE_B + 2 * 256 * CSTR_B);  // 221184
    constexpr int SMEM_SMALL = 2 * (2 * A_TILE_B + 2 * 128 * CSTR_B);  // 147456
    cudaFuncSetAttribute(k_gemm<256, 512, true>,  cudaFuncAttributeMaxDynamicSharedMemorySize, SMEM_BIG);
    cudaFuncSetAttribute(k_gemm<256, 512, false>, cudaFuncAttributeMaxDynamicSharedMemorySize, SMEM_BIG);
    cudaFuncSetAttribute(k_gemm<128, 256, false>, cudaFuncAttributeMaxDynamicSharedMemorySize, SMEM_SMALL);

    void* deg_ptr = nullptr;
    cudaGetSymbolAddress(&deg_ptr, g_deg);

    dim3 grid(782, 1);

    k_detect<<<1, 32>>>((const int*)ei);
    cudaMemsetAsync(deg_ptr, 0, N_NODES * sizeof(int));
    k_convw<<<320, 256>>>(w1l, w1r, w2l, w2r, w3l, w3r);
    k_gemm<256, 512, true><<<grid, 512, SMEM_BIG>>>(0, x);   // layer-1 GEMM, fused x-conversion (profiled slot #4? keep near front)
    k_count<<<(N_EDGES + 255) / 256, 256>>>(ei);
    k_scanA<<<SCAN_NB, 1024>>>();
    k_scanC<<<(N_NODES + 255) / 256, 256>>>();
    k_fill<<<(N_EDGES + 255) / 256, 256>>>(ei);

    // layer 1 aggregate
    k_agg128<<<(N_NODES + 7) / 8, 256>>>(b1, 1);
    // layer 2
    k_gemm<256, 512, false><<<grid, 512, SMEM_BIG>>>(256, nullptr);
    k_agg128<<<(N_NODES + 7) / 8, 256>>>(b2, 1);
    // layer 3
    k_gemm<128, 256, false><<<grid, 256, SMEM_SMALL>>>(512, nullptr);
    k_agg64<<<(N_NODES / 2 + 7) / 8, 256>>>(b3, out);
}

// round 9
// speedup vs baseline: 1.1684x; 1.1557x over previous
#include <cuda_runtime.h>
#include <cuda_bf16.h>
#include <cuda_fp16.h>
#include <cstdint>

#define N_NODES 100000
#define N_PAD   100096
#define N_EDGES 1600000
#define SCAN_CHUNK 4096
#define SCAN_NB ((N_NODES + SCAN_CHUNK - 1) / SCAN_CHUNK)  // 25

#define CSTR_B 144                     // bytes per smem row (72 fp16), 16B-aligned, conflict-free
#define A_TILE_B (128 * CSTR_B)        // 18432 B

// ---------------- scratch (static device globals; no allocs) ----------------
__device__ int g_is64;
__device__ __align__(16) int g_deg[N_NODES + 4];
__device__ __align__(16) int g_rowptr[N_NODES + 4];
__device__ __align__(16) int g_cursor[N_NODES];
__device__ int g_col[N_EDGES];
__device__ int g_bsum[SCAN_NB];
__device__ __half g_y16[(size_t)N_NODES * 128];      // neighbor-transform y, fp16 gather payload
__device__ float  g_hr[(size_t)N_NODES * 128];       // root-transform, fp32
__device__ __half g_ah[(size_t)N_PAD * 128];         // activation hi (fp16; pad rows stay 0)
__device__ __half g_al[(size_t)N_PAD * 128];         // activation lo (fp16 residual)
__device__ __half g_w16[640 * 128];                  // stacked fp16 weights: L1(256) L2(256) L3(128)

// ---------------- PTX helpers ----------------
#define CP_ASYNC16(dst, src) \
    asm volatile("cp.async.cg.shared.global [%0], [%1], 16;\n" :: "r"(dst), "l"(src))
#define CP_COMMIT() asm volatile("cp.async.commit_group;\n")
#define CP_WAIT(n)  asm volatile("cp.async.wait_group %0;\n" :: "n"(n))
#define LDSM_X4(r0, r1, r2, r3, addr) \
    asm volatile("ldmatrix.sync.aligned.m8n8.x4.shared.b16 {%0,%1,%2,%3}, [%4];" \
                 : "=r"(r0), "=r"(r1), "=r"(r2), "=r"(r3) : "r"(addr))

__device__ __forceinline__ void mma_f16(float acc[4], const uint32_t a[4], uint32_t b0, uint32_t b1) {
    asm volatile(
        "mma.sync.aligned.m16n8k16.row.col.f32.f16.f16.f32 "
        "{%0,%1,%2,%3}, {%4,%5,%6,%7}, {%8,%9}, {%0,%1,%2,%3};\n"
        : "+f"(acc[0]), "+f"(acc[1]), "+f"(acc[2]), "+f"(acc[3])
        : "r"(a[0]), "r"(a[1]), "r"(a[2]), "r"(a[3]), "r"(b0), "r"(b1));
}

// ---------------- edge dtype detection (int64 vs int32) ----------------
__global__ void k_detect(const int* __restrict__ ei32) {
    if (threadIdx.x == 0 && blockIdx.x == 0) {
        int is64 = 1;
        for (int i = 0; i < 128; i++) {
            if (ei32[2 * i + 1] != 0) { is64 = 0; break; }
        }
        g_is64 = is64;
    }
}

__device__ __forceinline__ int edge_val(const void* ei, size_t idx, int is64) {
    if (is64) return (int)((const long long*)ei)[idx];
    return ((const int*)ei)[idx];
}

// ---------------- CSR build ----------------
__global__ void k_count(const void* __restrict__ ei) {
    int e = blockIdx.x * blockDim.x + threadIdx.x;
    if (e < N_EDGES) {
        int dst = edge_val(ei, (size_t)N_EDGES + e, g_is64);
        atomicAdd(&g_deg[dst], 1);
    }
}

__global__ __launch_bounds__(1024) void k_scanA() {
    __shared__ int wsum[32];
    int b = blockIdx.x, tid = threadIdx.x, lane = tid & 31, wid = tid >> 5;
    int base = b * SCAN_CHUNK + tid * 4;
    int4 v = make_int4(0, 0, 0, 0);
    if (base + 3 < N_NODES) {
        v = *(const int4*)(g_deg + base);
    } else {
        int* p = (int*)&v;
        for (int i = 0; i < 4; i++) if (base + i < N_NODES) p[i] = g_deg[base + i];
    }
    int s0 = v.x, s1 = s0 + v.y, s2 = s1 + v.z, s3 = s2 + v.w;
    int x = s3;
    #pragma unroll
    for (int s = 1; s < 32; s <<= 1) {
        int t = __shfl_up_sync(0xffffffffu, x, s);
        if (lane >= s) x += t;
    }
    if (lane == 31) wsum[wid] = x;
    __syncthreads();
    if (wid == 0) {
        int w = wsum[lane];
        #pragma unroll
        for (int s = 1; s < 32; s <<= 1) {
            int t = __shfl_up_sync(0xffffffffu, w, s);
            if (lane >= s) w += t;
        }
        wsum[lane] = w;
    }
    __syncthreads();
    int off = (wid > 0 ? wsum[wid - 1] : 0) + (x - s3);
    int4 o = make_int4(off, off + s0, off + s1, off + s2);
    if (base + 3 < N_NODES) {
        *(int4*)(g_rowptr + base) = o;
    } else {
        int* p = (int*)&o;
        for (int i = 0; i < 4; i++) if (base + i < N_NODES) g_rowptr[base + i] = p[i];
    }
    if (tid == 0) g_bsum[b] = wsum[31];
}

// scanC does the 25-element top-level scan per block (no separate scanB kernel)
__global__ void k_scanC() {
    __shared__ int boff[SCAN_NB + 1];
    int tid = threadIdx.x;
    if (tid < 32) {
        int v = (tid < SCAN_NB) ? g_bsum[tid] : 0;
        int x = v;
        #pragma unroll
        for (int s = 1; s < 32; s <<= 1) {
            int t = __shfl_up_sync(0xffffffffu, x, s);
            if (tid >= s) x += t;
        }
        if (tid < SCAN_NB) boff[tid] = x - v;
        if (tid == 31) boff[SCAN_NB] = x;
    }
    __syncthreads();
    int i = blockIdx.x * blockDim.x + tid;
    if (i < N_NODES) {
        int r = g_rowptr[i] + boff[i / SCAN_CHUNK];
        g_rowptr[i] = r;
        g_cursor[i] = r;
    }
    if (i == 0) g_rowptr[N_NODES] = boff[SCAN_NB];
}

__global__ void k_fill(const void* __restrict__ ei) {
    int e = blockIdx.x * blockDim.x + threadIdx.x;
    if (e < N_EDGES) {
        int is64 = g_is64;
        int dst = edge_val(ei, (size_t)N_EDGES + e, is64);
        int src = edge_val(ei, (size_t)e, is64);
        int pos = atomicAdd(&g_cursor[dst], 1);
        g_col[pos] = src;
    }
}

// ---------------- conversions ----------------
__global__ void k_convw(const float* __restrict__ w1l, const float* __restrict__ w1r,
                        const float* __restrict__ w2l, const float* __restrict__ w2r,
                        const float* __restrict__ w3l, const float* __restrict__ w3r) {
    int i = blockIdx.x * blockDim.x + threadIdx.x;
    if (i >= 640 * 128) return;
    int row = i >> 7, c = i & 127;
    const float* src; int r;
    if (row < 128)      { src = w1l; r = row; }
    else if (row < 256) { src = w1r; r = row - 128; }
    else if (row < 384) { src = w2l; r = row - 256; }
    else if (row < 512) { src = w2r; r = row - 384; }
    else if (row < 576) { src = w3l; r = row - 512; }
    else                { src = w3r; r = row - 576; }
    g_w16[i] = __float2half_rn(src[r * 128 + c]);
}

__global__ void k_convx(const float4* __restrict__ x) {
    int i = blockIdx.x * blockDim.x + threadIdx.x;  // over float4 chunks
    if (i >= N_NODES * 32) return;
    float4 v = x[i];
    size_t o = (size_t)i * 4;
    __half h0 = __float2half_rn(v.x), h1 = __float2half_rn(v.y);
    __half h2 = __float2half_rn(v.z), h3 = __float2half_rn(v.w);
    *(__half2*)(g_ah + o)     = __halves2half2(h0, h1);
    *(__half2*)(g_ah + o + 2) = __halves2half2(h2, h3);
    __half l0 = __float2half_rn(v.x - __half2float(h0));
    __half l1 = __float2half_rn(v.y - __half2float(h1));
    __half l2 = __float2half_rn(v.z - __half2float(h2));
    __half l3 = __float2half_rn(v.w - __half2float(h3));
    *(__half2*)(g_al + o)     = __halves2half2(l0, l1);
    *(__half2*)(g_al + o + 2) = __halves2half2(l2, l3);
}

// ---------------- GEMM: M=128 x N=NT tile, 2-stage cp.async, ldmatrix, 2-term fp16 split ----------------
// smem per stage: [Ah | Al | W]; weight rows [wbase, wbase+NT/2) = W_l (-> y fp16), rest W_r (-> hr fp32)
template<int NT, int NTHR>
__global__ __launch_bounds__(NTHR, 1) void k_gemm(int wbase) {
    constexpr int W_TILE_B = NT * CSTR_B;
    constexpr int STAGE_B  = 2 * A_TILE_B + W_TILE_B;
    constexpr int WCOLS    = NT / 64;
    constexpr int YC       = NT / 2;

    extern __shared__ __align__(16) char smemc[];
    uint32_t smem_u = (uint32_t)__cvta_generic_to_shared(smemc);
    int m0 = blockIdx.x * 128;
    int tid = threadIdx.x;

    #pragma unroll
    for (int st = 0; st < 2; st++) {
        uint32_t sb = smem_u + st * STAGE_B;
        int kb = st * 64;
        for (int i = tid; i < 2048; i += NTHR) {        // A hi+lo
            int t = i >> 10, c = i & 1023;
            int r = c >> 3, q = c & 7;
            uint32_t doff = (uint32_t)(t * A_TILE_B + r * CSTR_B + q * 16);
            const __half* src = (t == 0 ? g_ah : g_al) + (size_t)(m0 + r) * 128 + kb + q * 8;
            CP_ASYNC16(sb + doff, src);
        }
        for (int i = tid; i < NT * 8; i += NTHR) {      // W single
            int r = i >> 3, q = i & 7;
            uint32_t doff = (uint32_t)(2 * A_TILE_B + r * CSTR_B + q * 16);
            const __half* src = g_w16 + (size_t)(wbase + r) * 128 + kb + q * 8;
            CP_ASYNC16(sb + doff, src);
        }
        CP_COMMIT();
    }

    int warp = tid >> 5, lane = tid & 31;
    int wm = (warp / WCOLS) * 32, wn = (warp % WCOLS) * 64;
    uint32_t aoff = ((lane & 7) + ((lane >> 3) & 1) * 8) * CSTR_B + (lane >> 4) * 16;
    uint32_t woff = (lane & 7) * CSTR_B + ((lane >> 3) & 1) * 16 + ((lane >> 3) >> 1) * (8 * CSTR_B);

    float acc[2][8][4] = {};

    #pragma unroll
    for (int st = 0; st < 2; st++) {
        if (st == 0) { CP_WAIT(1); } else { CP_WAIT(0); }
        __syncthreads();
        uint32_t sb = smem_u + st * STAGE_B;
        #pragma unroll
        for (int kl = 0; kl < 64; kl += 16) {
            uint32_t ah[2][4], al[2][4], w[8][2];
            #pragma unroll
            for (int i = 0; i < 2; i++) {
                uint32_t abase = sb + (wm + i * 16) * CSTR_B + kl * 2 + aoff;
                LDSM_X4(ah[i][0], ah[i][1], ah[i][2], ah[i][3], abase);
                LDSM_X4(al[i][0], al[i][1], al[i][2], al[i][3], abase + A_TILE_B);
            }
            #pragma unroll
            for (int jp = 0; jp < 4; jp++) {
                uint32_t wb = sb + 2 * A_TILE_B + (wn + jp * 16) * CSTR_B + kl * 2 + woff;
                LDSM_X4(w[2*jp][0], w[2*jp][1], w[2*jp+1][0], w[2*jp+1][1], wb);
            }
            #pragma unroll
            for (int j = 0; j < 8; j++) {
                #pragma unroll
                for (int i = 0; i < 2; i++) {
                    mma_f16(acc[i][j], ah[i], w[j][0], w[j][1]);  // hi * w
                    mma_f16(acc[i][j], al[i], w[j][0], w[j][1]);  // lo * w
                }
            }
        }
    }

    int g = lane >> 2, tg = lane & 3;
    #pragma unroll
    for (int i = 0; i < 2; i++) {
        #pragma unroll
        for (int j = 0; j < 8; j++) {
            int rm = m0 + wm + i * 16 + g;
            int cn = wn + j * 8 + tg * 2;
            if (cn < YC) {
                __half2 v01 = __floats2half2_rn(acc[i][j][0], acc[i][j][1]);
                __half2 v23 = __floats2half2_rn(acc[i][j][2], acc[i][j][3]);
                if (rm < N_NODES)     *(__half2*)&g_y16[(size_t)rm * YC + cn]       = v01;
                if (rm + 8 < N_NODES) *(__half2*)&g_y16[(size_t)(rm + 8) * YC + cn] = v23;
            } else {
                int hc = cn - YC;
                if (rm < N_NODES)
                    *(float2*)&g_hr[(size_t)rm * YC + hc] = make_float2(acc[i][j][0], acc[i][j][1]);
                if (rm + 8 < N_NODES)
                    *(float2*)&g_hr[(size_t)(rm + 8) * YC + hc] = make_float2(acc[i][j][2], acc[i][j][3]);
            }
        }
    }
}

// ---------------- aggregation: out = mean(gather y16) + hr + b (+relu), emit fp16 hi/lo ----------------
__device__ __forceinline__ void acc_half4(float4& acc, uint2 p) {
    float2 fa = __half22float2(*(__half2*)&p.x);
    float2 fb = __half22float2(*(__half2*)&p.y);
    acc.x += fa.x; acc.y += fa.y; acc.z += fb.x; acc.w += fb.y;
}

__global__ void k_agg128(const float* __restrict__ bias, int relu) {
    int warp = (blockIdx.x * blockDim.x + threadIdx.x) >> 5;
    int lane = threadIdx.x & 31;
    if (warp >= N_NODES) return;
    int rs = g_rowptr[warp], re = g_rowptr[warp + 1];
    float4 acc = make_float4(0.f, 0.f, 0.f, 0.f);
    const uint2* Y2 = (const uint2*)g_y16;
    int e = rs;
    for (; e + 4 <= re; e += 4) {
        int s0 = g_col[e], s1 = g_col[e + 1], s2 = g_col[e + 2], s3 = g_col[e + 3];
        uint2 p0 = Y2[(size_t)s0 * 32 + lane];
        uint2 p1 = Y2[(size_t)s1 * 32 + lane];
        uint2 p2 = Y2[(size_t)s2 * 32 + lane];
        uint2 p3 = Y2[(size_t)s3 * 32 + lane];
        acc_half4(acc, p0); acc_half4(acc, p1); acc_half4(acc, p2); acc_half4(acc, p3);
    }
    for (; e < re; e++) {
        uint2 p = Y2[(size_t)g_col[e] * 32 + lane];
        acc_half4(acc, p);
    }
    float inv = 1.f / fmaxf((float)(re - rs), 1.f);
    float4 hr = ((const float4*)g_hr)[(size_t)warp * 32 + lane];
    float4 b  = ((const float4*)bias)[lane];
    float o0 = acc.x * inv + hr.x + b.x;
    float o1 = acc.y * inv + hr.y + b.y;
    float o2 = acc.z * inv + hr.z + b.z;
    float o3 = acc.w * inv + hr.w + b.w;
    if (relu) {
        o0 = fmaxf(o0, 0.f); o1 = fmaxf(o1, 0.f);
        o2 = fmaxf(o2, 0.f); o3 = fmaxf(o3, 0.f);
    }
    size_t idx = (size_t)warp * 128 + lane * 4;
    __half h0 = __float2half_rn(o0), h1 = __float2half_rn(o1);
    __half h2 = __float2half_rn(o2), h3 = __float2half_rn(o3);
    *(__half2*)(g_ah + idx)     = __halves2half2(h0, h1);
    *(__half2*)(g_ah + idx + 2) = __halves2half2(h2, h3);
    __half l0 = __float2half_rn(o0 - __half2float(h0));
    __half l1 = __float2half_rn(o1 - __half2float(h1));
    __half l2 = __float2half_rn(o2 - __half2float(h2));
    __half l3 = __float2half_rn(o3 - __half2float(h3));
    *(__half2*)(g_al + idx)     = __halves2half2(l0, l1);
    *(__half2*)(g_al + idx + 2) = __halves2half2(l2, l3);
}

__global__ void k_agg64(const float* __restrict__ bias, float* __restrict__ out) {
    int gw = (blockIdx.x * blockDim.x + threadIdx.x) >> 5;
    int lane = threadIdx.x & 31;
    int half = lane >> 4, ln = lane & 15;
    int node = gw * 2 + half;
    if (node >= N_NODES) return;
    int rs = g_rowptr[node], re = g_rowptr[node + 1];
    float4 acc = make_float4(0.f, 0.f, 0.f, 0.f);
    const uint2* Y2 = (const uint2*)g_y16;
    int e = rs;
    for (; e + 4 <= re; e += 4) {
        int s0 = g_col[e], s1 = g_col[e + 1], s2 = g_col[e + 2], s3 = g_col[e + 3];
        uint2 p0 = Y2[(size_t)s0 * 16 + ln];
        uint2 p1 = Y2[(size_t)s1 * 16 + ln];
        uint2 p2 = Y2[(size_t)s2 * 16 + ln];
        uint2 p3 = Y2[(size_t)s3 * 16 + ln];
        acc_half4(acc, p0); acc_half4(acc, p1); acc_half4(acc, p2); acc_half4(acc, p3);
    }
    for (; e < re; e++) {
        uint2 p = Y2[(size_t)g_col[e] * 16 + ln];
        acc_half4(acc, p);
    }
    float inv = 1.f / fmaxf((float)(re - rs), 1.f);
    float4 hr = ((const float4*)g_hr)[(size_t)node * 16 + ln];
    float4 b  = ((const float4*)bias)[ln];
    float4 o;
    o.x = acc.x * inv + hr.x + b.x;
    o.y = acc.y * inv + hr.y + b.y;
    o.z = acc.z * inv + hr.z + b.z;
    o.w = acc.w * inv + hr.w + b.w;
    ((float4*)out)[(size_t)node * 16 + ln] = o;
}

// ---------------- launch ----------------
extern "C" void kernel_launch(void* const* d_in, const int* in_sizes, int n_in,
                              void* d_out, int out_size) {
    const float* x   = (const float*)d_in[0];
    const void*  ei  = d_in[1];
    const float* w1l = (const float*)d_in[2];
    const float* w1r = (const float*)d_in[3];
    const float* b1  = (const float*)d_in[4];
    const float* w2l = (const float*)d_in[5];
    const float* w2r = (const float*)d_in[6];
    const float* b2  = (const float*)d_in[7];
    const float* w3l = (const float*)d_in[8];
    const float* w3r = (const float*)d_in[9];
    const float* b3  = (const float*)d_in[10];
    float* out = (float*)d_out;

    constexpr int SMEM_BIG   = 2 * (2 * A_TILE_B + 256 * CSTR_B);  // 147456
    constexpr int SMEM_SMALL = 2 * (2 * A_TILE_B + 128 * CSTR_B);  // 110592
    cudaFuncSetAttribute(k_gemm<256, 512>, cudaFuncAttributeMaxDynamicSharedMemorySize, SMEM_BIG);
    cudaFuncSetAttribute(k_gemm<128, 256>, cudaFuncAttributeMaxDynamicSharedMemorySize, SMEM_SMALL);

    void* deg_ptr = nullptr;
    cudaGetSymbolAddress(&deg_ptr, g_deg);

    dim3 grid(782, 1);

    k_detect<<<1, 32>>>((const int*)ei);
    cudaMemsetAsync(deg_ptr, 0, N_NODES * sizeof(int));
    k_convw<<<320, 256>>>(w1l, w1r, w2l, w2r, w3l, w3r);
    k_convx<<<(N_NODES * 32 + 255) / 256, 256>>>((const float4*)x);
    k_gemm<256, 512><<<grid, 512, SMEM_BIG>>>(0);         // layer-1 GEMM (profiled slot)
    k_count<<<(N_EDGES + 255) / 256, 256>>>(ei);
    k_scanA<<<SCAN_NB, 1024>>>();
    k_scanC<<<(N_NODES + 255) / 256, 256>>>();
    k_fill<<<(N_EDGES + 255) / 256, 256>>>(ei);

    // layer 1 aggregate
    k_agg128<<<(N_NODES + 7) / 8, 256>>>(b1, 1);
    // layer 2
    k_gemm<256, 512><<<grid, 512, SMEM_BIG>>>(256);
    k_agg128<<<(N_NODES + 7) / 8, 256>>>(b2, 1);
    // layer 3
    k_gemm<128, 256><<<grid, 256, SMEM_SMALL>>>(512);
    k_agg64<<<(N_NODES / 2 + 7) / 8, 256>>>(b3, out);
}

// round 10
// speedup vs baseline: 1.2057x; 1.0319x over previous
#include <cuda_runtime.h>
#include <cuda_bf16.h>
#include <cuda_fp16.h>
#include <cstdint>

#define N_NODES 100000
#define N_PAD   100096
#define N_EDGES 1600000
#define SCAN_CHUNK 4096
#define SCAN_NB ((N_NODES + SCAN_CHUNK - 1) / SCAN_CHUNK)  // 25

#define CSTR_B 144                     // bytes per smem row (72 fp16), 16B-aligned, conflict-free
#define A_TILE_B (128 * CSTR_B)        // 18432 B

// ---------------- scratch (static device globals; no allocs) ----------------
__device__ int g_is64;
__device__ __align__(16) int g_deg[N_NODES + 4];
__device__ __align__(16) int g_rowptr[N_NODES + 4];
__device__ __align__(16) int g_cursor[N_NODES];
__device__ int g_col[N_EDGES];
__device__ int g_bsum[SCAN_NB];
__device__ __half g_y16[(size_t)N_NODES * 128];      // neighbor-transform y, fp16 gather payload
__device__ float  g_hr[(size_t)N_NODES * 128];       // root-transform, fp32
__device__ __half g_ah[(size_t)N_PAD * 128];         // activation hi (fp16; pad rows stay 0)
__device__ __half g_al[(size_t)N_PAD * 128];         // activation lo (fp16 residual)
__device__ __half g_w16[640 * 128];                  // stacked fp16 weights: L1(256) L2(256) L3(128)

// ---------------- PTX helpers ----------------
#define CP_ASYNC16(dst, src) \
    asm volatile("cp.async.cg.shared.global [%0], [%1], 16;\n" :: "r"(dst), "l"(src))
#define CP_COMMIT() asm volatile("cp.async.commit_group;\n")
#define CP_WAIT(n)  asm volatile("cp.async.wait_group %0;\n" :: "n"(n))
#define LDSM_X4(r0, r1, r2, r3, addr) \
    asm volatile("ldmatrix.sync.aligned.m8n8.x4.shared.b16 {%0,%1,%2,%3}, [%4];" \
                 : "=r"(r0), "=r"(r1), "=r"(r2), "=r"(r3) : "r"(addr))

__device__ __forceinline__ void mma_f16(float acc[4], const uint32_t a[4], uint32_t b0, uint32_t b1) {
    asm volatile(
        "mma.sync.aligned.m16n8k16.row.col.f32.f16.f16.f32 "
        "{%0,%1,%2,%3}, {%4,%5,%6,%7}, {%8,%9}, {%0,%1,%2,%3};\n"
        : "+f"(acc[0]), "+f"(acc[1]), "+f"(acc[2]), "+f"(acc[3])
        : "r"(a[0]), "r"(a[1]), "r"(a[2]), "r"(a[3]), "r"(b0), "r"(b1));
}

// ---------------- edge dtype detection (int64 vs int32) ----------------
__global__ void k_detect(const int* __restrict__ ei32) {
    if (threadIdx.x == 0 && blockIdx.x == 0) {
        int is64 = 1;
        for (int i = 0; i < 128; i++) {
            if (ei32[2 * i + 1] != 0) { is64 = 0; break; }
        }
        g_is64 = is64;
    }
}

// ---------------- CSR build (2 edges per thread) ----------------
__global__ void k_count(const void* __restrict__ ei) {
    int p = blockIdx.x * blockDim.x + threadIdx.x;   // pair index
    if (p * 2 >= N_EDGES) return;
    int d0, d1;
    if (g_is64) {
        longlong2 v = ((const longlong2*)ei)[N_EDGES / 2 + p];
        d0 = (int)v.x; d1 = (int)v.y;
    } else {
        int2 v = ((const int2*)ei)[N_EDGES / 2 + p];
        d0 = v.x; d1 = v.y;
    }
    atomicAdd(&g_deg[d0], 1);
    atomicAdd(&g_deg[d1], 1);
}

__global__ __launch_bounds__(1024) void k_scanA() {
    __shared__ int wsum[32];
    int b = blockIdx.x, tid = threadIdx.x, lane = tid & 31, wid = tid >> 5;
    int base = b * SCAN_CHUNK + tid * 4;
    int4 v = make_int4(0, 0, 0, 0);
    if (base + 3 < N_NODES) {
        v = *(const int4*)(g_deg + base);
    } else {
        int* p = (int*)&v;
        for (int i = 0; i < 4; i++) if (base + i < N_NODES) p[i] = g_deg[base + i];
    }
    int s0 = v.x, s1 = s0 + v.y, s2 = s1 + v.z, s3 = s2 + v.w;
    int x = s3;
    #pragma unroll
    for (int s = 1; s < 32; s <<= 1) {
        int t = __shfl_up_sync(0xffffffffu, x, s);
        if (lane >= s) x += t;
    }
    if (lane == 31) wsum[wid] = x;
    __syncthreads();
    if (wid == 0) {
        int w = wsum[lane];
        #pragma unroll
        for (int s = 1; s < 32; s <<= 1) {
            int t = __shfl_up_sync(0xffffffffu, w, s);
            if (lane >= s) w += t;
        }
        wsum[lane] = w;
    }
    __syncthreads();
    int off = (wid > 0 ? wsum[wid - 1] : 0) + (x - s3);
    int4 o = make_int4(off, off + s0, off + s1, off + s2);
    if (base + 3 < N_NODES) {
        *(int4*)(g_rowptr + base) = o;
    } else {
        int* p = (int*)&o;
        for (int i = 0; i < 4; i++) if (base + i < N_NODES) g_rowptr[base + i] = p[i];
    }
    if (tid == 0) g_bsum[b] = wsum[31];
}

// scanC does the 25-element top-level scan per block (no separate scanB kernel)
__global__ void k_scanC() {
    __shared__ int boff[SCAN_NB + 1];
    int tid = threadIdx.x;
    if (tid < 32) {
        int v = (tid < SCAN_NB) ? g_bsum[tid] : 0;
        int x = v;
        #pragma unroll
        for (int s = 1; s < 32; s <<= 1) {
            int t = __shfl_up_sync(0xffffffffu, x, s);
            if (tid >= s) x += t;
        }
        if (tid < SCAN_NB) boff[tid] = x - v;
        if (tid == 31) boff[SCAN_NB] = x;
    }
    __syncthreads();
    int i = blockIdx.x * blockDim.x + tid;
    if (i < N_NODES) {
        int r = g_rowptr[i] + boff[i / SCAN_CHUNK];
        g_rowptr[i] = r;
        g_cursor[i] = r;
    }
    if (i == 0) g_rowptr[N_NODES] = boff[SCAN_NB];
}

__global__ void k_fill(const void* __restrict__ ei) {
    int p = blockIdx.x * blockDim.x + threadIdx.x;   // pair index
    if (p * 2 >= N_EDGES) return;
    int d0, d1, s0, s1;
    if (g_is64) {
        longlong2 vd = ((const longlong2*)ei)[N_EDGES / 2 + p];
        longlong2 vs = ((const longlong2*)ei)[p];
        d0 = (int)vd.x; d1 = (int)vd.y; s0 = (int)vs.x; s1 = (int)vs.y;
    } else {
        int2 vd = ((const int2*)ei)[N_EDGES / 2 + p];
        int2 vs = ((const int2*)ei)[p];
        d0 = vd.x; d1 = vd.y; s0 = vs.x; s1 = vs.y;
    }
    g_col[atomicAdd(&g_cursor[d0], 1)] = s0;
    g_col[atomicAdd(&g_cursor[d1], 1)] = s1;
}

// ---------------- conversions ----------------
__global__ void k_convw(const float* __restrict__ w1l, const float* __restrict__ w1r,
                        const float* __restrict__ w2l, const float* __restrict__ w2r,
                        const float* __restrict__ w3l, const float* __restrict__ w3r) {
    int i = blockIdx.x * blockDim.x + threadIdx.x;
    if (i >= 640 * 128) return;
    int row = i >> 7, c = i & 127;
    const float* src; int r;
    if (row < 128)      { src = w1l; r = row; }
    else if (row < 256) { src = w1r; r = row - 128; }
    else if (row < 384) { src = w2l; r = row - 256; }
    else if (row < 512) { src = w2r; r = row - 384; }
    else if (row < 576) { src = w3l; r = row - 512; }
    else                { src = w3r; r = row - 576; }
    g_w16[i] = __float2half_rn(src[r * 128 + c]);
}

__global__ void k_convx(const float4* __restrict__ x) {
    int i = blockIdx.x * blockDim.x + threadIdx.x;  // over float4 chunks
    if (i >= N_NODES * 32) return;
    float4 v = x[i];
    size_t o = (size_t)i * 4;
    __half h0 = __float2half_rn(v.x), h1 = __float2half_rn(v.y);
    __half h2 = __float2half_rn(v.z), h3 = __float2half_rn(v.w);
    *(__half2*)(g_ah + o)     = __halves2half2(h0, h1);
    *(__half2*)(g_ah + o + 2) = __halves2half2(h2, h3);
    __half l0 = __float2half_rn(v.x - __half2float(h0));
    __half l1 = __float2half_rn(v.y - __half2float(h1));
    __half l2 = __float2half_rn(v.z - __half2float(h2));
    __half l3 = __float2half_rn(v.w - __half2float(h3));
    *(__half2*)(g_al + o)     = __halves2half2(l0, l1);
    *(__half2*)(g_al + o + 2) = __halves2half2(l2, l3);
}

// ---------------- GEMM: M=128 x N=NT tile, 2-stage cp.async, ldmatrix, 2-term fp16 split ----------------
template<int NT, int NTHR>
__global__ __launch_bounds__(NTHR, 1) void k_gemm(int wbase) {
    constexpr int W_TILE_B = NT * CSTR_B;
    constexpr int STAGE_B  = 2 * A_TILE_B + W_TILE_B;
    constexpr int WCOLS    = NT / 64;
    constexpr int YC       = NT / 2;

    extern __shared__ __align__(16) char smemc[];
    uint32_t smem_u = (uint32_t)__cvta_generic_to_shared(smemc);
    int m0 = blockIdx.x * 128;
    int tid = threadIdx.x;

    #pragma unroll
    for (int st = 0; st < 2; st++) {
        uint32_t sb = smem_u + st * STAGE_B;
        int kb = st * 64;
        for (int i = tid; i < 2048; i += NTHR) {        // A hi+lo
            int t = i >> 10, c = i & 1023;
            int r = c >> 3, q = c & 7;
            uint32_t doff = (uint32_t)(t * A_TILE_B + r * CSTR_B + q * 16);
            const __half* src = (t == 0 ? g_ah : g_al) + (size_t)(m0 + r) * 128 + kb + q * 8;
            CP_ASYNC16(sb + doff, src);
        }
        for (int i = tid; i < NT * 8; i += NTHR) {      // W single
            int r = i >> 3, q = i & 7;
            uint32_t doff = (uint32_t)(2 * A_TILE_B + r * CSTR_B + q * 16);
            const __half* src = g_w16 + (size_t)(wbase + r) * 128 + kb + q * 8;
            CP_ASYNC16(sb + doff, src);
        }
        CP_COMMIT();
    }

    int warp = tid >> 5, lane = tid & 31;
    int wm = (warp / WCOLS) * 32, wn = (warp % WCOLS) * 64;
    uint32_t aoff = ((lane & 7) + ((lane >> 3) & 1) * 8) * CSTR_B + (lane >> 4) * 16;
    uint32_t woff = (lane & 7) * CSTR_B + ((lane >> 3) & 1) * 16 + ((lane >> 3) >> 1) * (8 * CSTR_B);

    float acc[2][8][4] = {};

    #pragma unroll
    for (int st = 0; st < 2; st++) {
        if (st == 0) { CP_WAIT(1); } else { CP_WAIT(0); }
        __syncthreads();
        uint32_t sb = smem_u + st * STAGE_B;
        #pragma unroll
        for (int kl = 0; kl < 64; kl += 16) {
            uint32_t ah[2][4], al[2][4], w[8][2];
            #pragma unroll
            for (int i = 0; i < 2; i++) {
                uint32_t abase = sb + (wm + i * 16) * CSTR_B + kl * 2 + aoff;
                LDSM_X4(ah[i][0], ah[i][1], ah[i][2], ah[i][3], abase);
                LDSM_X4(al[i][0], al[i][1], al[i][2], al[i][3], abase + A_TILE_B);
            }
            #pragma unroll
            for (int jp = 0; jp < 4; jp++) {
                uint32_t wb = sb + 2 * A_TILE_B + (wn + jp * 16) * CSTR_B + kl * 2 + woff;
                LDSM_X4(w[2*jp][0], w[2*jp][1], w[2*jp+1][0], w[2*jp+1][1], wb);
            }
            #pragma unroll
            for (int j = 0; j < 8; j++) {
                #pragma unroll
                for (int i = 0; i < 2; i++) {
                    mma_f16(acc[i][j], ah[i], w[j][0], w[j][1]);  // hi * w
                    mma_f16(acc[i][j], al[i], w[j][0], w[j][1]);  // lo * w
                }
            }
        }
    }

    int g = lane >> 2, tg = lane & 3;
    #pragma unroll
    for (int i = 0; i < 2; i++) {
        #pragma unroll
        for (int j = 0; j < 8; j++) {
            int rm = m0 + wm + i * 16 + g;
            int cn = wn + j * 8 + tg * 2;
            if (cn < YC) {
                __half2 v01 = __floats2half2_rn(acc[i][j][0], acc[i][j][1]);
                __half2 v23 = __floats2half2_rn(acc[i][j][2], acc[i][j][3]);
                if (rm < N_NODES)     *(__half2*)&g_y16[(size_t)rm * YC + cn]       = v01;
                if (rm + 8 < N_NODES) *(__half2*)&g_y16[(size_t)(rm + 8) * YC + cn] = v23;
            } else {
                int hc = cn - YC;
                if (rm < N_NODES)
                    *(float2*)&g_hr[(size_t)rm * YC + hc] = make_float2(acc[i][j][0], acc[i][j][1]);
                if (rm + 8 < N_NODES)
                    *(float2*)&g_hr[(size_t)(rm + 8) * YC + hc] = make_float2(acc[i][j][2], acc[i][j][3]);
            }
        }
    }
}

// ---------------- aggregation: out = mean(gather y16) + hr + b (+relu), emit fp16 hi/lo ----------------
__device__ __forceinline__ void acc_half4(float4& acc, uint2 p) {
    float2 fa = __half22float2(*(__half2*)&p.x);
    float2 fb = __half22float2(*(__half2*)&p.y);
    acc.x += fa.x; acc.y += fa.y; acc.z += fb.x; acc.w += fb.y;
}

__global__ void k_agg128(const float* __restrict__ bias, int relu) {
    int warp = (blockIdx.x * blockDim.x + threadIdx.x) >> 5;
    int lane = threadIdx.x & 31;
    if (warp >= N_NODES) return;
    int rs = g_rowptr[warp], re = g_rowptr[warp + 1];
    float4 acc = make_float4(0.f, 0.f, 0.f, 0.f);
    const uint2* Y2 = (const uint2*)g_y16;
    int e = rs;
    for (; e + 4 <= re; e += 4) {
        int s0 = g_col[e], s1 = g_col[e + 1], s2 = g_col[e + 2], s3 = g_col[e + 3];
        uint2 p0 = Y2[(size_t)s0 * 32 + lane];
        uint2 p1 = Y2[(size_t)s1 * 32 + lane];
        uint2 p2 = Y2[(size_t)s2 * 32 + lane];
        uint2 p3 = Y2[(size_t)s3 * 32 + lane];
        acc_half4(acc, p0); acc_half4(acc, p1); acc_half4(acc, p2); acc_half4(acc, p3);
    }
    for (; e < re; e++) {
        uint2 p = Y2[(size_t)g_col[e] * 32 + lane];
        acc_half4(acc, p);
    }
    float inv = 1.f / fmaxf((float)(re - rs), 1.f);
    float4 hr = ((const float4*)g_hr)[(size_t)warp * 32 + lane];
    float4 b  = ((const float4*)bias)[lane];
    float o0 = acc.x * inv + hr.x + b.x;
    float o1 = acc.y * inv + hr.y + b.y;
    float o2 = acc.z * inv + hr.z + b.z;
    float o3 = acc.w * inv + hr.w + b.w;
    if (relu) {
        o0 = fmaxf(o0, 0.f); o1 = fmaxf(o1, 0.f);
        o2 = fmaxf(o2, 0.f); o3 = fmaxf(o3, 0.f);
    }
    size_t idx = (size_t)warp * 128 + lane * 4;
    __half h0 = __float2half_rn(o0), h1 = __float2half_rn(o1);
    __half h2 = __float2half_rn(o2), h3 = __float2half_rn(o3);
    *(__half2*)(g_ah + idx)     = __halves2half2(h0, h1);
    *(__half2*)(g_ah + idx + 2) = __halves2half2(h2, h3);
    __half l0 = __float2half_rn(o0 - __half2float(h0));
    __half l1 = __float2half_rn(o1 - __half2float(h1));
    __half l2 = __float2half_rn(o2 - __half2float(h2));
    __half l3 = __float2half_rn(o3 - __half2float(h3));
    *(__half2*)(g_al + idx)     = __halves2half2(l0, l1);
    *(__half2*)(g_al + idx + 2) = __halves2half2(l2, l3);
}

__global__ void k_agg64(const float* __restrict__ bias, float* __restrict__ out) {
    int gw = (blockIdx.x * blockDim.x + threadIdx.x) >> 5;
    int lane = threadIdx.x & 31;
    int half = lane >> 4, ln = lane & 15;
    int node = gw * 2 + half;
    if (node >= N_NODES) return;
    int rs = g_rowptr[node], re = g_rowptr[node + 1];
    float4 acc = make_float4(0.f, 0.f, 0.f, 0.f);
    const uint2* Y2 = (const uint2*)g_y16;
    int e = rs;
    for (; e + 4 <= re; e += 4) {
        int s0 = g_col[e], s1 = g_col[e + 1], s2 = g_col[e + 2], s3 = g_col[e + 3];
        uint2 p0 = Y2[(size_t)s0 * 16 + ln];
        uint2 p1 = Y2[(size_t)s1 * 16 + ln];
        uint2 p2 = Y2[(size_t)s2 * 16 + ln];
        uint2 p3 = Y2[(size_t)s3 * 16 + ln];
        acc_half4(acc, p0); acc_half4(acc, p1); acc_half4(acc, p2); acc_half4(acc, p3);
    }
    for (; e < re; e++) {
        uint2 p = Y2[(size_t)g_col[e] * 16 + ln];
        acc_half4(acc, p);
    }
    float inv = 1.f / fmaxf((float)(re - rs), 1.f);
    float4 hr = ((const float4*)g_hr)[(size_t)node * 16 + ln];
    float4 b  = ((const float4*)bias)[ln];
    float4 o;
    o.x = acc.x * inv + hr.x + b.x;
    o.y = acc.y * inv + hr.y + b.y;
    o.z = acc.z * inv + hr.z + b.z;
    o.w = acc.w * inv + hr.w + b.w;
    ((float4*)out)[(size_t)node * 16 + ln] = o;
}

// ---------------- launch ----------------
extern "C" void kernel_launch(void* const* d_in, const int* in_sizes, int n_in,
                              void* d_out, int out_size) {
    const float* x   = (const float*)d_in[0];
    const void*  ei  = d_in[1];
    const float* w1l = (const float*)d_in[2];
    const float* w1r = (const float*)d_in[3];
    const float* b1  = (const float*)d_in[4];
    const float* w2l = (const float*)d_in[5];
    const float* w2r = (const float*)d_in[6];
    const float* b2  = (const float*)d_in[7];
    const float* w3l = (const float*)d_in[8];
    const float* w3r = (const float*)d_in[9];
    const float* b3  = (const float*)d_in[10];
    float* out = (float*)d_out;

    constexpr int SMEM_BIG   = 2 * (2 * A_TILE_B + 256 * CSTR_B);  // 147456
    constexpr int SMEM_SMALL = 2 * (2 * A_TILE_B + 128 * CSTR_B);  // 110592
    cudaFuncSetAttribute(k_gemm<256, 512>, cudaFuncAttributeMaxDynamicSharedMemorySize, SMEM_BIG);
    cudaFuncSetAttribute(k_gemm<128, 256>, cudaFuncAttributeMaxDynamicSharedMemorySize, SMEM_SMALL);

    // lazily created side stream + fork/join events (host objects; no device allocs)
    static cudaStream_t s2 = nullptr;
    static cudaEvent_t evFork = nullptr, evJoin = nullptr;
    if (s2 == nullptr) {
        cudaStreamCreateWithFlags(&s2, cudaStreamNonBlocking);
        cudaEventCreateWithFlags(&evFork, cudaEventDisableTiming);
        cudaEventCreateWithFlags(&evJoin, cudaEventDisableTiming);
    }

    void* deg_ptr = nullptr;
    cudaGetSymbolAddress(&deg_ptr, g_deg);

    dim3 grid(782, 1);
    const int EPAIR_BLKS = (N_EDGES / 2 + 255) / 256;   // 3125

    // ---- stream 0: prerequisites for both branches ----
    k_detect<<<1, 32>>>((const int*)ei);
    cudaMemsetAsync(deg_ptr, 0, N_NODES * sizeof(int));
    cudaEventRecord(evFork, 0);

    // ---- side stream: CSR build chain (independent of conv/GEMM) ----
    cudaStreamWaitEvent(s2, evFork, 0);
    k_count<<<EPAIR_BLKS, 256, 0, s2>>>(ei);
    k_scanA<<<SCAN_NB, 1024, 0, s2>>>();
    k_scanC<<<(N_NODES + 255) / 256, 256, 0, s2>>>();
    k_fill<<<EPAIR_BLKS, 256, 0, s2>>>(ei);
    cudaEventRecord(evJoin, s2);

    // ---- stream 0: conversions + layer-1 GEMM (overlaps CSR chain) ----
    k_convw<<<320, 256>>>(w1l, w1r, w2l, w2r, w3l, w3r);
    k_convx<<<(N_NODES * 32 + 255) / 256, 256>>>((const float4*)x);
    k_gemm<256, 512><<<grid, 512, SMEM_BIG>>>(0);

    // ---- join: aggregation needs the CSR ----
    cudaStreamWaitEvent(0, evJoin, 0);
    k_agg128<<<(N_NODES + 7) / 8, 256>>>(b1, 1);
    // layer 2
    k_gemm<256, 512><<<grid, 512, SMEM_BIG>>>(256);
    k_agg128<<<(N_NODES + 7) / 8, 256>>>(b2, 1);
    // layer 3
    k_gemm<128, 256><<<grid, 256, SMEM_SMALL>>>(512);
    k_agg64<<<(N_NODES / 2 + 7) / 8, 256>>>(b3, out);
}

// round 11
// speedup vs baseline: 1.2225x; 1.0139x over previous
#include <cuda_runtime.h>
#include <cuda_bf16.h>
#include <cuda_fp16.h>
#include <cstdint>

#define N_NODES 100000
#define N_PAD   100096
#define N_EDGES 1600000
#define SCAN_CHUNK 4096
#define SCAN_NB ((N_NODES + SCAN_CHUNK - 1) / SCAN_CHUNK)  // 25

#define CSTR_B 144                     // bytes per smem row (72 fp16), 16B-aligned, conflict-free
#define A_TILE_B (128 * CSTR_B)        // 18432 B

// ---------------- scratch (static device globals; no allocs) ----------------
__device__ int g_is64;
__device__ __align__(16) int g_deg[N_NODES + 4];
__device__ __align__(16) int g_rowptr[N_NODES + 4];
__device__ __align__(16) int g_cursor[N_NODES];
__device__ int g_col[N_EDGES];
__device__ int g_bsum[SCAN_NB];
__device__ __half g_y16[(size_t)N_NODES * 128];      // neighbor-transform y, fp16 gather payload
__device__ __half g_hr16[(size_t)N_NODES * 128];     // root-transform, fp16
__device__ __half g_ah[(size_t)N_PAD * 128];         // activation hi (fp16; pad rows stay 0)
__device__ __half g_al[(size_t)N_PAD * 128];         // activation lo (fp16 residual)
__device__ __half g_w16[640 * 128];                  // stacked fp16 weights: L1(256) L2(256) L3(128)

// ---------------- PTX helpers ----------------
#define CP_ASYNC16(dst, src) \
    asm volatile("cp.async.cg.shared.global [%0], [%1], 16;\n" :: "r"(dst), "l"(src))
#define CP_COMMIT() asm volatile("cp.async.commit_group;\n")
#define CP_WAIT(n)  asm volatile("cp.async.wait_group %0;\n" :: "n"(n))
#define LDSM_X4(r0, r1, r2, r3, addr) \
    asm volatile("ldmatrix.sync.aligned.m8n8.x4.shared.b16 {%0,%1,%2,%3}, [%4];" \
                 : "=r"(r0), "=r"(r1), "=r"(r2), "=r"(r3) : "r"(addr))

__device__ __forceinline__ void mma_f16(float acc[4], const uint32_t a[4], uint32_t b0, uint32_t b1) {
    asm volatile(
        "mma.sync.aligned.m16n8k16.row.col.f32.f16.f16.f32 "
        "{%0,%1,%2,%3}, {%4,%5,%6,%7}, {%8,%9}, {%0,%1,%2,%3};\n"
        : "+f"(acc[0]), "+f"(acc[1]), "+f"(acc[2]), "+f"(acc[3])
        : "r"(a[0]), "r"(a[1]), "r"(a[2]), "r"(a[3]), "r"(b0), "r"(b1));
}

// ---------------- edge dtype detection (int64 vs int32) ----------------
__global__ void k_detect(const int* __restrict__ ei32) {
    if (threadIdx.x == 0 && blockIdx.x == 0) {
        int is64 = 1;
        for (int i = 0; i < 128; i++) {
            if (ei32[2 * i + 1] != 0) { is64 = 0; break; }
        }
        g_is64 = is64;
    }
}

// ---------------- CSR build (2 edges per thread) ----------------
__global__ void k_count(const void* __restrict__ ei) {
    int p = blockIdx.x * blockDim.x + threadIdx.x;   // pair index
    if (p * 2 >= N_EDGES) return;
    int d0, d1;
    if (g_is64) {
        longlong2 v = ((const longlong2*)ei)[N_EDGES / 2 + p];
        d0 = (int)v.x; d1 = (int)v.y;
    } else {
        int2 v = ((const int2*)ei)[N_EDGES / 2 + p];
        d0 = v.x; d1 = v.y;
    }
    atomicAdd(&g_deg[d0], 1);
    atomicAdd(&g_deg[d1], 1);
}

__global__ __launch_bounds__(1024) void k_scanA() {
    __shared__ int wsum[32];
    int b = blockIdx.x, tid = threadIdx.x, lane = tid & 31, wid = tid >> 5;
    int base = b * SCAN_CHUNK + tid * 4;
    int4 v = make_int4(0, 0, 0, 0);
    if (base + 3 < N_NODES) {
        v = *(const int4*)(g_deg + base);
    } else {
        int* p = (int*)&v;
        for (int i = 0; i < 4; i++) if (base + i < N_NODES) p[i] = g_deg[base + i];
    }
    int s0 = v.x, s1 = s0 + v.y, s2 = s1 + v.z, s3 = s2 + v.w;
    int x = s3;
    #pragma unroll
    for (int s = 1; s < 32; s <<= 1) {
        int t = __shfl_up_sync(0xffffffffu, x, s);
        if (lane >= s) x += t;
    }
    if (lane == 31) wsum[wid] = x;
    __syncthreads();
    if (wid == 0) {
        int w = wsum[lane];
        #pragma unroll
        for (int s = 1; s < 32; s <<= 1) {
            int t = __shfl_up_sync(0xffffffffu, w, s);
            if (lane >= s) w += t;
        }
        wsum[lane] = w;
    }
    __syncthreads();
    int off = (wid > 0 ? wsum[wid - 1] : 0) + (x - s3);
    int4 o = make_int4(off, off + s0, off + s1, off + s2);
    if (base + 3 < N_NODES) {
        *(int4*)(g_rowptr + base) = o;
    } else {
        int* p = (int*)&o;
        for (int i = 0; i < 4; i++) if (base + i < N_NODES) g_rowptr[base + i] = p[i];
    }
    if (tid == 0) g_bsum[b] = wsum[31];
}

// scanC does the 25-element top-level scan per block
__global__ void k_scanC() {
    __shared__ int boff[SCAN_NB + 1];
    int tid = threadIdx.x;
    if (tid < 32) {
        int v = (tid < SCAN_NB) ? g_bsum[tid] : 0;
        int x = v;
        #pragma unroll
        for (int s = 1; s < 32; s <<= 1) {
            int t = __shfl_up_sync(0xffffffffu, x, s);
            if (tid >= s) x += t;
        }
        if (tid < SCAN_NB) boff[tid] = x - v;
        if (tid == 31) boff[SCAN_NB] = x;
    }
    __syncthreads();
    int i = blockIdx.x * blockDim.x + tid;
    if (i < N_NODES) {
        int r = g_rowptr[i] + boff[i / SCAN_CHUNK];
        g_rowptr[i] = r;
        g_cursor[i] = r;
    }
    if (i == 0) g_rowptr[N_NODES] = boff[SCAN_NB];
}

__global__ void k_fill(const void* __restrict__ ei) {
    int p = blockIdx.x * blockDim.x + threadIdx.x;   // pair index
    if (p * 2 >= N_EDGES) return;
    int d0, d1, s0, s1;
    if (g_is64) {
        longlong2 vd = ((const longlong2*)ei)[N_EDGES / 2 + p];
        longlong2 vs = ((const longlong2*)ei)[p];
        d0 = (int)vd.x; d1 = (int)vd.y; s0 = (int)vs.x; s1 = (int)vs.y;
    } else {
        int2 vd = ((const int2*)ei)[N_EDGES / 2 + p];
        int2 vs = ((const int2*)ei)[p];
        d0 = vd.x; d1 = vd.y; s0 = vs.x; s1 = vs.y;
    }
    g_col[atomicAdd(&g_cursor[d0], 1)] = s0;
    g_col[atomicAdd(&g_cursor[d1], 1)] = s1;
}

// ---------------- fused conversions: x -> (ah, al) fp16 split; weights -> w16 ----------------
#define X_BLKS 12500   // N_NODES * 32 float4 chunks / 256
__global__ void k_conv(const float4* __restrict__ x,
                       const float* __restrict__ w1l, const float* __restrict__ w1r,
                       const float* __restrict__ w2l, const float* __restrict__ w2r,
                       const float* __restrict__ w3l, const float* __restrict__ w3r) {
    int b = blockIdx.x;
    if (b < X_BLKS) {
        int i = b * blockDim.x + threadIdx.x;  // over float4 chunks
        if (i >= N_NODES * 32) return;
        float4 v = x[i];
        size_t o = (size_t)i * 4;
        __half h0 = __float2half_rn(v.x), h1 = __float2half_rn(v.y);
        __half h2 = __float2half_rn(v.z), h3 = __float2half_rn(v.w);
        *(__half2*)(g_ah + o)     = __halves2half2(h0, h1);
        *(__half2*)(g_ah + o + 2) = __halves2half2(h2, h3);
        __half l0 = __float2half_rn(v.x - __half2float(h0));
        __half l1 = __float2half_rn(v.y - __half2float(h1));
        __half l2 = __float2half_rn(v.z - __half2float(h2));
        __half l3 = __float2half_rn(v.w - __half2float(h3));
        *(__half2*)(g_al + o)     = __halves2half2(l0, l1);
        *(__half2*)(g_al + o + 2) = __halves2half2(l2, l3);
    } else {
        int i = (b - X_BLKS) * blockDim.x + threadIdx.x;
        if (i >= 640 * 128) return;
        int row = i >> 7, c = i & 127;
        const float* src; int r;
        if (row < 128)      { src = w1l; r = row; }
        else if (row < 256) { src = w1r; r = row - 128; }
        else if (row < 384) { src = w2l; r = row - 256; }
        else if (row < 512) { src = w2r; r = row - 384; }
        else if (row < 576) { src = w3l; r = row - 512; }
        else                { src = w3r; r = row - 576; }
        g_w16[i] = __float2half_rn(src[r * 128 + c]);
    }
}

// ---------------- GEMM: M=128 x N=NT tile, 2-stage cp.async, ldmatrix, 2-term fp16 split ----------------
template<int NT, int NTHR>
__global__ __launch_bounds__(NTHR, 1) void k_gemm(int wbase) {
    constexpr int W_TILE_B = NT * CSTR_B;
    constexpr int STAGE_B  = 2 * A_TILE_B + W_TILE_B;
    constexpr int WCOLS    = NT / 64;
    constexpr int YC       = NT / 2;

    extern __shared__ __align__(16) char smemc[];
    uint32_t smem_u = (uint32_t)__cvta_generic_to_shared(smemc);
    int m0 = blockIdx.x * 128;
    int tid = threadIdx.x;

    #pragma unroll
    for (int st = 0; st < 2; st++) {
        uint32_t sb = smem_u + st * STAGE_B;
        int kb = st * 64;
        for (int i = tid; i < 2048; i += NTHR) {        // A hi+lo
            int t = i >> 10, c = i & 1023;
            int r = c >> 3, q = c & 7;
            uint32_t doff = (uint32_t)(t * A_TILE_B + r * CSTR_B + q * 16);
            const __half* src = (t == 0 ? g_ah : g_al) + (size_t)(m0 + r) * 128 + kb + q * 8;
            CP_ASYNC16(sb + doff, src);
        }
        for (int i = tid; i < NT * 8; i += NTHR) {      // W single
            int r = i >> 3, q = i & 7;
            uint32_t doff = (uint32_t)(2 * A_TILE_B + r * CSTR_B + q * 16);
            const __half* src = g_w16 + (size_t)(wbase + r) * 128 + kb + q * 8;
            CP_ASYNC16(sb + doff, src);
        }
        CP_COMMIT();
    }

    int warp = tid >> 5, lane = tid & 31;
    int wm = (warp / WCOLS) * 32, wn = (warp % WCOLS) * 64;
    uint32_t aoff = ((lane & 7) + ((lane >> 3) & 1) * 8) * CSTR_B + (lane >> 4) * 16;
    uint32_t woff = (lane & 7) * CSTR_B + ((lane >> 3) & 1) * 16 + ((lane >> 3) >> 1) * (8 * CSTR_B);

    float acc[2][8][4] = {};

    #pragma unroll
    for (int st = 0; st < 2; st++) {
        if (st == 0) { CP_WAIT(1); } else { CP_WAIT(0); }
        __syncthreads();
        uint32_t sb = smem_u + st * STAGE_B;
        #pragma unroll
        for (int kl = 0; kl < 64; kl += 16) {
            uint32_t ah[2][4], al[2][4], w[8][2];
            #pragma unroll
            for (int i = 0; i < 2; i++) {
                uint32_t abase = sb + (wm + i * 16) * CSTR_B + kl * 2 + aoff;
                LDSM_X4(ah[i][0], ah[i][1], ah[i][2], ah[i][3], abase);
                LDSM_X4(al[i][0], al[i][1], al[i][2], al[i][3], abase + A_TILE_B);
            }
            #pragma unroll
            for (int jp = 0; jp < 4; jp++) {
                uint32_t wb = sb + 2 * A_TILE_B + (wn + jp * 16) * CSTR_B + kl * 2 + woff;
                LDSM_X4(w[2*jp][0], w[2*jp][1], w[2*jp+1][0], w[2*jp+1][1], wb);
            }
            #pragma unroll
            for (int j = 0; j < 8; j++) {
                #pragma unroll
                for (int i = 0; i < 2; i++) {
                    mma_f16(acc[i][j], ah[i], w[j][0], w[j][1]);  // hi * w
                    mma_f16(acc[i][j], al[i], w[j][0], w[j][1]);  // lo * w
                }
            }
        }
    }

    int g = lane >> 2, tg = lane & 3;
    #pragma unroll
    for (int i = 0; i < 2; i++) {
        #pragma unroll
        for (int j = 0; j < 8; j++) {
            int rm = m0 + wm + i * 16 + g;
            int cn = wn + j * 8 + tg * 2;
            __half2 v01 = __floats2half2_rn(acc[i][j][0], acc[i][j][1]);
            __half2 v23 = __floats2half2_rn(acc[i][j][2], acc[i][j][3]);
            if (cn < YC) {
                if (rm < N_NODES)     *(__half2*)&g_y16[(size_t)rm * YC + cn]       = v01;
                if (rm + 8 < N_NODES) *(__half2*)&g_y16[(size_t)(rm + 8) * YC + cn] = v23;
            } else {
                int hc = cn - YC;
                if (rm < N_NODES)     *(__half2*)&g_hr16[(size_t)rm * YC + hc]       = v01;
                if (rm + 8 < N_NODES) *(__half2*)&g_hr16[(size_t)(rm + 8) * YC + hc] = v23;
            }
        }
    }
}

// ---------------- aggregation: out = mean(gather y16) + hr16 + b (+relu), emit fp16 hi/lo ----------------
__device__ __forceinline__ void acc_half4(float4& acc, uint2 p) {
    float2 fa = __half22float2(*(__half2*)&p.x);
    float2 fb = __half22float2(*(__half2*)&p.y);
    acc.x += fa.x; acc.y += fa.y; acc.z += fb.x; acc.w += fb.y;
}

__device__ __forceinline__ float4 half4_to_float4(uint2 p) {
    float2 fa = __half22float2(*(__half2*)&p.x);
    float2 fb = __half22float2(*(__half2*)&p.y);
    return make_float4(fa.x, fa.y, fb.x, fb.y);
}

__global__ void k_agg128(const float* __restrict__ bias, int relu) {
    int warp = (blockIdx.x * blockDim.x + threadIdx.x) >> 5;
    int lane = threadIdx.x & 31;
    if (warp >= N_NODES) return;
    int rs = g_rowptr[warp], re = g_rowptr[warp + 1];
    float4 acc = make_float4(0.f, 0.f, 0.f, 0.f);
    const uint2* Y2 = (const uint2*)g_y16;
    int e = rs;
    for (; e + 4 <= re; e += 4) {
        int s0 = g_col[e], s1 = g_col[e + 1], s2 = g_col[e + 2], s3 = g_col[e + 3];
        uint2 p0 = Y2[(size_t)s0 * 32 + lane];
        uint2 p1 = Y2[(size_t)s1 * 32 + lane];
        uint2 p2 = Y2[(size_t)s2 * 32 + lane];
        uint2 p3 = Y2[(size_t)s3 * 32 + lane];
        acc_half4(acc, p0); acc_half4(acc, p1); acc_half4(acc, p2); acc_half4(acc, p3);
    }
    for (; e < re; e++) {
        uint2 p = Y2[(size_t)g_col[e] * 32 + lane];
        acc_half4(acc, p);
    }
    float inv = 1.f / fmaxf((float)(re - rs), 1.f);
    float4 hr = half4_to_float4(((const uint2*)g_hr16)[(size_t)warp * 32 + lane]);
    float4 b  = ((const float4*)bias)[lane];
    float o0 = acc.x * inv + hr.x + b.x;
    float o1 = acc.y * inv + hr.y + b.y;
    float o2 = acc.z * inv + hr.z + b.z;
    float o3 = acc.w * inv + hr.w + b.w;
    if (relu) {
        o0 = fmaxf(o0, 0.f); o1 = fmaxf(o1, 0.f);
        o2 = fmaxf(o2, 0.f); o3 = fmaxf(o3, 0.f);
    }
    size_t idx = (size_t)warp * 128 + lane * 4;
    __half h0 = __float2half_rn(o0), h1 = __float2half_rn(o1);
    __half h2 = __float2half_rn(o2), h3 = __float2half_rn(o3);
    *(__half2*)(g_ah + idx)     = __halves2half2(h0, h1);
    *(__half2*)(g_ah + idx + 2) = __halves2half2(h2, h3);
    __half l0 = __float2half_rn(o0 - __half2float(h0));
    __half l1 = __float2half_rn(o1 - __half2float(h1));
    __half l2 = __float2half_rn(o2 - __half2float(h2));
    __half l3 = __float2half_rn(o3 - __half2float(h3));
    *(__half2*)(g_al + idx)     = __halves2half2(l0, l1);
    *(__half2*)(g_al + idx + 2) = __halves2half2(l2, l3);
}

__global__ void k_agg64(const float* __restrict__ bias, float* __restrict__ out) {
    int gw = (blockIdx.x * blockDim.x + threadIdx.x) >> 5;
    int lane = threadIdx.x & 31;
    int half = lane >> 4, ln = lane & 15;
    int node = gw * 2 + half;
    if (node >= N_NODES) return;
    int rs = g_rowptr[node], re = g_rowptr[node + 1];
    float4 acc = make_float4(0.f, 0.f, 0.f, 0.f);
    const uint2* Y2 = (const uint2*)g_y16;
    int e = rs;
    for (; e + 4 <= re; e += 4) {
        int s0 = g_col[e], s1 = g_col[e + 1], s2 = g_col[e + 2], s3 = g_col[e + 3];
        uint2 p0 = Y2[(size_t)s0 * 16 + ln];
        uint2 p1 = Y2[(size_t)s1 * 16 + ln];
        uint2 p2 = Y2[(size_t)s2 * 16 + ln];
        uint2 p3 = Y2[(size_t)s3 * 16 + ln];
        acc_half4(acc, p0); acc_half4(acc, p1); acc_half4(acc, p2); acc_half4(acc, p3);
    }
    for (; e < re; e++) {
        uint2 p = Y2[(size_t)g_col[e] * 16 + ln];
        acc_half4(acc, p);
    }
    float inv = 1.f / fmaxf((float)(re - rs), 1.f);
    float4 hr = half4_to_float4(((const uint2*)g_hr16)[(size_t)node * 16 + ln]);
    float4 b  = ((const float4*)bias)[ln];
    float4 o;
    o.x = acc.x * inv + hr.x + b.x;
    o.y = acc.y * inv + hr.y + b.y;
    o.z = acc.z * inv + hr.z + b.z;
    o.w = acc.w * inv + hr.w + b.w;
    ((float4*)out)[(size_t)node * 16 + ln] = o;
}

// ---------------- launch ----------------
extern "C" void kernel_launch(void* const* d_in, const int* in_sizes, int n_in,
                              void* d_out, int out_size) {
    const float* x   = (const float*)d_in[0];
    const void*  ei  = d_in[1];
    const float* w1l = (const float*)d_in[2];
    const float* w1r = (const float*)d_in[3];
    const float* b1  = (const float*)d_in[4];
    const float* w2l = (const float*)d_in[5];
    const float* w2r = (const float*)d_in[6];
    const float* b2  = (const float*)d_in[7];
    const float* w3l = (const float*)d_in[8];
    const float* w3r = (const float*)d_in[9];
    const float* b3  = (const float*)d_in[10];
    float* out = (float*)d_out;

    constexpr int SMEM_BIG   = 2 * (2 * A_TILE_B + 256 * CSTR_B);  // 147456
    constexpr int SMEM_SMALL = 2 * (2 * A_TILE_B + 128 * CSTR_B);  // 110592
    cudaFuncSetAttribute(k_gemm<256, 512>, cudaFuncAttributeMaxDynamicSharedMemorySize, SMEM_BIG);
    cudaFuncSetAttribute(k_gemm<128, 256>, cudaFuncAttributeMaxDynamicSharedMemorySize, SMEM_SMALL);

    // lazily created side stream + fork/join events (host objects; no device allocs)
    static cudaStream_t s2 = nullptr;
    static cudaEvent_t evFork = nullptr, evJoin = nullptr;
    if (s2 == nullptr) {
        cudaStreamCreateWithFlags(&s2, cudaStreamNonBlocking);
        cudaEventCreateWithFlags(&evFork, cudaEventDisableTiming);
        cudaEventCreateWithFlags(&evJoin, cudaEventDisableTiming);
    }

    void* deg_ptr = nullptr;
    cudaGetSymbolAddress(&deg_ptr, g_deg);

    dim3 grid(782, 1);
    const int EPAIR_BLKS = (N_EDGES / 2 + 255) / 256;   // 3125

    // ---- fork immediately; ENTIRE CSR chain lives on s2 ----
    cudaEventRecord(evFork, 0);
    cudaStreamWaitEvent(s2, evFork, 0);
    k_detect<<<1, 32, 0, s2>>>((const int*)ei);
    cudaMemsetAsync(deg_ptr, 0, N_NODES * sizeof(int), s2);
    k_count<<<EPAIR_BLKS, 256, 0, s2>>>(ei);
    k_scanA<<<SCAN_NB, 1024, 0, s2>>>();
    k_scanC<<<(N_NODES + 255) / 256, 256, 0, s2>>>();
    k_fill<<<EPAIR_BLKS, 256, 0, s2>>>(ei);
    cudaEventRecord(evJoin, s2);

    // ---- stream 0: fused conversions + layer-1 GEMM (overlaps CSR chain) ----
    k_conv<<<X_BLKS + 320, 256>>>((const float4*)x, w1l, w1r, w2l, w2r, w3l, w3r);
    k_gemm<256, 512><<<grid, 512, SMEM_BIG>>>(0);

    // ---- join: aggregation needs the CSR ----
    cudaStreamWaitEvent(0, evJoin, 0);
    k_agg128<<<(N_NODES + 7) / 8, 256>>>(b1, 1);
    // layer 2
    k_gemm<256, 512><<<grid, 512, SMEM_BIG>>>(256);
    k_agg128<<<(N_NODES + 7) / 8, 256>>>(b2, 1);
    // layer 3
    k_gemm<128, 256><<<grid, 256, SMEM_SMALL>>>(512);
    k_agg64<<<(N_NODES / 2 + 7) / 8, 256>>>(b3, out);
}

// round 12
// speedup vs baseline: 1.2581x; 1.0291x over previous
#include <cuda_runtime.h>
#include <cuda_bf16.h>
#include <cuda_fp16.h>
#include <cstdint>

#define N_NODES 100000
#define N_PAD   100096
#define N_EDGES 1600000
#define SCAN_CHUNK 4096
#define SCAN_NB ((N_NODES + SCAN_CHUNK - 1) / SCAN_CHUNK)  // 25
#define NSPLIT  50048                  // 391 tiles * 128 rows

#define CSTR_B 144                     // bytes per smem row (72 fp16), 16B-aligned, conflict-free
#define A_TILE_B (128 * CSTR_B)        // 18432 B

// ---------------- scratch (static device globals; no allocs) ----------------
__device__ int g_is64;
__device__ __align__(16) int g_deg[N_NODES + 4];
__device__ __align__(16) int g_rowptr[N_NODES + 4];
__device__ __align__(16) int g_cursor[N_NODES];
__device__ int g_col[N_EDGES];
__device__ int g_bsum[SCAN_NB];
__device__ __half g_y16[(size_t)N_NODES * 128];      // neighbor-transform y, fp16 gather payload
__device__ __half g_hr16[(size_t)N_NODES * 128];     // root-transform, fp16
__device__ __half g_ah[(size_t)N_PAD * 128];         // activation hi (fp16; pad rows stay 0)
__device__ __half g_al[(size_t)N_PAD * 128];         // activation lo (fp16 residual)
__device__ __half g_w16[640 * 128];                  // stacked fp16 weights: L1(256) L2(256) L3(128)

// ---------------- PTX helpers ----------------
#define CP_ASYNC16(dst, src) \
    asm volatile("cp.async.cg.shared.global [%0], [%1], 16;\n" :: "r"(dst), "l"(src))
#define CP_COMMIT() asm volatile("cp.async.commit_group;\n")
#define CP_WAIT(n)  asm volatile("cp.async.wait_group %0;\n" :: "n"(n))
#define LDSM_X4(r0, r1, r2, r3, addr) \
    asm volatile("ldmatrix.sync.aligned.m8n8.x4.shared.b16 {%0,%1,%2,%3}, [%4];" \
                 : "=r"(r0), "=r"(r1), "=r"(r2), "=r"(r3) : "r"(addr))

__device__ __forceinline__ void mma_f16(float acc[4], const uint32_t a[4], uint32_t b0, uint32_t b1) {
    asm volatile(
        "mma.sync.aligned.m16n8k16.row.col.f32.f16.f16.f32 "
        "{%0,%1,%2,%3}, {%4,%5,%6,%7}, {%8,%9}, {%0,%1,%2,%3};\n"
        : "+f"(acc[0]), "+f"(acc[1]), "+f"(acc[2]), "+f"(acc[3])
        : "r"(a[0]), "r"(a[1]), "r"(a[2]), "r"(a[3]), "r"(b0), "r"(b1));
}

// ---------------- edge dtype detection (int64 vs int32) ----------------
__global__ void k_detect(const int* __restrict__ ei32) {
    if (threadIdx.x == 0 && blockIdx.x == 0) {
        int is64 = 1;
        for (int i = 0; i < 128; i++) {
            if (ei32[2 * i + 1] != 0) { is64 = 0; break; }
        }
        g_is64 = is64;
    }
}

// ---------------- CSR build (2 edges per thread) ----------------
__global__ void k_count(const void* __restrict__ ei) {
    int p = blockIdx.x * blockDim.x + threadIdx.x;
    if (p * 2 >= N_EDGES) return;
    int d0, d1;
    if (g_is64) {
        longlong2 v = ((const longlong2*)ei)[N_EDGES / 2 + p];
        d0 = (int)v.x; d1 = (int)v.y;
    } else {
        int2 v = ((const int2*)ei)[N_EDGES / 2 + p];
        d0 = v.x; d1 = v.y;
    }
    atomicAdd(&g_deg[d0], 1);
    atomicAdd(&g_deg[d1], 1);
}

__global__ __launch_bounds__(1024) void k_scanA() {
    __shared__ int wsum[32];
    int b = blockIdx.x, tid = threadIdx.x, lane = tid & 31, wid = tid >> 5;
    int base = b * SCAN_CHUNK + tid * 4;
    int4 v = make_int4(0, 0, 0, 0);
    if (base + 3 < N_NODES) {
        v = *(const int4*)(g_deg + base);
    } else {
        int* p = (int*)&v;
        for (int i = 0; i < 4; i++) if (base + i < N_NODES) p[i] = g_deg[base + i];
    }
    int s0 = v.x, s1 = s0 + v.y, s2 = s1 + v.z, s3 = s2 + v.w;
    int x = s3;
    #pragma unroll
    for (int s = 1; s < 32; s <<= 1) {
        int t = __shfl_up_sync(0xffffffffu, x, s);
        if (lane >= s) x += t;
    }
    if (lane == 31) wsum[wid] = x;
    __syncthreads();
    if (wid == 0) {
        int w = wsum[lane];
        #pragma unroll
        for (int s = 1; s < 32; s <<= 1) {
            int t = __shfl_up_sync(0xffffffffu, w, s);
            if (lane >= s) w += t;
        }
        wsum[lane] = w;
    }
    __syncthreads();
    int off = (wid > 0 ? wsum[wid - 1] : 0) + (x - s3);
    int4 o = make_int4(off, off + s0, off + s1, off + s2);
    if (base + 3 < N_NODES) {
        *(int4*)(g_rowptr + base) = o;
    } else {
        int* p = (int*)&o;
        for (int i = 0; i < 4; i++) if (base + i < N_NODES) g_rowptr[base + i] = p[i];
    }
    if (tid == 0) g_bsum[b] = wsum[31];
}

__global__ void k_scanC() {
    __shared__ int boff[SCAN_NB + 1];
    int tid = threadIdx.x;
    if (tid < 32) {
        int v = (tid < SCAN_NB) ? g_bsum[tid] : 0;
        int x = v;
        #pragma unroll
        for (int s = 1; s < 32; s <<= 1) {
            int t = __shfl_up_sync(0xffffffffu, x, s);
            if (tid >= s) x += t;
        }
        if (tid < SCAN_NB) boff[tid] = x - v;
        if (tid == 31) boff[SCAN_NB] = x;
    }
    __syncthreads();
    int i = blockIdx.x * blockDim.x + tid;
    if (i < N_NODES) {
        int r = g_rowptr[i] + boff[i / SCAN_CHUNK];
        g_rowptr[i] = r;
        g_cursor[i] = r;
    }
    if (i == 0) g_rowptr[N_NODES] = boff[SCAN_NB];
}

__global__ void k_fill(const void* __restrict__ ei) {
    int p = blockIdx.x * blockDim.x + threadIdx.x;
    if (p * 2 >= N_EDGES) return;
    int d0, d1, s0, s1;
    if (g_is64) {
        longlong2 vd = ((const longlong2*)ei)[N_EDGES / 2 + p];
        longlong2 vs = ((const longlong2*)ei)[p];
        d0 = (int)vd.x; d1 = (int)vd.y; s0 = (int)vs.x; s1 = (int)vs.y;
    } else {
        int2 vd = ((const int2*)ei)[N_EDGES / 2 + p];
        int2 vs = ((const int2*)ei)[p];
        d0 = vd.x; d1 = vd.y; s0 = vs.x; s1 = vs.y;
    }
    g_col[atomicAdd(&g_cursor[d0], 1)] = s0;
    g_col[atomicAdd(&g_cursor[d1], 1)] = s1;
}

// ---------------- fused conversions: x -> (ah, al) fp16 split; weights -> w16 ----------------
#define X_BLKS 12500
__global__ void k_conv(const float4* __restrict__ x,
                       const float* __restrict__ w1l, const float* __restrict__ w1r,
                       const float* __restrict__ w2l, const float* __restrict__ w2r,
                       const float* __restrict__ w3l, const float* __restrict__ w3r) {
    int b = blockIdx.x;
    if (b < X_BLKS) {
        int i = b * blockDim.x + threadIdx.x;
        if (i >= N_NODES * 32) return;
        float4 v = x[i];
        size_t o = (size_t)i * 4;
        __half h0 = __float2half_rn(v.x), h1 = __float2half_rn(v.y);
        __half h2 = __float2half_rn(v.z), h3 = __float2half_rn(v.w);
        *(__half2*)(g_ah + o)     = __halves2half2(h0, h1);
        *(__half2*)(g_ah + o + 2) = __halves2half2(h2, h3);
        __half l0 = __float2half_rn(v.x - __half2float(h0));
        __half l1 = __float2half_rn(v.y - __half2float(h1));
        __half l2 = __float2half_rn(v.z - __half2float(h2));
        __half l3 = __float2half_rn(v.w - __half2float(h3));
        *(__half2*)(g_al + o)     = __halves2half2(l0, l1);
        *(__half2*)(g_al + o + 2) = __halves2half2(l2, l3);
    } else {
        int i = (b - X_BLKS) * blockDim.x + threadIdx.x;
        if (i >= 640 * 128) return;
        int row = i >> 7, c = i & 127;
        const float* src; int r;
        if (row < 128)      { src = w1l; r = row; }
        else if (row < 256) { src = w1r; r = row - 128; }
        else if (row < 384) { src = w2l; r = row - 256; }
        else if (row < 512) { src = w2r; r = row - 384; }
        else if (row < 576) { src = w3l; r = row - 512; }
        else                { src = w3r; r = row - 576; }
        g_w16[i] = __float2half_rn(src[r * 128 + c]);
    }
}

// ---------------- GEMM: M=128 x N=NT tile, 2-stage cp.async, ldmatrix, 2-term fp16 split ----------------
// mblk0: tile offset (row m0 = (blockIdx.x + mblk0) * 128) for split-grid pipelining
template<int NT, int NTHR>
__global__ __launch_bounds__(NTHR, 1) void k_gemm(int wbase, int mblk0) {
    constexpr int W_TILE_B = NT * CSTR_B;
    constexpr int STAGE_B  = 2 * A_TILE_B + W_TILE_B;
    constexpr int WCOLS    = NT / 64;
    constexpr int YC       = NT / 2;

    extern __shared__ __align__(16) char smemc[];
    uint32_t smem_u = (uint32_t)__cvta_generic_to_shared(smemc);
    int m0 = (blockIdx.x + mblk0) * 128;
    int tid = threadIdx.x;

    #pragma unroll
    for (int st = 0; st < 2; st++) {
        uint32_t sb = smem_u + st * STAGE_B;
        int kb = st * 64;
        for (int i = tid; i < 2048; i += NTHR) {        // A hi+lo
            int t = i >> 10, c = i & 1023;
            int r = c >> 3, q = c & 7;
            uint32_t doff = (uint32_t)(t * A_TILE_B + r * CSTR_B + q * 16);
            const __half* src = (t == 0 ? g_ah : g_al) + (size_t)(m0 + r) * 128 + kb + q * 8;
            CP_ASYNC16(sb + doff, src);
        }
        for (int i = tid; i < NT * 8; i += NTHR) {      // W single
            int r = i >> 3, q = i & 7;
            uint32_t doff = (uint32_t)(2 * A_TILE_B + r * CSTR_B + q * 16);
            const __half* src = g_w16 + (size_t)(wbase + r) * 128 + kb + q * 8;
            CP_ASYNC16(sb + doff, src);
        }
        CP_COMMIT();
    }

    int warp = tid >> 5, lane = tid & 31;
    int wm = (warp / WCOLS) * 32, wn = (warp % WCOLS) * 64;
    uint32_t aoff = ((lane & 7) + ((lane >> 3) & 1) * 8) * CSTR_B + (lane >> 4) * 16;
    uint32_t woff = (lane & 7) * CSTR_B + ((lane >> 3) & 1) * 16 + ((lane >> 3) >> 1) * (8 * CSTR_B);

    float acc[2][8][4] = {};

    #pragma unroll
    for (int st = 0; st < 2; st++) {
        if (st == 0) { CP_WAIT(1); } else { CP_WAIT(0); }
        __syncthreads();
        uint32_t sb = smem_u + st * STAGE_B;
        #pragma unroll
        for (int kl = 0; kl < 64; kl += 16) {
            uint32_t ah[2][4], al[2][4], w[8][2];
            #pragma unroll
            for (int i = 0; i < 2; i++) {
                uint32_t abase = sb + (wm + i * 16) * CSTR_B + kl * 2 + aoff;
                LDSM_X4(ah[i][0], ah[i][1], ah[i][2], ah[i][3], abase);
                LDSM_X4(al[i][0], al[i][1], al[i][2], al[i][3], abase + A_TILE_B);
            }
            #pragma unroll
            for (int jp = 0; jp < 4; jp++) {
                uint32_t wb = sb + 2 * A_TILE_B + (wn + jp * 16) * CSTR_B + kl * 2 + woff;
                LDSM_X4(w[2*jp][0], w[2*jp][1], w[2*jp+1][0], w[2*jp+1][1], wb);
            }
            #pragma unroll
            for (int j = 0; j < 8; j++) {
                #pragma unroll
                for (int i = 0; i < 2; i++) {
                    mma_f16(acc[i][j], ah[i], w[j][0], w[j][1]);  // hi * w
                    mma_f16(acc[i][j], al[i], w[j][0], w[j][1]);  // lo * w
                }
            }
        }
    }

    int g = lane >> 2, tg = lane & 3;
    #pragma unroll
    for (int i = 0; i < 2; i++) {
        #pragma unroll
        for (int j = 0; j < 8; j++) {
            int rm = m0 + wm + i * 16 + g;
            int cn = wn + j * 8 + tg * 2;
            __half2 v01 = __floats2half2_rn(acc[i][j][0], acc[i][j][1]);
            __half2 v23 = __floats2half2_rn(acc[i][j][2], acc[i][j][3]);
            if (cn < YC) {
                if (rm < N_NODES)     *(__half2*)&g_y16[(size_t)rm * YC + cn]       = v01;
                if (rm + 8 < N_NODES) *(__half2*)&g_y16[(size_t)(rm + 8) * YC + cn] = v23;
            } else {
                int hc = cn - YC;
                if (rm < N_NODES)     *(__half2*)&g_hr16[(size_t)rm * YC + hc]       = v01;
                if (rm + 8 < N_NODES) *(__half2*)&g_hr16[(size_t)(rm + 8) * YC + hc] = v23;
            }
        }
    }
}

// ---------------- aggregation: out = mean(gather y16) + hr16 + b (+relu), emit fp16 hi/lo ----------------
__device__ __forceinline__ void acc_half4(float4& acc, uint2 p) {
    float2 fa = __half22float2(*(__half2*)&p.x);
    float2 fb = __half22float2(*(__half2*)&p.y);
    acc.x += fa.x; acc.y += fa.y; acc.z += fb.x; acc.w += fb.y;
}

__device__ __forceinline__ float4 half4_to_float4(uint2 p) {
    float2 fa = __half22float2(*(__half2*)&p.x);
    float2 fb = __half22float2(*(__half2*)&p.y);
    return make_float4(fa.x, fa.y, fb.x, fb.y);
}

// processes dst nodes [n0, n1)
__global__ void k_agg128(const float* __restrict__ bias, int relu, int n0, int n1) {
    int warp = n0 + ((blockIdx.x * blockDim.x + threadIdx.x) >> 5);
    int lane = threadIdx.x & 31;
    if (warp >= n1) return;
    int rs = g_rowptr[warp], re = g_rowptr[warp + 1];
    float4 acc = make_float4(0.f, 0.f, 0.f, 0.f);
    const uint2* Y2 = (const uint2*)g_y16;
    int e = rs;
    for (; e + 4 <= re; e += 4) {
        int s0 = g_col[e], s1 = g_col[e + 1], s2 = g_col[e + 2], s3 = g_col[e + 3];
        uint2 p0 = Y2[(size_t)s0 * 32 + lane];
        uint2 p1 = Y2[(size_t)s1 * 32 + lane];
        uint2 p2 = Y2[(size_t)s2 * 32 + lane];
        uint2 p3 = Y2[(size_t)s3 * 32 + lane];
        acc_half4(acc, p0); acc_half4(acc, p1); acc_half4(acc, p2); acc_half4(acc, p3);
    }
    for (; e < re; e++) {
        uint2 p = Y2[(size_t)g_col[e] * 32 + lane];
        acc_half4(acc, p);
    }
    float inv = 1.f / fmaxf((float)(re - rs), 1.f);
    float4 hr = half4_to_float4(((const uint2*)g_hr16)[(size_t)warp * 32 + lane]);
    float4 b  = ((const float4*)bias)[lane];
    float o0 = acc.x * inv + hr.x + b.x;
    float o1 = acc.y * inv + hr.y + b.y;
    float o2 = acc.z * inv + hr.z + b.z;
    float o3 = acc.w * inv + hr.w + b.w;
    if (relu) {
        o0 = fmaxf(o0, 0.f); o1 = fmaxf(o1, 0.f);
        o2 = fmaxf(o2, 0.f); o3 = fmaxf(o3, 0.f);
    }
    size_t idx = (size_t)warp * 128 + lane * 4;
    __half h0 = __float2half_rn(o0), h1 = __float2half_rn(o1);
    __half h2 = __float2half_rn(o2), h3 = __float2half_rn(o3);
    *(__half2*)(g_ah + idx)     = __halves2half2(h0, h1);
    *(__half2*)(g_ah + idx + 2) = __halves2half2(h2, h3);
    __half l0 = __float2half_rn(o0 - __half2float(h0));
    __half l1 = __float2half_rn(o1 - __half2float(h1));
    __half l2 = __float2half_rn(o2 - __half2float(h2));
    __half l3 = __float2half_rn(o3 - __half2float(h3));
    *(__half2*)(g_al + idx)     = __halves2half2(l0, l1);
    *(__half2*)(g_al + idx + 2) = __halves2half2(l2, l3);
}

__global__ void k_agg64(const float* __restrict__ bias, float* __restrict__ out) {
    int gw = (blockIdx.x * blockDim.x + threadIdx.x) >> 5;
    int lane = threadIdx.x & 31;
    int half = lane >> 4, ln = lane & 15;
    int node = gw * 2 + half;
    if (node >= N_NODES) return;
    int rs = g_rowptr[node], re = g_rowptr[node + 1];
    float4 acc = make_float4(0.f, 0.f, 0.f, 0.f);
    const uint2* Y2 = (const uint2*)g_y16;
    int e = rs;
    for (; e + 4 <= re; e += 4) {
        int s0 = g_col[e], s1 = g_col[e + 1], s2 = g_col[e + 2], s3 = g_col[e + 3];
        uint2 p0 = Y2[(size_t)s0 * 16 + ln];
        uint2 p1 = Y2[(size_t)s1 * 16 + ln];
        uint2 p2 = Y2[(size_t)s2 * 16 + ln];
        uint2 p3 = Y2[(size_t)s3 * 16 + ln];
        acc_half4(acc, p0); acc_half4(acc, p1); acc_half4(acc, p2); acc_half4(acc, p3);
    }
    for (; e < re; e++) {
        uint2 p = Y2[(size_t)g_col[e] * 16 + ln];
        acc_half4(acc, p);
    }
    float inv = 1.f / fmaxf((float)(re - rs), 1.f);
    float4 hr = half4_to_float4(((const uint2*)g_hr16)[(size_t)node * 16 + ln]);
    float4 b  = ((const float4*)bias)[ln];
    float4 o;
    o.x = acc.x * inv + hr.x + b.x;
    o.y = acc.y * inv + hr.y + b.y;
    o.z = acc.z * inv + hr.z + b.z;
    o.w = acc.w * inv + hr.w + b.w;
    ((float4*)out)[(size_t)node * 16 + ln] = o;
}

// ---------------- launch ----------------
extern "C" void kernel_launch(void* const* d_in, const int* in_sizes, int n_in,
                              void* d_out, int out_size) {
    const float* x   = (const float*)d_in[0];
    const void*  ei  = d_in[1];
    const float* w1l = (const float*)d_in[2];
    const float* w1r = (const float*)d_in[3];
    const float* b1  = (const float*)d_in[4];
    const float* w2l = (const float*)d_in[5];
    const float* w2r = (const float*)d_in[6];
    const float* b2  = (const float*)d_in[7];
    const float* w3l = (const float*)d_in[8];
    const float* w3r = (const float*)d_in[9];
    const float* b3  = (const float*)d_in[10];
    float* out = (float*)d_out;

    constexpr int SMEM_BIG   = 2 * (2 * A_TILE_B + 256 * CSTR_B);  // 147456
    constexpr int SMEM_SMALL = 2 * (2 * A_TILE_B + 128 * CSTR_B);  // 110592
    cudaFuncSetAttribute(k_gemm<256, 512>, cudaFuncAttributeMaxDynamicSharedMemorySize, SMEM_BIG);
    cudaFuncSetAttribute(k_gemm<128, 256>, cudaFuncAttributeMaxDynamicSharedMemorySize, SMEM_SMALL);

    static cudaStream_t s2 = nullptr;
    static cudaEvent_t evFork = nullptr, evJoin = nullptr;
    static cudaEvent_t evG1 = nullptr, evB1 = nullptr, evG2 = nullptr, evB2 = nullptr;
    if (s2 == nullptr) {
        cudaStreamCreateWithFlags(&s2, cudaStreamNonBlocking);
        cudaEventCreateWithFlags(&evFork, cudaEventDisableTiming);
        cudaEventCreateWithFlags(&evJoin, cudaEventDisableTiming);
        cudaEventCreateWithFlags(&evG1, cudaEventDisableTiming);
        cudaEventCreateWithFlags(&evB1, cudaEventDisableTiming);
        cudaEventCreateWithFlags(&evG2, cudaEventDisableTiming);
        cudaEventCreateWithFlags(&evB2, cudaEventDisableTiming);
    }

    void* deg_ptr = nullptr;
    cudaGetSymbolAddress(&deg_ptr, g_deg);

    const int EPAIR_BLKS = (N_EDGES / 2 + 255) / 256;   // 3125
    const int T0 = 391, T1 = 391;                       // tile split (rows: 50048 / 50048)
    const int AP0_BLKS = NSPLIT / 8;                    // 6256 (8 warps/block)
    const int AP1_BLKS = (N_NODES - NSPLIT + 7) / 8;    // 6244

    // ---- fork: CSR chain on s2 ----
    cudaEventRecord(evFork, 0);
    cudaStreamWaitEvent(s2, evFork, 0);
    k_detect<<<1, 32, 0, s2>>>((const int*)ei);
    cudaMemsetAsync(deg_ptr, 0, N_NODES * sizeof(int), s2);
    k_count<<<EPAIR_BLKS, 256, 0, s2>>>(ei);
    k_scanA<<<SCAN_NB, 1024, 0, s2>>>();
    k_scanC<<<(N_NODES + 255) / 256, 256, 0, s2>>>();
    k_fill<<<EPAIR_BLKS, 256, 0, s2>>>(ei);
    cudaEventRecord(evJoin, s2);

    // ---- stream 0: conversions + full layer-1 GEMM (overlaps CSR chain) ----
    k_conv<<<X_BLKS + 320, 256>>>((const float4*)x, w1l, w1r, w2l, w2r, w3l, w3r);
    k_gemm<256, 512><<<782, 512, SMEM_BIG>>>(0, 0);
    cudaEventRecord(evG1, 0);

    // ---- boundary 1: split agg L1 + GEMM L2, two pipelined chains ----
    cudaStreamWaitEvent(0, evJoin, 0);                  // s0 needs CSR
    cudaStreamWaitEvent(s2, evG1, 0);                   // s2 needs full y16/hr16 (CSR already on s2)
    k_agg128<<<AP0_BLKS, 256>>>(b1, 1, 0, NSPLIT);                  // s0: agg p0
    k_gemm<256, 512><<<T0, 512, SMEM_BIG>>>(256, 0);                // s0: gemm L2 p0
    k_agg128<<<AP1_BLKS, 256, 0, s2>>>(b1, 1, NSPLIT, N_NODES);     // s2: agg p1
    k_gemm<256, 512><<<T1, 512, SMEM_BIG, s2>>>(256, T0);           // s2: gemm L2 p1
    cudaEventRecord(evB1, s2);
    cudaEventRecord(evG2, 0);

    // ---- boundary 2: split agg L2 + GEMM L3 ----
    cudaStreamWaitEvent(0, evB1, 0);                    // s0 needs full y16 L2
    cudaStreamWaitEvent(s2, evG2, 0);                   // s2 needs s0's gemm L2 p0
    k_agg128<<<AP0_BLKS, 256>>>(b2, 1, 0, NSPLIT);
    k_gemm<128, 256><<<T0, 256, SMEM_SMALL>>>(512, 0);
    k_agg128<<<AP1_BLKS, 256, 0, s2>>>(b2, 1, NSPLIT, N_NODES);
    k_gemm<128, 256><<<T1, 256, SMEM_SMALL, s2>>>(512, T0);
    cudaEventRecord(evB2, s2);

    // ---- final aggregation ----
    cudaStreamWaitEvent(0, evB2, 0);
    k_agg64<<<(N_NODES / 2 + 7) / 8, 256>>>(b3, out);
}

// round 14
// speedup vs baseline: 1.2670x; 1.0071x over previous
#include <cuda_runtime.h>
#include <cuda_bf16.h>
#include <cuda_fp16.h>
#include <cstdint>

#define N_NODES 100000
#define N_PAD   100096
#define N_EDGES 1600000
#define SCAN_CHUNK 4096
#define SCAN_NB ((N_NODES + SCAN_CHUNK - 1) / SCAN_CHUNK)  // 25
#define NSPLIT  50048                  // 391 tiles * 128 rows
#define XCH_TOT (N_NODES * 32)         // float4 chunks in x
#define XCH_P0  (NSPLIT * 32)          // 1601536

#define CSTR_B 144                     // bytes per smem row (72 fp16), 16B-aligned, conflict-free
#define A_TILE_B (128 * CSTR_B)        // 18432 B

// ---------------- scratch (static device globals; no allocs) ----------------
__device__ int g_is64;
__device__ __align__(16) int g_deg[N_NODES + 4];
__device__ __align__(16) int g_rowptr[N_NODES + 4];
__device__ __align__(16) int g_cursor[N_NODES];
__device__ int g_col[N_EDGES];
__device__ int g_bsum[SCAN_NB];
__device__ __half g_y16[(size_t)N_NODES * 128];      // neighbor-transform y, fp16 gather payload
__device__ __half g_hr16[(size_t)N_NODES * 128];     // root-transform, fp16
__device__ __half g_ah[(size_t)N_PAD * 128];         // activation hi (fp16; pad rows stay 0)
__device__ __half g_al[(size_t)N_PAD * 128];         // activation lo (fp16 residual)
__device__ __half g_w16[640 * 128];                  // stacked fp16 weights: L1(256) L2(256) L3(128)

// ---------------- PTX helpers ----------------
#define CP_ASYNC16(dst, src) \
    asm volatile("cp.async.cg.shared.global [%0], [%1], 16;\n" :: "r"(dst), "l"(src))
#define CP_COMMIT() asm volatile("cp.async.commit_group;\n")
#define CP_WAIT(n)  asm volatile("cp.async.wait_group %0;\n" :: "n"(n))
#define LDSM_X4(r0, r1, r2, r3, addr) \
    asm volatile("ldmatrix.sync.aligned.m8n8.x4.shared.b16 {%0,%1,%2,%3}, [%4];" \
                 : "=r"(r0), "=r"(r1), "=r"(r2), "=r"(r3) : "r"(addr))

__device__ __forceinline__ void mma_f16(float acc[4], const uint32_t a[4], uint32_t b0, uint32_t b1) {
    asm volatile(
        "mma.sync.aligned.m16n8k16.row.col.f32.f16.f16.f32 "
        "{%0,%1,%2,%3}, {%4,%5,%6,%7}, {%8,%9}, {%0,%1,%2,%3};\n"
        : "+f"(acc[0]), "+f"(acc[1]), "+f"(acc[2]), "+f"(acc[3])
        : "r"(a[0]), "r"(a[1]), "r"(a[2]), "r"(a[3]), "r"(b0), "r"(b1));
}

// ---------------- edge dtype detection (int64 vs int32) ----------------
__global__ void k_detect(const int* __restrict__ ei32) {
    if (threadIdx.x == 0 && blockIdx.x == 0) {
        int is64 = 1;
        for (int i = 0; i < 128; i++) {
            if (ei32[2 * i + 1] != 0) { is64 = 0; break; }
        }
        g_is64 = is64;
    }
}

// ---------------- CSR build (2 edges per thread) ----------------
__global__ void k_count(const void* __restrict__ ei) {
    int p = blockIdx.x * blockDim.x + threadIdx.x;
    if (p * 2 >= N_EDGES) return;
    int d0, d1;
    if (g_is64) {
        longlong2 v = ((const longlong2*)ei)[N_EDGES / 2 + p];
        d0 = (int)v.x; d1 = (int)v.y;
    } else {
        int2 v = ((const int2*)ei)[N_EDGES / 2 + p];
        d0 = v.x; d1 = v.y;
    }
    atomicAdd(&g_deg[d0], 1);
    atomicAdd(&g_deg[d1], 1);
}

__global__ __launch_bounds__(1024) void k_scanA() {
    __shared__ int wsum[32];
    int b = blockIdx.x, tid = threadIdx.x, lane = tid & 31, wid = tid >> 5;
    int base = b * SCAN_CHUNK + tid * 4;
    int4 v = make_int4(0, 0, 0, 0);
    if (base + 3 < N_NODES) {
        v = *(const int4*)(g_deg + base);
    } else {
        int* p = (int*)&v;
        for (int i = 0; i < 4; i++) if (base + i < N_NODES) p[i] = g_deg[base + i];
    }
    int s0 = v.x, s1 = s0 + v.y, s2 = s1 + v.z, s3 = s2 + v.w;
    int x = s3;
    #pragma unroll
    for (int s = 1; s < 32; s <<= 1) {
        int t = __shfl_up_sync(0xffffffffu, x, s);
        if (lane >= s) x += t;
    }
    if (lane == 31) wsum[wid] = x;
    __syncthreads();
    if (wid == 0) {
        int w = wsum[lane];
        #pragma unroll
        for (int s = 1; s < 32; s <<= 1) {
            int t = __shfl_up_sync(0xffffffffu, w, s);
            if (lane >= s) w += t;
        }
        wsum[lane] = w;
    }
    __syncthreads();
    int off = (wid > 0 ? wsum[wid - 1] : 0) + (x - s3);
    int4 o = make_int4(off, off + s0, off + s1, off + s2);
    if (base + 3 < N_NODES) {
        *(int4*)(g_rowptr + base) = o;
    } else {
        int* p = (int*)&o;
        for (int i = 0; i < 4; i++) if (base + i < N_NODES) g_rowptr[base + i] = p[i];
    }
    if (tid == 0) g_bsum[b] = wsum[31];
}

__global__ void k_scanC() {
    __shared__ int boff[SCAN_NB + 1];
    int tid = threadIdx.x;
    if (tid < 32) {
        int v = (tid < SCAN_NB) ? g_bsum[tid] : 0;
        int x = v;
        #pragma unroll
        for (int s = 1; s < 32; s <<= 1) {
            int t = __shfl_up_sync(0xffffffffu, x, s);
            if (tid >= s) x += t;
        }
        if (tid < SCAN_NB) boff[tid] = x - v;
        if (tid == 31) boff[SCAN_NB] = x;
    }
    __syncthreads();
    int i = blockIdx.x * blockDim.x + tid;
    if (i < N_NODES) {
        int r = g_rowptr[i] + boff[i / SCAN_CHUNK];
        g_rowptr[i] = r;
        g_cursor[i] = r;
    }
    if (i == 0) g_rowptr[N_NODES] = boff[SCAN_NB];
}

__global__ void k_fill(const void* __restrict__ ei) {
    int p = blockIdx.x * blockDim.x + threadIdx.x;
    if (p * 2 >= N_EDGES) return;
    int d0, d1, s0, s1;
    if (g_is64) {
        longlong2 vd = ((const longlong2*)ei)[N_EDGES / 2 + p];
        longlong2 vs = ((const longlong2*)ei)[p];
        d0 = (int)vd.x; d1 = (int)vd.y; s0 = (int)vs.x; s1 = (int)vs.y;
    } else {
        int2 vd = ((const int2*)ei)[N_EDGES / 2 + p];
        int2 vs = ((const int2*)ei)[p];
        d0 = vd.x; d1 = vd.y; s0 = vs.x; s1 = vs.y;
    }
    g_col[atomicAdd(&g_cursor[d0], 1)] = s0;
    g_col[atomicAdd(&g_cursor[d1], 1)] = s1;
}

// ---------------- conversions ----------------
__global__ void k_convw(const float* __restrict__ w1l, const float* __restrict__ w1r,
                        const float* __restrict__ w2l, const float* __restrict__ w2r,
                        const float* __restrict__ w3l, const float* __restrict__ w3r) {
    int i = blockIdx.x * blockDim.x + threadIdx.x;
    if (i >= 640 * 128) return;
    int row = i >> 7, c = i & 127;
    const float* src; int r;
    if (row < 128)      { src = w1l; r = row; }
    else if (row < 256) { src = w1r; r = row - 128; }
    else if (row < 384) { src = w2l; r = row - 256; }
    else if (row < 512) { src = w2r; r = row - 384; }
    else if (row < 576) { src = w3l; r = row - 512; }
    else                { src = w3r; r = row - 576; }
    g_w16[i] = __float2half_rn(src[r * 128 + c]);
}

// converts x chunks [c0, c1) (float4 granularity)
__global__ void k_convx(const float4* __restrict__ x, int c0, int c1) {
    int i = c0 + blockIdx.x * blockDim.x + threadIdx.x;
    if (i >= c1) return;
    float4 v = x[i];
    size_t o = (size_t)i * 4;
    __half h0 = __float2half_rn(v.x), h1 = __float2half_rn(v.y);
    __half h2 = __float2half_rn(v.z), h3 = __float2half_rn(v.w);
    *(__half2*)(g_ah + o)     = __halves2half2(h0, h1);
    *(__half2*)(g_ah + o + 2) = __halves2half2(h2, h3);
    __half l0 = __float2half_rn(v.x - __half2float(h0));
    __half l1 = __float2half_rn(v.y - __half2float(h1));
    __half l2 = __float2half_rn(v.z - __half2float(h2));
    __half l3 = __float2half_rn(v.w - __half2float(h3));
    *(__half2*)(g_al + o)     = __halves2half2(l0, l1);
    *(__half2*)(g_al + o + 2) = __halves2half2(l2, l3);
}

// ---------------- GEMM: M=128 x N=NT tile, 2-stage cp.async, ldmatrix, 2-term fp16 split ----------------
template<int NT, int NTHR>
__global__ __launch_bounds__(NTHR, 1) void k_gemm(int wbase, int mblk0) {
    constexpr int W_TILE_B = NT * CSTR_B;
    constexpr int STAGE_B  = 2 * A_TILE_B + W_TILE_B;
    constexpr int WCOLS    = NT / 64;
    constexpr int YC       = NT / 2;

    extern __shared__ __align__(16) char smemc[];
    uint32_t smem_u = (uint32_t)__cvta_generic_to_shared(smemc);
    int m0 = (blockIdx.x + mblk0) * 128;
    int tid = threadIdx.x;

    #pragma unroll
    for (int st = 0; st < 2; st++) {
        uint32_t sb = smem_u + st * STAGE_B;
        int kb = st * 64;
        for (int i = tid; i < 2048; i += NTHR) {        // A hi+lo
            int t = i >> 10, c = i & 1023;
            int r = c >> 3, q = c & 7;
            uint32_t doff = (uint32_t)(t * A_TILE_B + r * CSTR_B + q * 16);
            const __half* src = (t == 0 ? g_ah : g_al) + (size_t)(m0 + r) * 128 + kb + q * 8;
            CP_ASYNC16(sb + doff, src);
        }
        for (int i = tid; i < NT * 8; i += NTHR) {      // W single
            int r = i >> 3, q = i & 7;
            uint32_t doff = (uint32_t)(2 * A_TILE_B + r * CSTR_B + q * 16);
            const __half* src = g_w16 + (size_t)(wbase + r) * 128 + kb + q * 8;
            CP_ASYNC16(sb + doff, src);
        }
        CP_COMMIT();
    }

    int warp = tid >> 5, lane = tid & 31;
    int wm = (warp / WCOLS) * 32, wn = (warp % WCOLS) * 64;
    uint32_t aoff = ((lane & 7) + ((lane >> 3) & 1) * 8) * CSTR_B + (lane >> 4) * 16;
    uint32_t woff = (lane & 7) * CSTR_B + ((lane >> 3) & 1) * 16 + ((lane >> 3) >> 1) * (8 * CSTR_B);

    float acc[2][8][4] = {};

    #pragma unroll
    for (int st = 0; st < 2; st++) {
        if (st == 0) { CP_WAIT(1); } else { CP_WAIT(0); }
        __syncthreads();
        uint32_t sb = smem_u + st * STAGE_B;
        #pragma unroll
        for (int kl = 0; kl < 64; kl += 16) {
            uint32_t ah[2][4], al[2][4], w[8][2];
            #pragma unroll
            for (int i = 0; i < 2; i++) {
                uint32_t abase = sb + (wm + i * 16) * CSTR_B + kl * 2 + aoff;
                LDSM_X4(ah[i][0], ah[i][1], ah[i][2], ah[i][3], abase);
                LDSM_X4(al[i][0], al[i][1], al[i][2], al[i][3], abase + A_TILE_B);
            }
            #pragma unroll
            for (int jp = 0; jp < 4; jp++) {
                uint32_t wb = sb + 2 * A_TILE_B + (wn + jp * 16) * CSTR_B + kl * 2 + woff;
                LDSM_X4(w[2*jp][0], w[2*jp][1], w[2*jp+1][0], w[2*jp+1][1], wb);
            }
            #pragma unroll
            for (int j = 0; j < 8; j++) {
                #pragma unroll
                for (int i = 0; i < 2; i++) {
                    mma_f16(acc[i][j], ah[i], w[j][0], w[j][1]);  // hi * w
                    mma_f16(acc[i][j], al[i], w[j][0], w[j][1]);  // lo * w
                }
            }
        }
    }

    int g = lane >> 2, tg = lane & 3;
    #pragma unroll
    for (int i = 0; i < 2; i++) {
        #pragma unroll
        for (int j = 0; j < 8; j++) {
            int rm = m0 + wm + i * 16 + g;
            int cn = wn + j * 8 + tg * 2;
            __half2 v01 = __floats2half2_rn(acc[i][j][0], acc[i][j][1]);
            __half2 v23 = __floats2half2_rn(acc[i][j][2], acc[i][j][3]);
            if (cn < YC) {
                if (rm < N_NODES)     *(__half2*)&g_y16[(size_t)rm * YC + cn]       = v01;
                if (rm + 8 < N_NODES) *(__half2*)&g_y16[(size_t)(rm + 8) * YC + cn] = v23;
            } else {
                int hc = cn - YC;
                if (rm < N_NODES)     *(__half2*)&g_hr16[(size_t)rm * YC + hc]       = v01;
                if (rm + 8 < N_NODES) *(__half2*)&g_hr16[(size_t)(rm + 8) * YC + hc] = v23;
            }
        }
    }
}

// ---------------- aggregation: out = mean(gather y16) + hr16 + b (+relu), emit fp16 hi/lo ----------------
__device__ __forceinline__ void acc_half4(float4& acc, uint2 p) {
    float2 fa = __half22float2(*(__half2*)&p.x);
    float2 fb = __half22float2(*(__half2*)&p.y);
    acc.x += fa.x; acc.y += fa.y; acc.z += fb.x; acc.w += fb.y;
}

__device__ __forceinline__ float4 half4_to_float4(uint2 p) {
    float2 fa = __half22float2(*(__half2*)&p.x);
    float2 fb = __half22float2(*(__half2*)&p.y);
    return make_float4(fa.x, fa.y, fb.x, fb.y);
}

// processes dst nodes [n0, n1)
__global__ void k_agg128(const float* __restrict__ bias, int relu, int n0, int n1) {
    int warp = n0 + ((blockIdx.x * blockDim.x + threadIdx.x) >> 5);
    int lane = threadIdx.x & 31;
    if (warp >= n1) return;
    int rs = g_rowptr[warp], re = g_rowptr[warp + 1];
    float4 acc = make_float4(0.f, 0.f, 0.f, 0.f);
    const uint2* Y2 = (const uint2*)g_y16;
    int e = rs;
    for (; e + 4 <= re; e += 4) {
        int s0 = g_col[e], s1 = g_col[e + 1], s2 = g_col[e + 2], s3 = g_col[e + 3];
        uint2 p0 = Y2[(size_t)s0 * 32 + lane];
        uint2 p1 = Y2[(size_t)s1 * 32 + lane];
        uint2 p2 = Y2[(size_t)s2 * 32 + lane];
        uint2 p3 = Y2[(size_t)s3 * 32 + lane];
        acc_half4(acc, p0); acc_half4(acc, p1); acc_half4(acc, p2); acc_half4(acc, p3);
    }
    for (; e < re; e++) {
        uint2 p = Y2[(size_t)g_col[e] * 32 + lane];
        acc_half4(acc, p);
    }
    float inv = 1.f / fmaxf((float)(re - rs), 1.f);
    float4 hr = half4_to_float4(((const uint2*)g_hr16)[(size_t)warp * 32 + lane]);
    float4 b  = ((const float4*)bias)[lane];
    float o0 = acc.x * inv + hr.x + b.x;
    float o1 = acc.y * inv + hr.y + b.y;
    float o2 = acc.z * inv + hr.z + b.z;
    float o3 = acc.w * inv + hr.w + b.w;
    if (relu) {
        o0 = fmaxf(o0, 0.f); o1 = fmaxf(o1, 0.f);
        o2 = fmaxf(o2, 0.f); o3 = fmaxf(o3, 0.f);
    }
    size_t idx = (size_t)warp * 128 + lane * 4;
    __half h0 = __float2half_rn(o0), h1 = __float2half_rn(o1);
    __half h2 = __float2half_rn(o2), h3 = __float2half_rn(o3);
    *(__half2*)(g_ah + idx)     = __halves2half2(h0, h1);
    *(__half2*)(g_ah + idx + 2) = __halves2half2(h2, h3);
    __half l0 = __float2half_rn(o0 - __half2float(h0));
    __half l1 = __float2half_rn(o1 - __half2float(h1));
    __half l2 = __float2half_rn(o2 - __half2float(h2));
    __half l3 = __float2half_rn(o3 - __half2float(h3));
    *(__half2*)(g_al + idx)     = __halves2half2(l0, l1);
    *(__half2*)(g_al + idx + 2) = __halves2half2(l2, l3);
}

__global__ void k_agg64(const float* __restrict__ bias, float* __restrict__ out) {
    int gw = (blockIdx.x * blockDim.x + threadIdx.x) >> 5;
    int lane = threadIdx.x & 31;
    int half = lane >> 4, ln = lane & 15;
    int node = gw * 2 + half;
    if (node >= N_NODES) return;
    int rs = g_rowptr[node], re = g_rowptr[node + 1];
    float4 acc = make_float4(0.f, 0.f, 0.f, 0.f);
    const uint2* Y2 = (const uint2*)g_y16;
    int e = rs;
    for (; e + 4 <= re; e += 4) {
        int s0 = g_col[e], s1 = g_col[e + 1], s2 = g_col[e + 2], s3 = g_col[e + 3];
        uint2 p0 = Y2[(size_t)s0 * 16 + ln];
        uint2 p1 = Y2[(size_t)s1 * 16 + ln];
        uint2 p2 = Y2[(size_t)s2 * 16 + ln];
        uint2 p3 = Y2[(size_t)s3 * 16 + ln];
        acc_half4(acc, p0); acc_half4(acc, p1); acc_half4(acc, p2); acc_half4(acc, p3);
    }
    for (; e < re; e++) {
        uint2 p = Y2[(size_t)g_col[e] * 16 + ln];
        acc_half4(acc, p);
    }
    float inv = 1.f / fmaxf((float)(re - rs), 1.f);
    float4 hr = half4_to_float4(((const uint2*)g_hr16)[(size_t)node * 16 + ln]);
    float4 b  = ((const float4*)bias)[ln];
    float4 o;
    o.x = acc.x * inv + hr.x + b.x;
    o.y = acc.y * inv + hr.y + b.y;
    o.z = acc.z * inv + hr.z + b.z;
    o.w = acc.w * inv + hr.w + b.w;
    ((float4*)out)[(size_t)node * 16 + ln] = o;
}

// ---------------- launch ----------------
extern "C" void kernel_launch(void* const* d_in, const int* in_sizes, int n_in,
                              void* d_out, int out_size) {
    const float* x   = (const float*)d_in[0];
    const void*  ei  = d_in[1];
    const float* w1l = (const float*)d_in[2];
    const float* w1r = (const float*)d_in[3];
    const float* b1  = (const float*)d_in[4];
    const float* w2l = (const float*)d_in[5];
    const float* w2r = (const float*)d_in[6];
    const float* b2  = (const float*)d_in[7];
    const float* w3l = (const float*)d_in[8];
    const float* w3r = (const float*)d_in[9];
    const float* b3  = (const float*)d_in[10];
    float* out = (float*)d_out;

    constexpr int SMEM_BIG   = 2 * (2 * A_TILE_B + 256 * CSTR_B);  // 147456
    constexpr int SMEM_SMALL = 2 * (2 * A_TILE_B + 128 * CSTR_B);  // 110592
    cudaFuncSetAttribute(k_gemm<256, 512>, cudaFuncAttributeMaxDynamicSharedMemorySize, SMEM_BIG);
    cudaFuncSetAttribute(k_gemm<128, 256>, cudaFuncAttributeMaxDynamicSharedMemorySize, SMEM_SMALL);

    static cudaStream_t s2 = nullptr, s3 = nullptr;
    static cudaEvent_t evFork = nullptr, evJoin = nullptr;
    static cudaEvent_t evC0 = nullptr, evG1p0 = nullptr, evG1p1 = nullptr;
    static cudaEvent_t evB1 = nullptr, evG2 = nullptr, evB2 = nullptr;
    if (s2 == nullptr) {
        cudaStreamCreateWithFlags(&s2, cudaStreamNonBlocking);
        cudaStreamCreateWithFlags(&s3, cudaStreamNonBlocking);
        cudaEventCreateWithFlags(&evFork, cudaEventDisableTiming);
        cudaEventCreateWithFlags(&evJoin, cudaEventDisableTiming);
        cudaEventCreateWithFlags(&evC0, cudaEventDisableTiming);
        cudaEventCreateWithFlags(&evG1p0, cudaEventDisableTiming);
        cudaEventCreateWithFlags(&evG1p1, cudaEventDisableTiming);
        cudaEventCreateWithFlags(&evB1, cudaEventDisableTiming);
        cudaEventCreateWithFlags(&evG2, cudaEventDisableTiming);
        cudaEventCreateWithFlags(&evB2, cudaEventDisableTiming);
    }

    void* deg_ptr = nullptr;
    cudaGetSymbolAddress(&deg_ptr, g_deg);

    const int EPAIR_BLKS = (N_EDGES / 2 + 255) / 256;   // 3125
    const int T0 = 391, T1 = 391;
    const int AP0_BLKS = NSPLIT / 8;                    // 6256
    const int AP1_BLKS = (N_NODES - NSPLIT + 7) / 8;    // 6244
    const int XP0_BLKS = XCH_P0 / 256;                  // 6256
    const int XP1_BLKS = (XCH_TOT - XCH_P0 + 255) / 256;

    // ---- fork: CSR chain on s2 ----
    cudaEventRecord(evFork, 0);
    cudaStreamWaitEvent(s2, evFork, 0);
    cudaStreamWaitEvent(s3, evFork, 0);
    k_detect<<<1, 32, 0, s2>>>((const int*)ei);
    cudaMemsetAsync(deg_ptr, 0, N_NODES * sizeof(int), s2);
    k_count<<<EPAIR_BLKS, 256, 0, s2>>>(ei);
    k_scanA<<<SCAN_NB, 1024, 0, s2>>>();
    k_scanC<<<(N_NODES + 255) / 256, 256, 0, s2>>>();
    k_fill<<<EPAIR_BLKS, 256, 0, s2>>>(ei);
    cudaEventRecord(evJoin, s2);

    // ---- s0: weights + x half 0 -> GEMM L1 p0 ----
    k_convw<<<320, 256>>>(w1l, w1r, w2l, w2r, w3l, w3r);
    k_convx<<<XP0_BLKS, 256>>>((const float4*)x, 0, XCH_P0);
    cudaEventRecord(evC0, 0);
    k_gemm<256, 512><<<T0, 512, SMEM_BIG>>>(0, 0);
    cudaEventRecord(evG1p0, 0);

    // ---- s3: x half 1 (staggered) -> GEMM L1 p1 ----
    cudaStreamWaitEvent(s3, evC0, 0);
    k_convx<<<XP1_BLKS, 256, 0, s3>>>((const float4*)x, XCH_P0, XCH_TOT);
    k_gemm<256, 512><<<T1, 512, SMEM_BIG, s3>>>(0, T0);
    cudaEventRecord(evG1p1, s3);

    // ---- boundary 1: split agg L1 + GEMM L2 (agg needs BOTH gemm L1 halves + CSR) ----
    cudaStreamWaitEvent(0, evJoin, 0);
    cudaStreamWaitEvent(0, evG1p1, 0);
    cudaStreamWaitEvent(s2, evG1p0, 0);
    cudaStreamWaitEvent(s2, evG1p1, 0);
    k_agg128<<<AP0_BLKS, 256>>>(b1, 1, 0, NSPLIT);
    k_gemm<256, 512><<<T0, 512, SMEM_BIG>>>(256, 0);
    k_agg128<<<AP1_BLKS, 256, 0, s2>>>(b1, 1, NSPLIT, N_NODES);
    k_gemm<256, 512><<<T1, 512, SMEM_BIG, s2>>>(256, T0);
    cudaEventRecord(evB1, s2);
    cudaEventRecord(evG2, 0);

    // ---- boundary 2: split agg L2 + GEMM L3 ----
    cudaStreamWaitEvent(0, evB1, 0);
    cudaStreamWaitEvent(s2, evG2, 0);
    k_agg128<<<AP0_BLKS, 256>>>(b2, 1, 0, NSPLIT);
    k_gemm<128, 256><<<T0, 256, SMEM_SMALL>>>(512, 0);
    k_agg128<<<AP1_BLKS, 256, 0, s2>>>(b2, 1, NSPLIT, N_NODES);
    k_gemm<128, 256><<<T1, 256, SMEM_SMALL, s2>>>(512, T0);
    cudaEventRecord(evB2, s2);

    // ---- final aggregation ----
    cudaStreamWaitEvent(0, evB2, 0);
    k_agg64<<<(N_NODES / 2 + 7) / 8, 256>>>(b3, out);
}

// round 15
// speedup vs baseline: 1.2707x; 1.0030x over previous
#include <cuda_runtime.h>
#include <cuda_bf16.h>
#include <cuda_fp16.h>
#include <cstdint>

#define N_NODES 100000
#define N_PAD   100096
#define N_EDGES 1600000
#define SCAN_CHUNK 4096
#define SCAN_NB ((N_NODES + SCAN_CHUNK - 1) / SCAN_CHUNK)  // 25
#define NSPLIT  50048                  // 391 tiles * 128 rows
#define XCH_TOT (N_NODES * 32)         // float4 chunks in x
#define XCH_P0  (NSPLIT * 32)

#define CSTR_B 144                     // bytes per smem row (72 fp16), 16B-aligned, conflict-free
#define A_TILE_B (128 * CSTR_B)        // 18432 B

// ---------------- scratch (static device globals; no allocs) ----------------
__device__ int g_is64;
__device__ __align__(16) int g_deg[N_NODES + 4];
__device__ __align__(16) int g_rowptr[N_NODES + 4];
__device__ __align__(16) int g_cursor[N_NODES];
__device__ int g_col[N_EDGES];
__device__ int g_bsum[SCAN_NB];
__device__ __half g_y16[(size_t)N_NODES * 128];      // neighbor-transform y, fp16 gather payload
__device__ __half g_hr16[(size_t)N_NODES * 128];     // root-transform, fp16
__device__ __half g_ah[(size_t)N_PAD * 128];         // activation hi (fp16; pad rows stay 0)
__device__ __half g_al[(size_t)N_PAD * 128];         // activation lo (fp16 residual)
__device__ __half g_w16[640 * 128];                  // stacked fp16 weights: L1(256) L2(256) L3(128)

// ---------------- PTX helpers ----------------
#define CP_ASYNC16(dst, src) \
    asm volatile("cp.async.cg.shared.global [%0], [%1], 16;\n" :: "r"(dst), "l"(src))
#define CP_COMMIT() asm volatile("cp.async.commit_group;\n")
#define CP_WAIT(n)  asm volatile("cp.async.wait_group %0;\n" :: "n"(n))
#define LDSM_X4(r0, r1, r2, r3, addr) \
    asm volatile("ldmatrix.sync.aligned.m8n8.x4.shared.b16 {%0,%1,%2,%3}, [%4];" \
                 : "=r"(r0), "=r"(r1), "=r"(r2), "=r"(r3) : "r"(addr))

__device__ __forceinline__ void mma_f16(float acc[4], const uint32_t a[4], uint32_t b0, uint32_t b1) {
    asm volatile(
        "mma.sync.aligned.m16n8k16.row.col.f32.f16.f16.f32 "
        "{%0,%1,%2,%3}, {%4,%5,%6,%7}, {%8,%9}, {%0,%1,%2,%3};\n"
        : "+f"(acc[0]), "+f"(acc[1]), "+f"(acc[2]), "+f"(acc[3])
        : "r"(a[0]), "r"(a[1]), "r"(a[2]), "r"(a[3]), "r"(b0), "r"(b1));
}

// ---------------- edge dtype detection (int64 vs int32) ----------------
__global__ void k_detect(const int* __restrict__ ei32) {
    if (threadIdx.x == 0 && blockIdx.x == 0) {
        int is64 = 1;
        for (int i = 0; i < 128; i++) {
            if (ei32[2 * i + 1] != 0) { is64 = 0; break; }
        }
        g_is64 = is64;
    }
}

// ---------------- CSR build (2 edges per thread) ----------------
__global__ void k_count(const void* __restrict__ ei) {
    int p = blockIdx.x * blockDim.x + threadIdx.x;
    if (p * 2 >= N_EDGES) return;
    int d0, d1;
    if (g_is64) {
        longlong2 v = ((const longlong2*)ei)[N_EDGES / 2 + p];
        d0 = (int)v.x; d1 = (int)v.y;
    } else {
        int2 v = ((const int2*)ei)[N_EDGES / 2 + p];
        d0 = v.x; d1 = v.y;
    }
    atomicAdd(&g_deg[d0], 1);
    atomicAdd(&g_deg[d1], 1);
}

__global__ __launch_bounds__(1024) void k_scanA() {
    __shared__ int wsum[32];
    int b = blockIdx.x, tid = threadIdx.x, lane = tid & 31, wid = tid >> 5;
    int base = b * SCAN_CHUNK + tid * 4;
    int4 v = make_int4(0, 0, 0, 0);
    if (base + 3 < N_NODES) {
        v = *(const int4*)(g_deg + base);
    } else {
        int* p = (int*)&v;
        for (int i = 0; i < 4; i++) if (base + i < N_NODES) p[i] = g_deg[base + i];
    }
    int s0 = v.x, s1 = s0 + v.y, s2 = s1 + v.z, s3 = s2 + v.w;
    int x = s3;
    #pragma unroll
    for (int s = 1; s < 32; s <<= 1) {
        int t = __shfl_up_sync(0xffffffffu, x, s);
        if (lane >= s) x += t;
    }
    if (lane == 31) wsum[wid] = x;
    __syncthreads();
    if (wid == 0) {
        int w = wsum[lane];
        #pragma unroll
        for (int s = 1; s < 32; s <<= 1) {
            int t = __shfl_up_sync(0xffffffffu, w, s);
            if (lane >= s) w += t;
        }
        wsum[lane] = w;
    }
    __syncthreads();
    int off = (wid > 0 ? wsum[wid - 1] : 0) + (x - s3);
    int4 o = make_int4(off, off + s0, off + s1, off + s2);
    if (base + 3 < N_NODES) {
        *(int4*)(g_rowptr + base) = o;
    } else {
        int* p = (int*)&o;
        for (int i = 0; i < 4; i++) if (base + i < N_NODES) g_rowptr[base + i] = p[i];
    }
    if (tid == 0) g_bsum[b] = wsum[31];
}

__global__ void k_scanC() {
    __shared__ int boff[SCAN_NB + 1];
    int tid = threadIdx.x;
    if (tid < 32) {
        int v = (tid < SCAN_NB) ? g_bsum[tid] : 0;
        int x = v;
        #pragma unroll
        for (int s = 1; s < 32; s <<= 1) {
            int t = __shfl_up_sync(0xffffffffu, x, s);
            if (tid >= s) x += t;
        }
        if (tid < SCAN_NB) boff[tid] = x - v;
        if (tid == 31) boff[SCAN_NB] = x;
    }
    __syncthreads();
    int i = blockIdx.x * blockDim.x + tid;
    if (i < N_NODES) {
        int r = g_rowptr[i] + boff[i / SCAN_CHUNK];
        g_rowptr[i] = r;
        g_cursor[i] = r;
    }
    if (i == 0) g_rowptr[N_NODES] = boff[SCAN_NB];
}

__global__ void k_fill(const void* __restrict__ ei) {
    int p = blockIdx.x * blockDim.x + threadIdx.x;
    if (p * 2 >= N_EDGES) return;
    int d0, d1, s0, s1;
    if (g_is64) {
        longlong2 vd = ((const longlong2*)ei)[N_EDGES / 2 + p];
        longlong2 vs = ((const longlong2*)ei)[p];
        d0 = (int)vd.x; d1 = (int)vd.y; s0 = (int)vs.x; s1 = (int)vs.y;
    } else {
        int2 vd = ((const int2*)ei)[N_EDGES / 2 + p];
        int2 vs = ((const int2*)ei)[p];
        d0 = vd.x; d1 = vd.y; s0 = vs.x; s1 = vs.y;
    }
    g_col[atomicAdd(&g_cursor[d0], 1)] = s0;
    g_col[atomicAdd(&g_cursor[d1], 1)] = s1;
}

// ---------------- conversions ----------------
__global__ void k_convw(const float* __restrict__ w1l, const float* __restrict__ w1r,
                        const float* __restrict__ w2l, const float* __restrict__ w2r,
                        const float* __restrict__ w3l, const float* __restrict__ w3r) {
    int i = blockIdx.x * blockDim.x + threadIdx.x;
    if (i >= 640 * 128) return;
    int row = i >> 7, c = i & 127;
    const float* src; int r;
    if (row < 128)      { src = w1l; r = row; }
    else if (row < 256) { src = w1r; r = row - 128; }
    else if (row < 384) { src = w2l; r = row - 256; }
    else if (row < 512) { src = w2r; r = row - 384; }
    else if (row < 576) { src = w3l; r = row - 512; }
    else                { src = w3r; r = row - 576; }
    g_w16[i] = __float2half_rn(src[r * 128 + c]);
}

__global__ void k_convx(const float4* __restrict__ x, int c0, int c1) {
    int i = c0 + blockIdx.x * blockDim.x + threadIdx.x;
    if (i >= c1) return;
    float4 v = x[i];
    size_t o = (size_t)i * 4;
    __half h0 = __float2half_rn(v.x), h1 = __float2half_rn(v.y);
    __half h2 = __float2half_rn(v.z), h3 = __float2half_rn(v.w);
    *(__half2*)(g_ah + o)     = __halves2half2(h0, h1);
    *(__half2*)(g_ah + o + 2) = __halves2half2(h2, h3);
    __half l0 = __float2half_rn(v.x - __half2float(h0));
    __half l1 = __float2half_rn(v.y - __half2float(h1));
    __half l2 = __float2half_rn(v.z - __half2float(h2));
    __half l3 = __float2half_rn(v.w - __half2float(h3));
    *(__half2*)(g_al + o)     = __halves2half2(l0, l1);
    *(__half2*)(g_al + o + 2) = __halves2half2(l2, l3);
}

// ---------------- GEMM: M=128 x N=NT tile, 2-stage cp.async, ldmatrix, fp16 split ----------------
// y columns (cn < YC): 2-term (ah+al)*w.  hr columns: 1-term ah*w (hr is fp16-stored anyway).
// Warp map wm=(warp&3)*32, wn=(warp>>2)*64 balances the reduced-HMMA warps across SMSPs.
template<int NT, int NTHR>
__global__ __launch_bounds__(NTHR, 1) void k_gemm(int wbase, int mblk0) {
    constexpr int W_TILE_B = NT * CSTR_B;
    constexpr int STAGE_B  = 2 * A_TILE_B + W_TILE_B;
    constexpr int YC       = NT / 2;

    extern __shared__ __align__(16) char smemc[];
    uint32_t smem_u = (uint32_t)__cvta_generic_to_shared(smemc);
    int m0 = (blockIdx.x + mblk0) * 128;
    int tid = threadIdx.x;

    #pragma unroll
    for (int st = 0; st < 2; st++) {
        uint32_t sb = smem_u + st * STAGE_B;
        int kb = st * 64;
        for (int i = tid; i < 2048; i += NTHR) {        // A hi+lo
            int t = i >> 10, c = i & 1023;
            int r = c >> 3, q = c & 7;
            uint32_t doff = (uint32_t)(t * A_TILE_B + r * CSTR_B + q * 16);
            const __half* src = (t == 0 ? g_ah : g_al) + (size_t)(m0 + r) * 128 + kb + q * 8;
            CP_ASYNC16(sb + doff, src);
        }
        for (int i = tid; i < NT * 8; i += NTHR) {      // W single
            int r = i >> 3, q = i & 7;
            uint32_t doff = (uint32_t)(2 * A_TILE_B + r * CSTR_B + q * 16);
            const __half* src = g_w16 + (size_t)(wbase + r) * 128 + kb + q * 8;
            CP_ASYNC16(sb + doff, src);
        }
        CP_COMMIT();
    }

    int warp = tid >> 5, lane = tid & 31;
    int wm = (warp & 3) * 32, wn = (warp >> 2) * 64;   // SMSP-balanced mapping
    bool full = (wn < YC);                              // y columns need the lo term
    uint32_t aoff = ((lane & 7) + ((lane >> 3) & 1) * 8) * CSTR_B + (lane >> 4) * 16;
    uint32_t woff = (lane & 7) * CSTR_B + ((lane >> 3) & 1) * 16 + ((lane >> 3) >> 1) * (8 * CSTR_B);

    float acc[2][8][4] = {};

    #pragma unroll
    for (int st = 0; st < 2; st++) {
        if (st == 0) { CP_WAIT(1); } else { CP_WAIT(0); }
        __syncthreads();
        uint32_t sb = smem_u + st * STAGE_B;
        #pragma unroll
        for (int kl = 0; kl < 64; kl += 16) {
            uint32_t ah[2][4], al[2][4], w[8][2];
            #pragma unroll
            for (int i = 0; i < 2; i++) {
                uint32_t abase = sb + (wm + i * 16) * CSTR_B + kl * 2 + aoff;
                LDSM_X4(ah[i][0], ah[i][1], ah[i][2], ah[i][3], abase);
                if (full) LDSM_X4(al[i][0], al[i][1], al[i][2], al[i][3], abase + A_TILE_B);
            }
            #pragma unroll
            for (int jp = 0; jp < 4; jp++) {
                uint32_t wb = sb + 2 * A_TILE_B + (wn + jp * 16) * CSTR_B + kl * 2 + woff;
                LDSM_X4(w[2*jp][0], w[2*jp][1], w[2*jp+1][0], w[2*jp+1][1], wb);
            }
            #pragma unroll
            for (int j = 0; j < 8; j++) {
                #pragma unroll
                for (int i = 0; i < 2; i++) {
                    mma_f16(acc[i][j], ah[i], w[j][0], w[j][1]);          // hi * w
                    if (full) mma_f16(acc[i][j], al[i], w[j][0], w[j][1]); // lo * w (y only)
                }
            }
        }
    }

    int g = lane >> 2, tg = lane & 3;
    #pragma unroll
    for (int i = 0; i < 2; i++) {
        #pragma unroll
        for (int j = 0; j < 8; j++) {
            int rm = m0 + wm + i * 16 + g;
            int cn = wn + j * 8 + tg * 2;
            __half2 v01 = __floats2half2_rn(acc[i][j][0], acc[i][j][1]);
            __half2 v23 = __floats2half2_rn(acc[i][j][2], acc[i][j][3]);
            if (cn < YC) {
                if (rm < N_NODES)     *(__half2*)&g_y16[(size_t)rm * YC + cn]       = v01;
                if (rm + 8 < N_NODES) *(__half2*)&g_y16[(size_t)(rm + 8) * YC + cn] = v23;
            } else {
                int hc = cn - YC;
                if (rm < N_NODES)     *(__half2*)&g_hr16[(size_t)rm * YC + hc]       = v01;
                if (rm + 8 < N_NODES) *(__half2*)&g_hr16[(size_t)(rm + 8) * YC + hc] = v23;
            }
        }
    }
}

// ---------------- aggregation: out = mean(gather y16) + hr16 + b (+relu), emit fp16 hi/lo ----------------
__device__ __forceinline__ void acc_half4(float4& acc, uint2 p) {
    float2 fa = __half22float2(*(__half2*)&p.x);
    float2 fb = __half22float2(*(__half2*)&p.y);
    acc.x += fa.x; acc.y += fa.y; acc.z += fb.x; acc.w += fb.y;
}

__device__ __forceinline__ float4 half4_to_float4(uint2 p) {
    float2 fa = __half22float2(*(__half2*)&p.x);
    float2 fb = __half22float2(*(__half2*)&p.y);
    return make_float4(fa.x, fa.y, fb.x, fb.y);
}

__global__ void k_agg128(const float* __restrict__ bias, int relu, int n0, int n1) {
    int warp = n0 + ((blockIdx.x * blockDim.x + threadIdx.x) >> 5);
    int lane = threadIdx.x & 31;
    if (warp >= n1) return;
    int rs = g_rowptr[warp], re = g_rowptr[warp + 1];
    float4 acc = make_float4(0.f, 0.f, 0.f, 0.f);
    const uint2* Y2 = (const uint2*)g_y16;
    int e = rs;
    for (; e + 4 <= re; e += 4) {
        int s0 = g_col[e], s1 = g_col[e + 1], s2 = g_col[e + 2], s3 = g_col[e + 3];
        uint2 p0 = Y2[(size_t)s0 * 32 + lane];
        uint2 p1 = Y2[(size_t)s1 * 32 + lane];
        uint2 p2 = Y2[(size_t)s2 * 32 + lane];
        uint2 p3 = Y2[(size_t)s3 * 32 + lane];
        acc_half4(acc, p0); acc_half4(acc, p1); acc_half4(acc, p2); acc_half4(acc, p3);
    }
    for (; e < re; e++) {
        uint2 p = Y2[(size_t)g_col[e] * 32 + lane];
        acc_half4(acc, p);
    }
    float inv = 1.f / fmaxf((float)(re - rs), 1.f);
    float4 hr = half4_to_float4(((const uint2*)g_hr16)[(size_t)warp * 32 + lane]);
    float4 b  = ((const float4*)bias)[lane];
    float o0 = acc.x * inv + hr.x + b.x;
    float o1 = acc.y * inv + hr.y + b.y;
    float o2 = acc.z * inv + hr.z + b.z;
    float o3 = acc.w * inv + hr.w + b.w;
    if (relu) {
        o0 = fmaxf(o0, 0.f); o1 = fmaxf(o1, 0.f);
        o2 = fmaxf(o2, 0.f); o3 = fmaxf(o3, 0.f);
    }
    size_t idx = (size_t)warp * 128 + lane * 4;
    __half h0 = __float2half_rn(o0), h1 = __float2half_rn(o1);
    __half h2 = __float2half_rn(o2), h3 = __float2half_rn(o3);
    *(__half2*)(g_ah + idx)     = __halves2half2(h0, h1);
    *(__half2*)(g_ah + idx + 2) = __halves2half2(h2, h3);
    __half l0 = __float2half_rn(o0 - __half2float(h0));
    __half l1 = __float2half_rn(o1 - __half2float(h1));
    __half l2 = __float2half_rn(o2 - __half2float(h2));
    __half l3 = __float2half_rn(o3 - __half2float(h3));
    *(__half2*)(g_al + idx)     = __halves2half2(l0, l1);
    *(__half2*)(g_al + idx + 2) = __halves2half2(l2, l3);
}

__global__ void k_agg64(const float* __restrict__ bias, float* __restrict__ out) {
    int gw = (blockIdx.x * blockDim.x + threadIdx.x) >> 5;
    int lane = threadIdx.x & 31;
    int half = lane >> 4, ln = lane & 15;
    int node = gw * 2 + half;
    if (node >= N_NODES) return;
    int rs = g_rowptr[node], re = g_rowptr[node + 1];
    float4 acc = make_float4(0.f, 0.f, 0.f, 0.f);
    const uint2* Y2 = (const uint2*)g_y16;
    int e = rs;
    for (; e + 4 <= re; e += 4) {
        int s0 = g_col[e], s1 = g_col[e + 1], s2 = g_col[e + 2], s3 = g_col[e + 3];
        uint2 p0 = Y2[(size_t)s0 * 16 + ln];
        uint2 p1 = Y2[(size_t)s1 * 16 + ln];
        uint2 p2 = Y2[(size_t)s2 * 16 + ln];
        uint2 p3 = Y2[(size_t)s3 * 16 + ln];
        acc_half4(acc, p0); acc_half4(acc, p1); acc_half4(acc, p2); acc_half4(acc, p3);
    }
    for (; e < re; e++) {
        uint2 p = Y2[(size_t)g_col[e] * 16 + ln];
        acc_half4(acc, p);
    }
    float inv = 1.f / fmaxf((float)(re - rs), 1.f);
    float4 hr = half4_to_float4(((const uint2*)g_hr16)[(size_t)node * 16 + ln]);
    float4 b  = ((const float4*)bias)[ln];
    float4 o;
    o.x = acc.x * inv + hr.x + b.x;
    o.y = acc.y * inv + hr.y + b.y;
    o.z = acc.z * inv + hr.z + b.z;
    o.w = acc.w * inv + hr.w + b.w;
    ((float4*)out)[(size_t)node * 16 + ln] = o;
}

// ---------------- launch ----------------
extern "C" void kernel_launch(void* const* d_in, const int* in_sizes, int n_in,
                              void* d_out, int out_size) {
    const float* x   = (const float*)d_in[0];
    const void*  ei  = d_in[1];
    const float* w1l = (const float*)d_in[2];
    const float* w1r = (const float*)d_in[3];
    const float* b1  = (const float*)d_in[4];
    const float* w2l = (const float*)d_in[5];
    const float* w2r = (const float*)d_in[6];
    const float* b2  = (const float*)d_in[7];
    const float* w3l = (const float*)d_in[8];
    const float* w3r = (const float*)d_in[9];
    const float* b3  = (const float*)d_in[10];
    float* out = (float*)d_out;

    constexpr int SMEM_BIG   = 2 * (2 * A_TILE_B + 256 * CSTR_B);  // 147456
    constexpr int SMEM_SMALL = 2 * (2 * A_TILE_B + 128 * CSTR_B);  // 110592
    cudaFuncSetAttribute(k_gemm<256, 512>, cudaFuncAttributeMaxDynamicSharedMemorySize, SMEM_BIG);
    cudaFuncSetAttribute(k_gemm<128, 256>, cudaFuncAttributeMaxDynamicSharedMemorySize, SMEM_SMALL);

    static cudaStream_t s2 = nullptr, s3 = nullptr;
    static cudaEvent_t evFork = nullptr, evJoin = nullptr;
    static cudaEvent_t evC0 = nullptr, evG1p0 = nullptr, evG1p1 = nullptr;
    static cudaEvent_t evB1 = nullptr, evG2 = nullptr, evB2 = nullptr;
    if (s2 == nullptr) {
        cudaStreamCreateWithFlags(&s2, cudaStreamNonBlocking);
        cudaStreamCreateWithFlags(&s3, cudaStreamNonBlocking);
        cudaEventCreateWithFlags(&evFork, cudaEventDisableTiming);
        cudaEventCreateWithFlags(&evJoin, cudaEventDisableTiming);
        cudaEventCreateWithFlags(&evC0, cudaEventDisableTiming);
        cudaEventCreateWithFlags(&evG1p0, cudaEventDisableTiming);
        cudaEventCreateWithFlags(&evG1p1, cudaEventDisableTiming);
        cudaEventCreateWithFlags(&evB1, cudaEventDisableTiming);
        cudaEventCreateWithFlags(&evG2, cudaEventDisableTiming);
        cudaEventCreateWithFlags(&evB2, cudaEventDisableTiming);
    }

    void* deg_ptr = nullptr;
    cudaGetSymbolAddress(&deg_ptr, g_deg);

    const int EPAIR_BLKS = (N_EDGES / 2 + 255) / 256;   // 3125
    const int T0 = 391, T1 = 391;
    const int AP0_BLKS = NSPLIT / 8;                    // 6256
    const int AP1_BLKS = (N_NODES - NSPLIT + 7) / 8;    // 6244
    const int XP0_BLKS = XCH_P0 / 256;                  // 6256
    const int XP1_BLKS = (XCH_TOT - XCH_P0 + 255) / 256;

    // ---- fork: CSR chain on s2 ----
    cudaEventRecord(evFork, 0);
    cudaStreamWaitEvent(s2, evFork, 0);
    cudaStreamWaitEvent(s3, evFork, 0);
    k_detect<<<1, 32, 0, s2>>>((const int*)ei);
    cudaMemsetAsync(deg_ptr, 0, N_NODES * sizeof(int), s2);
    k_count<<<EPAIR_BLKS, 256, 0, s2>>>(ei);
    k_scanA<<<SCAN_NB, 1024, 0, s2>>>();
    k_scanC<<<(N_NODES + 255) / 256, 256, 0, s2>>>();
    k_fill<<<EPAIR_BLKS, 256, 0, s2>>>(ei);
    cudaEventRecord(evJoin, s2);

    // ---- s0: weights + x half 0 -> GEMM L1 p0 ----
    k_convw<<<320, 256>>>(w1l, w1r, w2l, w2r, w3l, w3r);
    k_convx<<<XP0_BLKS, 256>>>((const float4*)x, 0, XCH_P0);
    cudaEventRecord(evC0, 0);
    k_gemm<256, 512><<<T0, 512, SMEM_BIG>>>(0, 0);
    cudaEventRecord(evG1p0, 0);

    // ---- s3: x half 1 (staggered) -> GEMM L1 p1 ----
    cudaStreamWaitEvent(s3, evC0, 0);
    k_convx<<<XP1_BLKS, 256, 0, s3>>>((const float4*)x, XCH_P0, XCH_TOT);
    k_gemm<256, 512><<<T1, 512, SMEM_BIG, s3>>>(0, T0);
    cudaEventRecord(evG1p1, s3);

    // ---- boundary 1: split agg L1 + GEMM L2 ----
    cudaStreamWaitEvent(0, evJoin, 0);
    cudaStreamWaitEvent(0, evG1p1, 0);
    cudaStreamWaitEvent(s2, evG1p0, 0);
    cudaStreamWaitEvent(s2, evG1p1, 0);
    k_agg128<<<AP0_BLKS, 256>>>(b1, 1, 0, NSPLIT);
    k_gemm<256, 512><<<T0, 512, SMEM_BIG>>>(256, 0);
    k_agg128<<<AP1_BLKS, 256, 0, s2>>>(b1, 1, NSPLIT, N_NODES);
    k_gemm<256, 512><<<T1, 512, SMEM_BIG, s2>>>(256, T0);
    cudaEventRecord(evB1, s2);
    cudaEventRecord(evG2, 0);

    // ---- boundary 2: split agg L2 + GEMM L3 ----
    cudaStreamWaitEvent(0, evB1, 0);
    cudaStreamWaitEvent(s2, evG2, 0);
    k_agg128<<<AP0_BLKS, 256>>>(b2, 1, 0, NSPLIT);
    k_gemm<128, 256><<<T0, 256, SMEM_SMALL>>>(512, 0);
    k_agg128<<<AP1_BLKS, 256, 0, s2>>>(b2, 1, NSPLIT, N_NODES);
    k_gemm<128, 256><<<T1, 256, SMEM_SMALL, s2>>>(512, T0);
    cudaEventRecord(evB2, s2);

    // ---- final aggregation ----
    cudaStreamWaitEvent(0, evB2, 0);
    k_agg64<<<(N_NODES / 2 + 7) / 8, 256>>>(b3, out);
}

// round 16
// speedup vs baseline: 1.2844x; 1.0107x over previous
#include <cuda_runtime.h>
#include <cuda_bf16.h>
#include <cuda_fp16.h>
#include <cstdint>

#define N_NODES 100000
#define N_PAD   100096
#define N_EDGES 1600000
#define SCAN_CHUNK 4096
#define SCAN_NB ((N_NODES + SCAN_CHUNK - 1) / SCAN_CHUNK)  // 25
#define NSPLIT  50048
#define XCH_TOT (N_NODES * 32)
#define XCH_P0  (NSPLIT * 32)

#define CSTR_B 144
#define A_TILE_B (128 * CSTR_B)

// ---------------- scratch (static device globals; no allocs) ----------------
__device__ int g_is64;
__device__ __align__(16) int g_deg[N_NODES + 4];
__device__ __align__(16) int g_rowptr[N_NODES + 4];
__device__ __align__(16) int g_cursor[N_NODES];
__device__ int g_col[N_EDGES];
__device__ int g_bsum[SCAN_NB];
__device__ __half g_y16[(size_t)N_NODES * 128];
__device__ __half g_hr16[(size_t)N_NODES * 128];
__device__ __half g_ah[(size_t)N_PAD * 128];
__device__ __half g_al[(size_t)N_PAD * 128];
__device__ __half g_w16[640 * 128];

// ---------------- PTX helpers ----------------
#define CP_ASYNC16(dst, src) \
    asm volatile("cp.async.cg.shared.global [%0], [%1], 16;\n" :: "r"(dst), "l"(src))
#define CP_COMMIT() asm volatile("cp.async.commit_group;\n")
#define CP_WAIT(n)  asm volatile("cp.async.wait_group %0;\n" :: "n"(n))
#define LDSM_X4(r0, r1, r2, r3, addr) \
    asm volatile("ldmatrix.sync.aligned.m8n8.x4.shared.b16 {%0,%1,%2,%3}, [%4];" \
                 : "=r"(r0), "=r"(r1), "=r"(r2), "=r"(r3) : "r"(addr))

__device__ __forceinline__ void mma_f16(float acc[4], const uint32_t a[4], uint32_t b0, uint32_t b1) {
    asm volatile(
        "mma.sync.aligned.m16n8k16.row.col.f32.f16.f16.f32 "
        "{%0,%1,%2,%3}, {%4,%5,%6,%7}, {%8,%9}, {%0,%1,%2,%3};\n"
        : "+f"(acc[0]), "+f"(acc[1]), "+f"(acc[2]), "+f"(acc[3])
        : "r"(a[0]), "r"(a[1]), "r"(a[2]), "r"(a[3]), "r"(b0), "r"(b1));
}

// ---------------- edge dtype detection ----------------
__global__ void k_detect(const int* __restrict__ ei32) {
    if (threadIdx.x == 0 && blockIdx.x == 0) {
        int is64 = 1;
        for (int i = 0; i < 128; i++) {
            if (ei32[2 * i + 1] != 0) { is64 = 0; break; }
        }
        g_is64 = is64;
    }
}

// ---------------- CSR build (4 edges per thread) ----------------
__global__ void k_count(const void* __restrict__ ei) {
    int q = blockIdx.x * blockDim.x + threadIdx.x;   // quad index
    if (q * 4 >= N_EDGES) return;
    int d[4];
    if (g_is64) {
        longlong2 v0 = ((const longlong2*)ei)[N_EDGES / 2 + q * 2];
        longlong2 v1 = ((const longlong2*)ei)[N_EDGES / 2 + q * 2 + 1];
        d[0] = (int)v0.x; d[1] = (int)v0.y; d[2] = (int)v1.x; d[3] = (int)v1.y;
    } else {
        int4 v = ((const int4*)ei)[N_EDGES / 4 + q];
        d[0] = v.x; d[1] = v.y; d[2] = v.z; d[3] = v.w;
    }
    #pragma unroll
    for (int i = 0; i < 4; i++) atomicAdd(&g_deg[d[i]], 1);
}

__global__ __launch_bounds__(1024) void k_scanA() {
    __shared__ int wsum[32];
    int b = blockIdx.x, tid = threadIdx.x, lane = tid & 31, wid = tid >> 5;
    int base = b * SCAN_CHUNK + tid * 4;
    int4 v = make_int4(0, 0, 0, 0);
    if (base + 3 < N_NODES) {
        v = *(const int4*)(g_deg + base);
    } else {
        int* p = (int*)&v;
        for (int i = 0; i < 4; i++) if (base + i < N_NODES) p[i] = g_deg[base + i];
    }
    int s0 = v.x, s1 = s0 + v.y, s2 = s1 + v.z, s3 = s2 + v.w;
    int x = s3;
    #pragma unroll
    for (int s = 1; s < 32; s <<= 1) {
        int t = __shfl_up_sync(0xffffffffu, x, s);
        if (lane >= s) x += t;
    }
    if (lane == 31) wsum[wid] = x;
    __syncthreads();
    if (wid == 0) {
        int w = wsum[lane];
        #pragma unroll
        for (int s = 1; s < 32; s <<= 1) {
            int t = __shfl_up_sync(0xffffffffu, w, s);
            if (lane >= s) w += t;
        }
        wsum[lane] = w;
    }
    __syncthreads();
    int off = (wid > 0 ? wsum[wid - 1] : 0) + (x - s3);
    int4 o = make_int4(off, off + s0, off + s1, off + s2);
    if (base + 3 < N_NODES) {
        *(int4*)(g_rowptr + base) = o;
    } else {
        int* p = (int*)&o;
        for (int i = 0; i < 4; i++) if (base + i < N_NODES) g_rowptr[base + i] = p[i];
    }
    if (tid == 0) g_bsum[b] = wsum[31];
}

__global__ void k_scanC() {
    __shared__ int boff[SCAN_NB + 1];
    int tid = threadIdx.x;
    if (tid < 32) {
        int v = (tid < SCAN_NB) ? g_bsum[tid] : 0;
        int x = v;
        #pragma unroll
        for (int s = 1; s < 32; s <<= 1) {
            int t = __shfl_up_sync(0xffffffffu, x, s);
            if (tid >= s) x += t;
        }
        if (tid < SCAN_NB) boff[tid] = x - v;
        if (tid == 31) boff[SCAN_NB] = x;
    }
    __syncthreads();
    int i = blockIdx.x * blockDim.x + tid;
    if (i < N_NODES) {
        int r = g_rowptr[i] + boff[i / SCAN_CHUNK];
        g_rowptr[i] = r;
        g_cursor[i] = r;
    }
    if (i == 0) g_rowptr[N_NODES] = boff[SCAN_NB];
}

__global__ void k_fill(const void* __restrict__ ei) {
    int q = blockIdx.x * blockDim.x + threadIdx.x;   // quad index
    if (q * 4 >= N_EDGES) return;
    int d[4], s[4];
    if (g_is64) {
        longlong2 vd0 = ((const longlong2*)ei)[N_EDGES / 2 + q * 2];
        longlong2 vd1 = ((const longlong2*)ei)[N_EDGES / 2 + q * 2 + 1];
        longlong2 vs0 = ((const longlong2*)ei)[q * 2];
        longlong2 vs1 = ((const longlong2*)ei)[q * 2 + 1];
        d[0] = (int)vd0.x; d[1] = (int)vd0.y; d[2] = (int)vd1.x; d[3] = (int)vd1.y;
        s[0] = (int)vs0.x; s[1] = (int)vs0.y; s[2] = (int)vs1.x; s[3] = (int)vs1.y;
    } else {
        int4 vd = ((const int4*)ei)[N_EDGES / 4 + q];
        int4 vs = ((const int4*)ei)[q];
        d[0] = vd.x; d[1] = vd.y; d[2] = vd.z; d[3] = vd.w;
        s[0] = vs.x; s[1] = vs.y; s[2] = vs.z; s[3] = vs.w;
    }
    #pragma unroll
    for (int i = 0; i < 4; i++) g_col[atomicAdd(&g_cursor[d[i]], 1)] = s[i];
}

// ---------------- conversions ----------------
__global__ void k_convw(const float* __restrict__ w1l, const float* __restrict__ w1r,
                        const float* __restrict__ w2l, const float* __restrict__ w2r,
                        const float* __restrict__ w3l, const float* __restrict__ w3r) {
    int i = blockIdx.x * blockDim.x + threadIdx.x;
    if (i >= 640 * 128) return;
    int row = i >> 7, c = i & 127;
    const float* src; int r;
    if (row < 128)      { src = w1l; r = row; }
    else if (row < 256) { src = w1r; r = row - 128; }
    else if (row < 384) { src = w2l; r = row - 256; }
    else if (row < 512) { src = w2r; r = row - 384; }
    else if (row < 576) { src = w3l; r = row - 512; }
    else                { src = w3r; r = row - 576; }
    g_w16[i] = __float2half_rn(src[r * 128 + c]);
}

__global__ void k_convx(const float4* __restrict__ x, int c0, int c1) {
    int i = c0 + blockIdx.x * blockDim.x + threadIdx.x;
    if (i >= c1) return;
    float4 v = x[i];
    size_t o = (size_t)i * 4;
    __half h0 = __float2half_rn(v.x), h1 = __float2half_rn(v.y);
    __half h2 = __float2half_rn(v.z), h3 = __float2half_rn(v.w);
    *(__half2*)(g_ah + o)     = __halves2half2(h0, h1);
    *(__half2*)(g_ah + o + 2) = __halves2half2(h2, h3);
    __half l0 = __float2half_rn(v.x - __half2float(h0));
    __half l1 = __float2half_rn(v.y - __half2float(h1));
    __half l2 = __float2half_rn(v.z - __half2float(h2));
    __half l3 = __float2half_rn(v.w - __half2float(h3));
    *(__half2*)(g_al + o)     = __halves2half2(l0, l1);
    *(__half2*)(g_al + o + 2) = __halves2half2(l2, l3);
}

// ---------------- GEMM (R14 form: 2-term y, 1-term hr, SMSP-balanced) ----------------
template<int NT, int NTHR>
__global__ __launch_bounds__(NTHR, 1) void k_gemm(int wbase, int mblk0) {
    constexpr int W_TILE_B = NT * CSTR_B;
    constexpr int STAGE_B  = 2 * A_TILE_B + W_TILE_B;
    constexpr int YC       = NT / 2;

    extern __shared__ __align__(16) char smemc[];
    uint32_t smem_u = (uint32_t)__cvta_generic_to_shared(smemc);
    int m0 = (blockIdx.x + mblk0) * 128;
    int tid = threadIdx.x;

    #pragma unroll
    for (int st = 0; st < 2; st++) {
        uint32_t sb = smem_u + st * STAGE_B;
        int kb = st * 64;
        for (int i = tid; i < 2048; i += NTHR) {
            int t = i >> 10, c = i & 1023;
            int r = c >> 3, q = c & 7;
            uint32_t doff = (uint32_t)(t * A_TILE_B + r * CSTR_B + q * 16);
            const __half* src = (t == 0 ? g_ah : g_al) + (size_t)(m0 + r) * 128 + kb + q * 8;
            CP_ASYNC16(sb + doff, src);
        }
        for (int i = tid; i < NT * 8; i += NTHR) {
            int r = i >> 3, q = i & 7;
            uint32_t doff = (uint32_t)(2 * A_TILE_B + r * CSTR_B + q * 16);
            const __half* src = g_w16 + (size_t)(wbase + r) * 128 + kb + q * 8;
            CP_ASYNC16(sb + doff, src);
        }
        CP_COMMIT();
    }

    int warp = tid >> 5, lane = tid & 31;
    int wm = (warp & 3) * 32, wn = (warp >> 2) * 64;
    bool full = (wn < YC);
    uint32_t aoff = ((lane & 7) + ((lane >> 3) & 1) * 8) * CSTR_B + (lane >> 4) * 16;
    uint32_t woff = (lane & 7) * CSTR_B + ((lane >> 3) & 1) * 16 + ((lane >> 3) >> 1) * (8 * CSTR_B);

    float acc[2][8][4] = {};

    #pragma unroll
    for (int st = 0; st < 2; st++) {
        if (st == 0) { CP_WAIT(1); } else { CP_WAIT(0); }
        __syncthreads();
        uint32_t sb = smem_u + st * STAGE_B;
        #pragma unroll
        for (int kl = 0; kl < 64; kl += 16) {
            uint32_t ah[2][4], al[2][4], w[8][2];
            #pragma unroll
            for (int i = 0; i < 2; i++) {
                uint32_t abase = sb + (wm + i * 16) * CSTR_B + kl * 2 + aoff;
                LDSM_X4(ah[i][0], ah[i][1], ah[i][2], ah[i][3], abase);
                if (full) LDSM_X4(al[i][0], al[i][1], al[i][2], al[i][3], abase + A_TILE_B);
            }
            #pragma unroll
            for (int jp = 0; jp < 4; jp++) {
                uint32_t wb = sb + 2 * A_TILE_B + (wn + jp * 16) * CSTR_B + kl * 2 + woff;
                LDSM_X4(w[2*jp][0], w[2*jp][1], w[2*jp+1][0], w[2*jp+1][1], wb);
            }
            #pragma unroll
            for (int j = 0; j < 8; j++) {
                #pragma unroll
                for (int i = 0; i < 2; i++) {
                    mma_f16(acc[i][j], ah[i], w[j][0], w[j][1]);
                    if (full) mma_f16(acc[i][j], al[i], w[j][0], w[j][1]);
                }
            }
        }
    }

    int g = lane >> 2, tg = lane & 3;
    #pragma unroll
    for (int i = 0; i < 2; i++) {
        #pragma unroll
        for (int j = 0; j < 8; j++) {
            int rm = m0 + wm + i * 16 + g;
            int cn = wn + j * 8 + tg * 2;
            __half2 v01 = __floats2half2_rn(acc[i][j][0], acc[i][j][1]);
            __half2 v23 = __floats2half2_rn(acc[i][j][2], acc[i][j][3]);
            if (cn < YC) {
                if (rm < N_NODES)     *(__half2*)&g_y16[(size_t)rm * YC + cn]       = v01;
                if (rm + 8 < N_NODES) *(__half2*)&g_y16[(size_t)(rm + 8) * YC + cn] = v23;
            } else {
                int hc = cn - YC;
                if (rm < N_NODES)     *(__half2*)&g_hr16[(size_t)rm * YC + hc]       = v01;
                if (rm + 8 < N_NODES) *(__half2*)&g_hr16[(size_t)(rm + 8) * YC + hc] = v23;
            }
        }
    }
}

// ---------------- aggregation (unroll 8) ----------------
__device__ __forceinline__ void acc_half4(float4& acc, uint2 p) {
    float2 fa = __half22float2(*(__half2*)&p.x);
    float2 fb = __half22float2(*(__half2*)&p.y);
    acc.x += fa.x; acc.y += fa.y; acc.z += fb.x; acc.w += fb.y;
}

__device__ __forceinline__ float4 half4_to_float4(uint2 p) {
    float2 fa = __half22float2(*(__half2*)&p.x);
    float2 fb = __half22float2(*(__half2*)&p.y);
    return make_float4(fa.x, fa.y, fb.x, fb.y);
}

__global__ void k_agg128(const float* __restrict__ bias, int relu, int n0, int n1) {
    int warp = n0 + ((blockIdx.x * blockDim.x + threadIdx.x) >> 5);
    int lane = threadIdx.x & 31;
    if (warp >= n1) return;
    int rs = g_rowptr[warp], re = g_rowptr[warp + 1];
    float4 acc = make_float4(0.f, 0.f, 0.f, 0.f);
    const uint2* Y2 = (const uint2*)g_y16;
    int e = rs;
    for (; e + 8 <= re; e += 8) {
        uint2 p[8];
        #pragma unroll
        for (int k = 0; k < 8; k++) p[k] = Y2[(size_t)g_col[e + k] * 32 + lane];
        #pragma unroll
        for (int k = 0; k < 8; k++) acc_half4(acc, p[k]);
    }
    for (; e + 4 <= re; e += 4) {
        uint2 p[4];
        #pragma unroll
        for (int k = 0; k < 4; k++) p[k] = Y2[(size_t)g_col[e + k] * 32 + lane];
        #pragma unroll
        for (int k = 0; k < 4; k++) acc_half4(acc, p[k]);
    }
    for (; e < re; e++) {
        uint2 p = Y2[(size_t)g_col[e] * 32 + lane];
        acc_half4(acc, p);
    }
    float inv = 1.f / fmaxf((float)(re - rs), 1.f);
    float4 hr = half4_to_float4(((const uint2*)g_hr16)[(size_t)warp * 32 + lane]);
    float4 b  = ((const float4*)bias)[lane];
    float o0 = acc.x * inv + hr.x + b.x;
    float o1 = acc.y * inv + hr.y + b.y;
    float o2 = acc.z * inv + hr.z + b.z;
    float o3 = acc.w * inv + hr.w + b.w;
    if (relu) {
        o0 = fmaxf(o0, 0.f); o1 = fmaxf(o1, 0.f);
        o2 = fmaxf(o2, 0.f); o3 = fmaxf(o3, 0.f);
    }
    size_t idx = (size_t)warp * 128 + lane * 4;
    __half h0 = __float2half_rn(o0), h1 = __float2half_rn(o1);
    __half h2 = __float2half_rn(o2), h3 = __float2half_rn(o3);
    *(__half2*)(g_ah + idx)     = __halves2half2(h0, h1);
    *(__half2*)(g_ah + idx + 2) = __halves2half2(h2, h3);
    __half l0 = __float2half_rn(o0 - __half2float(h0));
    __half l1 = __float2half_rn(o1 - __half2float(h1));
    __half l2 = __float2half_rn(o2 - __half2float(h2));
    __half l3 = __float2half_rn(o3 - __half2float(h3));
    *(__half2*)(g_al + idx)     = __halves2half2(l0, l1);
    *(__half2*)(g_al + idx + 2) = __halves2half2(l2, l3);
}

__global__ void k_agg64(const float* __restrict__ bias, float* __restrict__ out) {
    int gw = (blockIdx.x * blockDim.x + threadIdx.x) >> 5;
    int lane = threadIdx.x & 31;
    int half = lane >> 4, ln = lane & 15;
    int node = gw * 2 + half;
    if (node >= N_NODES) return;
    int rs = g_rowptr[node], re = g_rowptr[node + 1];
    float4 acc = make_float4(0.f, 0.f, 0.f, 0.f);
    const uint2* Y2 = (const uint2*)g_y16;
    int e = rs;
    for (; e + 8 <= re; e += 8) {
        uint2 p[8];
        #pragma unroll
        for (int k = 0; k < 8; k++) p[k] = Y2[(size_t)g_col[e + k] * 16 + ln];
        #pragma unroll
        for (int k = 0; k < 8; k++) acc_half4(acc, p[k]);
    }
    for (; e + 4 <= re; e += 4) {
        uint2 p[4];
        #pragma unroll
        for (int k = 0; k < 4; k++) p[k] = Y2[(size_t)g_col[e + k] * 16 + ln];
        #pragma unroll
        for (int k = 0; k < 4; k++) acc_half4(acc, p[k]);
    }
    for (; e < re; e++) {
        uint2 p = Y2[(size_t)g_col[e] * 16 + ln];
        acc_half4(acc, p);
    }
    float inv = 1.f / fmaxf((float)(re - rs), 1.f);
    float4 hr = half4_to_float4(((const uint2*)g_hr16)[(size_t)node * 16 + ln]);
    float4 b  = ((const float4*)bias)[ln];
    float4 o;
    o.x = acc.x * inv + hr.x + b.x;
    o.y = acc.y * inv + hr.y + b.y;
    o.z = acc.z * inv + hr.z + b.z;
    o.w = acc.w * inv + hr.w + b.w;
    ((float4*)out)[(size_t)node * 16 + ln] = o;
}

// ---------------- launch ----------------
extern "C" void kernel_launch(void* const* d_in, const int* in_sizes, int n_in,
                              void* d_out, int out_size) {
    const float* x   = (const float*)d_in[0];
    const void*  ei  = d_in[1];
    const float* w1l = (const float*)d_in[2];
    const float* w1r = (const float*)d_in[3];
    const float* b1  = (const float*)d_in[4];
    const float* w2l = (const float*)d_in[5];
    const float* w2r = (const float*)d_in[6];
    const float* b2  = (const float*)d_in[7];
    const float* w3l = (const float*)d_in[8];
    const float* w3r = (const float*)d_in[9];
    const float* b3  = (const float*)d_in[10];
    float* out = (float*)d_out;

    constexpr int SMEM_BIG   = 2 * (2 * A_TILE_B + 256 * CSTR_B);  // 147456
    constexpr int SMEM_SMALL = 2 * (2 * A_TILE_B + 128 * CSTR_B);  // 110592
    cudaFuncSetAttribute(k_gemm<256, 512>, cudaFuncAttributeMaxDynamicSharedMemorySize, SMEM_BIG);
    cudaFuncSetAttribute(k_gemm<128, 256>, cudaFuncAttributeMaxDynamicSharedMemorySize, SMEM_SMALL);

    static cudaStream_t s2 = nullptr, s3 = nullptr;
    static cudaEvent_t evFork = nullptr, evJoin = nullptr;
    static cudaEvent_t evC0 = nullptr, evG1p0 = nullptr, evG1p1 = nullptr;
    static cudaEvent_t evB1 = nullptr, evG2 = nullptr, evB2 = nullptr;
    if (s2 == nullptr) {
        cudaStreamCreateWithFlags(&s2, cudaStreamNonBlocking);
        cudaStreamCreateWithFlags(&s3, cudaStreamNonBlocking);
        cudaEventCreateWithFlags(&evFork, cudaEventDisableTiming);
        cudaEventCreateWithFlags(&evJoin, cudaEventDisableTiming);
        cudaEventCreateWithFlags(&evC0, cudaEventDisableTiming);
        cudaEventCreateWithFlags(&evG1p0, cudaEventDisableTiming);
        cudaEventCreateWithFlags(&evG1p1, cudaEventDisableTiming);
        cudaEventCreateWithFlags(&evB1, cudaEventDisableTiming);
        cudaEventCreateWithFlags(&evG2, cudaEventDisableTiming);
        cudaEventCreateWithFlags(&evB2, cudaEventDisableTiming);
    }

    void* deg_ptr = nullptr;
    cudaGetSymbolAddress(&deg_ptr, g_deg);

    const int EQUAD_BLKS = (N_EDGES / 4 + 255) / 256;   // 1563
    const int T0 = 391, T1 = 391;
    const int AP0_BLKS = NSPLIT / 8;
    const int AP1_BLKS = (N_NODES - NSPLIT + 7) / 8;
    const int XP0_BLKS = XCH_P0 / 256;
    const int XP1_BLKS = (XCH_TOT - XCH_P0 + 255) / 256;

    // ---- fork: CSR chain on s2 ----
    cudaEventRecord(evFork, 0);
    cudaStreamWaitEvent(s2, evFork, 0);
    cudaStreamWaitEvent(s3, evFork, 0);
    k_detect<<<1, 32, 0, s2>>>((const int*)ei);
    cudaMemsetAsync(deg_ptr, 0, N_NODES * sizeof(int), s2);
    k_count<<<EQUAD_BLKS, 256, 0, s2>>>(ei);
    k_scanA<<<SCAN_NB, 1024, 0, s2>>>();
    k_scanC<<<(N_NODES + 255) / 256, 256, 0, s2>>>();
    k_fill<<<EQUAD_BLKS, 256, 0, s2>>>(ei);
    cudaEventRecord(evJoin, s2);

    // ---- s0: weights + x half 0 -> GEMM L1 p0 ----
    k_convw<<<320, 256>>>(w1l, w1r, w2l, w2r, w3l, w3r);
    k_convx<<<XP0_BLKS, 256>>>((const float4*)x, 0, XCH_P0);
    cudaEventRecord(evC0, 0);
    k_gemm<256, 512><<<T0, 512, SMEM_BIG>>>(0, 0);
    cudaEventRecord(evG1p0, 0);

    // ---- s3: x half 1 -> GEMM L1 p1 ----
    cudaStreamWaitEvent(s3, evC0, 0);
    k_convx<<<XP1_BLKS, 256, 0, s3>>>((const float4*)x, XCH_P0, XCH_TOT);
    k_gemm<256, 512><<<T1, 512, SMEM_BIG, s3>>>(0, T0);
    cudaEventRecord(evG1p1, s3);

    // ---- boundary 1 ----
    cudaStreamWaitEvent(0, evJoin, 0);
    cudaStreamWaitEvent(0, evG1p1, 0);
    cudaStreamWaitEvent(s2, evG1p0, 0);
    cudaStreamWaitEvent(s2, evG1p1, 0);
    k_agg128<<<AP0_BLKS, 256>>>(b1, 1, 0, NSPLIT);
    k_gemm<256, 512><<<T0, 512, SMEM_BIG>>>(256, 0);
    k_agg128<<<AP1_BLKS, 256, 0, s2>>>(b1, 1, NSPLIT, N_NODES);
    k_gemm<256, 512><<<T1, 512, SMEM_BIG, s2>>>(256, T0);
    cudaEventRecord(evB1, s2);
    cudaEventRecord(evG2, 0);

    // ---- boundary 2 ----
    cudaStreamWaitEvent(0, evB1, 0);
    cudaStreamWaitEvent(s2, evG2, 0);
    k_agg128<<<AP0_BLKS, 256>>>(b2, 1, 0, NSPLIT);
    k_gemm<128, 256><<<T0, 256, SMEM_SMALL>>>(512, 0);
    k_agg128<<<AP1_BLKS, 256, 0, s2>>>(b2, 1, NSPLIT, N_NODES);
    k_gemm<128, 256><<<T1, 256, SMEM_SMALL, s2>>>(512, T0);
    cudaEventRecord(evB2, s2);

    // ---- final aggregation ----
    cudaStreamWaitEvent(0, evB2, 0);
    k_agg64<<<(N_NODES / 2 + 7) / 8, 256>>>(b3, out);
}